// round 5
// baseline (speedup 1.0000x reference)
#include <cuda_runtime.h>
#include <math.h>
#include <float.h>

#define B_   8
#define CIN  32
#define CI   16
#define Hh   128
#define Ww   128
#define NHH  31
#define LL   961
#define LLP  964      // padded row stride (%4==0)
#define FIN  784
#define FOUT 196
#define FV   1568
#define NTHREADS 256

// ---------------- scratch (device globals; no cudaMalloc allowed) -------------
__device__ float g_x1[(size_t)B_*CI*Hh*Ww];
__device__ float g_x2[(size_t)B_*CI*Hh*Ww];
__device__ float g_x3[(size_t)B_*CIN*Hh*Ww];
__device__ float g_p6[(size_t)B_*LL*FIN];
__device__ float g_p4[(size_t)B_*LL*FIN];
__device__ float g_p62[(size_t)B_*LL*FV];
__device__ float g_wf[(size_t)B_*LL*FOUT];
__device__ float g_xf[(size_t)B_*LL*FOUT];
__device__ float g_A[(size_t)B_*LL*LL];
__device__ float g_Ti[(size_t)B_*LL*LL];
__device__ float g_W2[(size_t)B_*LL*FOUT];
__device__ float g_MsumP[(size_t)LL*LLP];
__device__ float g_bsum[LL];
__device__ float g_AmP[(size_t)B_*LL*LLP];
__device__ float g_y[(size_t)B_*LL*FV];
__device__ float g_fold[(size_t)B_*CIN*Hh*Ww];
__device__ float g_o1[(size_t)B_*CI*Hh*Ww];

// Stable logistic, zero iff expf(x) < FLT_MIN (x < ~-87.3365) — matches ref.
static __device__ __forceinline__ float sigmoid_ref(float x) {
    if (x >= 0.f) return 1.f / (1.f + expf(-x));
    float e = expf(x);
    if (e < FLT_MIN) e = 0.f;
    return e / (1.f + e);
}

// ---------------- conv: refpad 3x3, 32->16 twice (x1, x2) --------------------
__global__ void conv3x3_dual_kernel(const float* __restrict__ x,
                                    const float* __restrict__ w1, const float* __restrict__ b1,
                                    const float* __restrict__ w2, const float* __restrict__ b2)
{
    __shared__ float sw1[CI*CIN*9];
    __shared__ float sw2[CI*CIN*9];
    int t = threadIdx.x;
    for (int i = t; i < CI*CIN*9; i += NTHREADS) { sw1[i] = w1[i]; sw2[i] = w2[i]; }
    __syncthreads();
    int pix = blockIdx.x * NTHREADS + t;
    int b = blockIdx.y;
    int h = pix >> 7, w = pix & 127;
    float acc1[CI], acc2[CI];
    #pragma unroll
    for (int co = 0; co < CI; co++) { acc1[co] = b1[co]; acc2[co] = b2[co]; }
    const float* xb = x + (size_t)b * CIN * Hh * Ww;
    for (int ci = 0; ci < CIN; ci++) {
        float v[9];
        #pragma unroll
        for (int dh = 0; dh < 3; dh++) {
            int hh = h + dh - 1;
            hh = hh < 0 ? 1 : (hh >= Hh ? Hh - 2 : hh);
            #pragma unroll
            for (int dw = 0; dw < 3; dw++) {
                int w2p = w + dw - 1;
                w2p = w2p < 0 ? 1 : (w2p >= Ww ? Ww - 2 : w2p);
                v[dh*3 + dw] = xb[(ci*Hh + hh)*Ww + w2p];
            }
        }
        #pragma unroll
        for (int co = 0; co < CI; co++) {
            const float* p1 = &sw1[(co*CIN + ci)*9];
            const float* p2 = &sw2[(co*CIN + ci)*9];
            float s1 = 0.f, s2 = 0.f;
            #pragma unroll
            for (int k = 0; k < 9; k++) { s1 += p1[k]*v[k]; s2 += p2[k]*v[k]; }
            acc1[co] += s1; acc2[co] += s2;
        }
    }
    size_t base = (size_t)b * CI * Hh * Ww + pix;
    #pragma unroll
    for (int co = 0; co < CI; co++) {
        g_x1[base + (size_t)co*Hh*Ww] = acc1[co];
        g_x2[base + (size_t)co*Hh*Ww] = acc2[co];
    }
}

// ---------------- conv: 1x1 theta, x1(16) -> x3(32), +bias -------------------
__global__ void conv1x1_theta_kernel(const float* __restrict__ tw, const float* __restrict__ tb)
{
    __shared__ float sw[CIN*CI];
    int t = threadIdx.x;
    for (int i = t; i < CIN*CI; i += NTHREADS) sw[i] = tw[i];
    __syncthreads();
    int pix = blockIdx.x * NTHREADS + t;
    int b = blockIdx.y;
    float in[CI];
    #pragma unroll
    for (int ci = 0; ci < CI; ci++) in[ci] = g_x1[((size_t)b*CI + ci)*Hh*Ww + pix];
    #pragma unroll
    for (int co = 0; co < CIN; co++) {
        float s = tb[co];
        #pragma unroll
        for (int ci = 0; ci < CI; ci++) s += sw[co*CI + ci]*in[ci];
        g_x3[((size_t)b*CIN + co)*Hh*Ww + pix] = s;
    }
}

// ---------------- unfold: src(B,C,H,W) -> dst(B,L,C*49) ----------------------
__global__ void unfold_kernel(const float* __restrict__ src, float* __restrict__ dst,
                              int C, size_t total)
{
    size_t t = (size_t)blockIdx.x * NTHREADS + threadIdx.x;
    if (t >= total) return;
    int F = C * 49;
    int f = (int)(t % F);
    size_t r = t / F;
    int l = (int)(r % LL);
    int b = (int)(r / LL);
    int c = f / 49, rr = f % 49, kh = rr / 7, kw = rr % 7;
    int h = (l / NHH)*4 + kh, w = (l % NHH)*4 + kw;
    dst[t] = src[(((size_t)b*C + c)*Hh + h)*Ww + w];
}

// ---------------- MsumP (stride 964) = mconv_w + mfc_w; bsum -----------------
__global__ void msum_kernel(const float* __restrict__ mw1, const float* __restrict__ mw2,
                            const float* __restrict__ mb1, const float* __restrict__ mb2)
{
    size_t t = (size_t)blockIdx.x * NTHREADS + threadIdx.x;
    if (t < (size_t)LL*LL) {
        int n = (int)(t / LL), c = (int)(t % LL);
        g_MsumP[(size_t)n*LLP + c] = mw1[t] + mw2[t];
    }
    if (t < LL) g_bsum[t] = mb1[t] + mb2[t];
}

// ============ TF32 tensor-core GEMM (optionally 3xTF32 split) ================
// BT=true : B stored (N,K) row-major  -> C[m,n] = sum_k A[m,k]*B[n,k]
// BT=false: B stored (K,N) row-major  -> C[m,n] = sum_k A[m,k]*B[k,n]
// SPLIT=true: 3xTF32 (hi*hi + hi*lo + lo*hi) ~ fp32 accuracy.
__device__ __forceinline__ unsigned f2tf32(float x) {
    unsigned r;
    asm("cvt.rna.tf32.f32 %0, %1;" : "=r"(r) : "f"(x));
    return r;
}
__device__ __forceinline__ void mma_tf32(float c[4],
    unsigned a0, unsigned a1, unsigned a2, unsigned a3, unsigned b0, unsigned b1)
{
    asm volatile("mma.sync.aligned.m16n8k8.row.col.f32.tf32.tf32.f32 "
        "{%0,%1,%2,%3}, {%4,%5,%6,%7}, {%8,%9}, {%0,%1,%2,%3};"
        : "+f"(c[0]), "+f"(c[1]), "+f"(c[2]), "+f"(c[3])
        : "r"(a0), "r"(a1), "r"(a2), "r"(a3), "r"(b0), "r"(b1));
}

template <bool BT, bool SPLIT>
__global__ void __launch_bounds__(256, 2) gemm_tc_kernel(
    const float* __restrict__ Ag, const float* __restrict__ Bg,
    float* __restrict__ Cg, int M, int N, int K,
    int lda, int ldb, int ldc, long long sA, long long sB, long long sC,
    const float* __restrict__ rowBias, const float* __restrict__ colBias)
{
    __shared__ unsigned Ash[16][132];               // [k][m] tf32 hi bits
    __shared__ unsigned Bsh[16][132];               // [k][n]
    __shared__ unsigned Asl[SPLIT ? 16 : 1][SPLIT ? 132 : 1];
    __shared__ unsigned Bsl[SPLIT ? 16 : 1][SPLIT ? 132 : 1];

    const int tid = threadIdx.x;
    const int wid = tid >> 5, lane = tid & 31;
    const int wm = wid >> 2, wn = wid & 3;        // 2 x 4 warp grid
    const int m_w = wm * 64, n_w = wn * 32;       // 64 x 32 warp tile
    const int g = lane >> 2, tg = lane & 3;
    const int m0 = blockIdx.y * 128, n0 = blockIdx.x * 128;
    const float* Ab = Ag + (long long)blockIdx.z * sA;
    const float* Bb = Bg + (long long)blockIdx.z * sB;
    float*       Cb = Cg + (long long)blockIdx.z * sC;

    float acc[4][4][4];
    #pragma unroll
    for (int i = 0; i < 4; i++)
        #pragma unroll
        for (int j = 0; j < 4; j++)
            #pragma unroll
            for (int q = 0; q < 4; q++) acc[i][j][q] = 0.f;

    const int a_c = (tid & 3) * 4;   // k offset within 16-chunk
    const int a_r = tid >> 2;        // 0..63
    const int bn_q = (tid & 31) * 4; // n offset (BT=false B loads)
    const int bk_r = tid >> 5;       // 0..7

    for (int k0 = 0; k0 < K; k0 += 16) {
        const bool fullk = (k0 + 16 <= K);
        // ---- A tile: rows m, k contiguous ----
        #pragma unroll
        for (int i = 0; i < 2; i++) {
            int m = a_r + 64*i;
            int gm = m0 + m;
            float4 v = make_float4(0.f,0.f,0.f,0.f);
            if (gm < M) {
                const float* p = Ab + (long long)gm*lda + k0 + a_c;
                if (fullk) v = *(const float4*)p;
                else {
                    if (k0 + a_c + 0 < K) v.x = p[0];
                    if (k0 + a_c + 1 < K) v.y = p[1];
                    if (k0 + a_c + 2 < K) v.z = p[2];
                    if (k0 + a_c + 3 < K) v.w = p[3];
                }
            }
            unsigned h0 = f2tf32(v.x), h1 = f2tf32(v.y),
                     h2 = f2tf32(v.z), h3 = f2tf32(v.w);
            Ash[a_c+0][m] = h0; Ash[a_c+1][m] = h1;
            Ash[a_c+2][m] = h2; Ash[a_c+3][m] = h3;
            if (SPLIT) {
                Asl[a_c+0][m] = f2tf32(v.x - __uint_as_float(h0));
                Asl[a_c+1][m] = f2tf32(v.y - __uint_as_float(h1));
                Asl[a_c+2][m] = f2tf32(v.z - __uint_as_float(h2));
                Asl[a_c+3][m] = f2tf32(v.w - __uint_as_float(h3));
            }
        }
        // ---- B tile ----
        if (BT) {
            #pragma unroll
            for (int i = 0; i < 2; i++) {
                int n = a_r + 64*i;
                int gn = n0 + n;
                float4 v = make_float4(0.f,0.f,0.f,0.f);
                if (gn < N) {
                    const float* p = Bb + (long long)gn*ldb + k0 + a_c;
                    if (fullk) v = *(const float4*)p;
                    else {
                        if (k0 + a_c + 0 < K) v.x = p[0];
                        if (k0 + a_c + 1 < K) v.y = p[1];
                        if (k0 + a_c + 2 < K) v.z = p[2];
                        if (k0 + a_c + 3 < K) v.w = p[3];
                    }
                }
                unsigned h0 = f2tf32(v.x), h1 = f2tf32(v.y),
                         h2 = f2tf32(v.z), h3 = f2tf32(v.w);
                Bsh[a_c+0][n] = h0; Bsh[a_c+1][n] = h1;
                Bsh[a_c+2][n] = h2; Bsh[a_c+3][n] = h3;
                if (SPLIT) {
                    Bsl[a_c+0][n] = f2tf32(v.x - __uint_as_float(h0));
                    Bsl[a_c+1][n] = f2tf32(v.y - __uint_as_float(h1));
                    Bsl[a_c+2][n] = f2tf32(v.z - __uint_as_float(h2));
                    Bsl[a_c+3][n] = f2tf32(v.w - __uint_as_float(h3));
                }
            }
        } else {
            #pragma unroll
            for (int i = 0; i < 2; i++) {
                int k = bk_r + 8*i;
                int gk = k0 + k;
                int gn = n0 + bn_q;
                float4 v = make_float4(0.f,0.f,0.f,0.f);
                if (gk < K) {
                    const float* p = Bb + (long long)gk*ldb + gn;
                    if (gn + 3 < N) v = *(const float4*)p;
                    else {
                        if (gn+0 < N) v.x = p[0];
                        if (gn+1 < N) v.y = p[1];
                        if (gn+2 < N) v.z = p[2];
                    }
                }
                unsigned h0 = f2tf32(v.x), h1 = f2tf32(v.y),
                         h2 = f2tf32(v.z), h3 = f2tf32(v.w);
                Bsh[k][bn_q+0] = h0; Bsh[k][bn_q+1] = h1;
                Bsh[k][bn_q+2] = h2; Bsh[k][bn_q+3] = h3;
                if (SPLIT) {
                    Bsl[k][bn_q+0] = f2tf32(v.x - __uint_as_float(h0));
                    Bsl[k][bn_q+1] = f2tf32(v.y - __uint_as_float(h1));
                    Bsl[k][bn_q+2] = f2tf32(v.z - __uint_as_float(h2));
                    Bsl[k][bn_q+3] = f2tf32(v.w - __uint_as_float(h3));
                }
            }
        }
        __syncthreads();
        #pragma unroll
        for (int kk = 0; kk < 16; kk += 8) {
            unsigned bh[4][2], bl[4][2];
            #pragma unroll
            for (int nt = 0; nt < 4; nt++) {
                int n = n_w + nt*8 + g;
                bh[nt][0] = Bsh[kk + tg][n];
                bh[nt][1] = Bsh[kk + tg + 4][n];
                if (SPLIT) {
                    bl[nt][0] = Bsl[kk + tg][n];
                    bl[nt][1] = Bsl[kk + tg + 4][n];
                }
            }
            #pragma unroll
            for (int mt = 0; mt < 4; mt++) {
                int m = m_w + mt*16 + g;
                unsigned ah0 = Ash[kk + tg][m];
                unsigned ah1 = Ash[kk + tg][m + 8];
                unsigned ah2 = Ash[kk + tg + 4][m];
                unsigned ah3 = Ash[kk + tg + 4][m + 8];
                if (SPLIT) {
                    unsigned al0 = Asl[kk + tg][m];
                    unsigned al1 = Asl[kk + tg][m + 8];
                    unsigned al2 = Asl[kk + tg + 4][m];
                    unsigned al3 = Asl[kk + tg + 4][m + 8];
                    #pragma unroll
                    for (int nt = 0; nt < 4; nt++) {
                        mma_tf32(acc[mt][nt], ah0, ah1, ah2, ah3, bh[nt][0], bh[nt][1]);
                        mma_tf32(acc[mt][nt], ah0, ah1, ah2, ah3, bl[nt][0], bl[nt][1]);
                        mma_tf32(acc[mt][nt], al0, al1, al2, al3, bh[nt][0], bh[nt][1]);
                    }
                } else {
                    #pragma unroll
                    for (int nt = 0; nt < 4; nt++)
                        mma_tf32(acc[mt][nt], ah0, ah1, ah2, ah3, bh[nt][0], bh[nt][1]);
                }
            }
        }
        __syncthreads();
    }
    #pragma unroll
    for (int mt = 0; mt < 4; mt++) {
        #pragma unroll
        for (int nt = 0; nt < 4; nt++) {
            int r0 = m0 + m_w + mt*16 + g;
            int r1 = r0 + 8;
            int c  = n0 + n_w + nt*8 + 2*tg;
            float rb0 = (rowBias && r0 < M) ? rowBias[r0] : 0.f;
            float rb1 = (rowBias && r1 < M) ? rowBias[r1] : 0.f;
            float cb0 = (colBias && c   < N) ? colBias[c]   : 0.f;
            float cb1 = (colBias && c+1 < N) ? colBias[c+1] : 0.f;
            if (r0 < M) {
                if (c   < N) Cb[(long long)r0*ldc + c]   = acc[mt][nt][0] + rb0 + cb0;
                if (c+1 < N) Cb[(long long)r0*ldc + c+1] = acc[mt][nt][1] + rb0 + cb1;
            }
            if (r1 < M) {
                if (c   < N) Cb[(long long)r1*ldc + c]   = acc[mt][nt][2] + rb1 + cb0;
                if (c+1 < N) Cb[(long long)r1*ldc + c+1] = acc[mt][nt][3] + rb1 + cb1;
            }
        }
    }
}

// ---------------- masked softmax -> Am (d_out) + AmP (padded) ----------------
__global__ void softmax_kernel(float* __restrict__ Am)
{
    int row = blockIdx.x;                    // b*L + l
    const float* Ar = g_A  + (size_t)row * LL;
    const float* Tr = g_Ti + (size_t)row * LL;
    int t = threadIdx.x;
    const float scale = 0.07142857142857142f;
    float v[4], mb[4];
    float mx = -INFINITY;
    #pragma unroll
    for (int i = 0; i < 4; i++) {
        int m = t + i*NTHREADS;
        v[i] = 0.f; mb[i] = 0.f;
        if (m < LL) {
            float mask = sigmoid_ref(Tr[m]);
            v[i] = Ar[m] * mask * scale;
            mb[i] = (mask != 0.f) ? 1.f : 0.f;
            mx = fmaxf(mx, v[i]);
        }
    }
    __shared__ float red[NTHREADS];
    red[t] = mx; __syncthreads();
    for (int s = NTHREADS/2; s > 0; s >>= 1) {
        if (t < s) red[t] = fmaxf(red[t], red[t+s]);
        __syncthreads();
    }
    mx = red[0]; __syncthreads();
    float e[4]; float sum = 0.f;
    #pragma unroll
    for (int i = 0; i < 4; i++) {
        int m = t + i*NTHREADS;
        if (m < LL) { e[i] = expf(v[i] - mx); sum += e[i]; } else e[i] = 0.f;
    }
    red[t] = sum; __syncthreads();
    for (int s = NTHREADS/2; s > 0; s >>= 1) {
        if (t < s) red[t] += red[t+s];
        __syncthreads();
    }
    float inv = 1.f / red[0];
    #pragma unroll
    for (int i = 0; i < 4; i++) {
        int m = t + i*NTHREADS;
        if (m < LL) {
            float val = e[i] * inv * mb[i];
            Am[(size_t)row*LL + m] = val;
            g_AmP[(size_t)row*LLP + m] = val;
        }
    }
}

// ---------------- fold (gather form, no atomics) ------------------------------
__global__ void fold_kernel()
{
    size_t t = (size_t)blockIdx.x * NTHREADS + threadIdx.x;
    if (t >= (size_t)B_*CIN*Hh*Ww) return;
    int w = (int)(t % Ww); size_t r = t / Ww;
    int h = (int)(r % Hh); r /= Hh;
    int c = (int)(r % CIN);
    int b = (int)(r / CIN);
    int i0 = (h > 6) ? (h - 3) >> 2 : 0;
    int i1 = h >> 2; if (i1 > NHH - 1) i1 = NHH - 1;
    int j0 = (w > 6) ? (w - 3) >> 2 : 0;
    int j1 = w >> 2; if (j1 > NHH - 1) j1 = NHH - 1;
    float s = 0.f;
    for (int i = i0; i <= i1; i++) {
        int kh = h - i*4;
        for (int j = j0; j <= j1; j++) {
            int kw = w - j*4;
            s += g_y[((size_t)b*LL + i*NHH + j)*FV + c*49 + kh*7 + kw];
        }
    }
    g_fold[t] = s;
}

// ---------------- conv c1: refpad 3x3, 32->16, leaky(0.2) --------------------
__global__ void conv3x3_c1_kernel(const float* __restrict__ w1)
{
    __shared__ float sw[CI*CIN*9];
    int t = threadIdx.x;
    for (int i = t; i < CI*CIN*9; i += NTHREADS) sw[i] = w1[i];
    __syncthreads();
    int pix = blockIdx.x * NTHREADS + t;
    int b = blockIdx.y;
    int h = pix >> 7, w = pix & 127;
    float acc[CI];
    #pragma unroll
    for (int co = 0; co < CI; co++) acc[co] = 0.f;
    const float* xb = g_fold + (size_t)b * CIN * Hh * Ww;
    for (int ci = 0; ci < CIN; ci++) {
        float v[9];
        #pragma unroll
        for (int dh = 0; dh < 3; dh++) {
            int hh = h + dh - 1;
            hh = hh < 0 ? 1 : (hh >= Hh ? Hh - 2 : hh);
            #pragma unroll
            for (int dw = 0; dw < 3; dw++) {
                int w2p = w + dw - 1;
                w2p = w2p < 0 ? 1 : (w2p >= Ww ? Ww - 2 : w2p);
                v[dh*3 + dw] = xb[(ci*Hh + hh)*Ww + w2p];
            }
        }
        #pragma unroll
        for (int co = 0; co < CI; co++) {
            const float* p1 = &sw[(co*CIN + ci)*9];
            float s1 = 0.f;
            #pragma unroll
            for (int k = 0; k < 9; k++) s1 += p1[k]*v[k];
            acc[co] += s1;
        }
    }
    size_t base = (size_t)b * CI * Hh * Ww + pix;
    #pragma unroll
    for (int co = 0; co < CI; co++) {
        float s = acc[co];
        g_o1[base + (size_t)co*Hh*Ww] = (s > 0.f) ? s : 0.2f*s;
    }
}

// ---------------- conv c2: 1x1 16->32, leaky(0.2), + residual ----------------
__global__ void conv1x1_c2_res_kernel(const float* __restrict__ cw,
                                      const float* __restrict__ x,
                                      float* __restrict__ outp)
{
    __shared__ float sw[CIN*CI];
    int t = threadIdx.x;
    for (int i = t; i < CIN*CI; i += NTHREADS) sw[i] = cw[i];
    __syncthreads();
    int pix = blockIdx.x * NTHREADS + t;
    int b = blockIdx.y;
    float in[CI];
    #pragma unroll
    for (int ci = 0; ci < CI; ci++) in[ci] = g_o1[((size_t)b*CI + ci)*Hh*Ww + pix];
    #pragma unroll
    for (int co = 0; co < CIN; co++) {
        float s = 0.f;
        #pragma unroll
        for (int ci = 0; ci < CI; ci++) s += sw[co*CI + ci]*in[ci];
        s = (s > 0.f) ? s : 0.2f*s;
        size_t idx = ((size_t)b*CIN + co)*Hh*Ww + pix;
        outp[idx] = x[idx] + s;
    }
}

// ---------------- launch ------------------------------------------------------
extern "C" void kernel_launch(void* const* d_in, const int* in_sizes, int n_in,
                              void* d_out, int out_size)
{
    const float* x        = (const float*)d_in[0];
    const float* g_w      = (const float*)d_in[1];
    const float* g_b      = (const float*)d_in[2];
    const float* w_w      = (const float*)d_in[3];
    const float* w_b      = (const float*)d_in[4];
    const float* theta_w  = (const float*)d_in[5];
    const float* theta_b  = (const float*)d_in[6];
    const float* fc1_w    = (const float*)d_in[7];
    const float* fc1_b    = (const float*)d_in[8];
    const float* mconv_w  = (const float*)d_in[9];
    const float* mconv_b  = (const float*)d_in[10];
    const float* mfc_w    = (const float*)d_in[11];
    const float* mfc_b    = (const float*)d_in[12];
    const float* c1_w     = (const float*)d_in[13];
    const float* c2_w     = (const float*)d_in[14];
    float* out = (float*)d_out;

    float *px1, *px2, *px3, *pp6, *pp4, *pp62, *pwf, *pxf, *pA, *pTi, *pW2,
          *pMsumP, *pbsum, *pAmP, *py;
    cudaGetSymbolAddress((void**)&px1,   g_x1);
    cudaGetSymbolAddress((void**)&px2,   g_x2);
    cudaGetSymbolAddress((void**)&px3,   g_x3);
    cudaGetSymbolAddress((void**)&pp6,   g_p6);
    cudaGetSymbolAddress((void**)&pp4,   g_p4);
    cudaGetSymbolAddress((void**)&pp62,  g_p62);
    cudaGetSymbolAddress((void**)&pwf,   g_wf);
    cudaGetSymbolAddress((void**)&pxf,   g_xf);
    cudaGetSymbolAddress((void**)&pA,    g_A);
    cudaGetSymbolAddress((void**)&pTi,   g_Ti);
    cudaGetSymbolAddress((void**)&pW2,   g_W2);
    cudaGetSymbolAddress((void**)&pMsumP,g_MsumP);
    cudaGetSymbolAddress((void**)&pbsum, g_bsum);
    cudaGetSymbolAddress((void**)&pAmP,  g_AmP);
    cudaGetSymbolAddress((void**)&py,    g_y);

    dim3 convGrid(Hh*Ww/NTHREADS, B_);

    conv3x3_dual_kernel<<<convGrid, NTHREADS>>>(x, g_w, g_b, w_w, w_b);
    conv1x1_theta_kernel<<<convGrid, NTHREADS>>>(theta_w, theta_b);

    {
        size_t tot = (size_t)B_*LL*FIN;
        int nb = (int)((tot + NTHREADS - 1) / NTHREADS);
        unfold_kernel<<<nb, NTHREADS>>>(px1, pp6,  CI, tot);
        unfold_kernel<<<nb, NTHREADS>>>(px2, pp4,  CI, tot);
    }
    {
        size_t tot = (size_t)B_*LL*FV;
        int nb = (int)((tot + NTHREADS - 1) / NTHREADS);
        unfold_kernel<<<nb, NTHREADS>>>(px3, pp62, CIN, tot);
    }

    msum_kernel<<<(int)(((size_t)LL*LL + NTHREADS - 1)/NTHREADS), NTHREADS>>>(
        mconv_w, mfc_w, mconv_b, mfc_b);

    // wf = p4 @ fc1_w^T + fc1_b ; xf = p6 @ fc1_w^T + fc1_b  (3xTF32)
    {
        dim3 g((FOUT + 127)/128, (B_*LL + 127)/128, 1);
        gemm_tc_kernel<true,true><<<g, 256>>>(pp4, fc1_w, pwf, B_*LL, FOUT, FIN,
                                              FIN, FIN, FOUT, 0, 0, 0,
                                              nullptr, fc1_b);
        gemm_tc_kernel<true,true><<<g, 256>>>(pp6, fc1_w, pxf, B_*LL, FOUT, FIN,
                                              FIN, FIN, FOUT, 0, 0, 0,
                                              nullptr, fc1_b);
    }
    // A[b] = wf[b] @ xf[b]^T  (3xTF32)
    {
        dim3 g((LL + 127)/128, (LL + 127)/128, B_);
        gemm_tc_kernel<true,true><<<g, 256>>>(pwf, pxf, pA, LL, LL, FOUT,
                                              FOUT, FOUT, LL,
                                              (long long)LL*FOUT, (long long)LL*FOUT,
                                              (long long)LL*LL, nullptr, nullptr);
    }
    // W2[b] = Msum @ wf[b]  (assoc. rewrite; 3xTF32)
    {
        dim3 g((FOUT + 127)/128, (LL + 127)/128, B_);
        gemm_tc_kernel<false,true><<<g, 256>>>(pMsumP, pwf, pW2, LL, FOUT, LL,
                                               LLP, FOUT, FOUT,
                                               0, (long long)LL*FOUT, (long long)LL*FOUT,
                                               nullptr, nullptr);
    }
    // Ti[b] = W2[b] @ xf[b]^T + bsum  (3xTF32)
    {
        dim3 g((LL + 127)/128, (LL + 127)/128, B_);
        gemm_tc_kernel<true,true><<<g, 256>>>(pW2, pxf, pTi, LL, LL, FOUT,
                                              FOUT, FOUT, LL,
                                              (long long)LL*FOUT, (long long)LL*FOUT,
                                              (long long)LL*LL, pbsum, nullptr);
    }

    softmax_kernel<<<B_*LL, NTHREADS>>>(out);

    // y[b] = Am[b] @ p62[b]  (single-pass TF32)
    {
        dim3 g((FV + 127)/128, (LL + 127)/128, B_);
        gemm_tc_kernel<false,false><<<g, 256>>>(pAmP, pp62, py, LL, FV, LL,
                                                LLP, FV, FV,
                                                (long long)LL*LLP, (long long)LL*FV,
                                                (long long)LL*FV, nullptr, nullptr);
    }

    fold_kernel<<<(int)(((size_t)B_*CIN*Hh*Ww + NTHREADS - 1)/NTHREADS), NTHREADS>>>();
    conv3x3_c1_kernel<<<convGrid, NTHREADS>>>(c1_w);
    conv1x1_c2_res_kernel<<<convGrid, NTHREADS>>>(c2_w, x, out + (size_t)B_*LL*LL);
}

// round 6
// speedup vs baseline: 1.5314x; 1.5314x over previous
#include <cuda_runtime.h>
#include <math.h>
#include <float.h>

#define B_   8
#define CIN  32
#define CI   16
#define Hh   128
#define Ww   128
#define NHH  31
#define LL   961
#define LLP  964      // padded row stride (%4==0)
#define FIN  784
#define FOUT 196
#define FV   1568
#define NTHREADS 256

// ---------------- scratch (device globals; no cudaMalloc allowed) -------------
__device__ float g_x1[(size_t)B_*CI*Hh*Ww];
__device__ float g_x2[(size_t)B_*CI*Hh*Ww];
__device__ float g_x3[(size_t)B_*CIN*Hh*Ww];
__device__ float g_p6[(size_t)B_*LL*FIN];
__device__ float g_p4[(size_t)B_*LL*FIN];
__device__ float g_p62[(size_t)B_*LL*FV];
__device__ float g_wf[(size_t)B_*LL*FOUT];
__device__ float g_xf[(size_t)B_*LL*FOUT];
__device__ float g_A[(size_t)B_*LL*LL];
__device__ float g_Ti[(size_t)B_*LL*LL];
__device__ float g_W2[(size_t)B_*LL*FOUT];
__device__ float g_MsumP[(size_t)LL*LLP];
__device__ float g_bsum[LL];
__device__ float g_AmP[(size_t)B_*LL*LLP];
__device__ float g_y[(size_t)B_*LL*FV];
__device__ float g_fold[(size_t)B_*CIN*Hh*Ww];
__device__ float g_o1[(size_t)B_*CI*Hh*Ww];

// Stable logistic, zero iff expf(x) < FLT_MIN (x < ~-87.3365) — matches ref.
static __device__ __forceinline__ float sigmoid_ref(float x) {
    if (x >= 0.f) return 1.f / (1.f + expf(-x));
    float e = expf(x);
    if (e < FLT_MIN) e = 0.f;
    return e / (1.f + e);
}

// ---------------- conv: refpad 3x3, 32->16 twice (x1, x2) --------------------
__global__ void conv3x3_dual_kernel(const float* __restrict__ x,
                                    const float* __restrict__ w1, const float* __restrict__ b1,
                                    const float* __restrict__ w2, const float* __restrict__ b2)
{
    __shared__ float sw1[CI*CIN*9];
    __shared__ float sw2[CI*CIN*9];
    int t = threadIdx.x;
    for (int i = t; i < CI*CIN*9; i += NTHREADS) { sw1[i] = w1[i]; sw2[i] = w2[i]; }
    __syncthreads();
    int pix = blockIdx.x * NTHREADS + t;
    int b = blockIdx.y;
    int h = pix >> 7, w = pix & 127;
    float acc1[CI], acc2[CI];
    #pragma unroll
    for (int co = 0; co < CI; co++) { acc1[co] = b1[co]; acc2[co] = b2[co]; }
    const float* xb = x + (size_t)b * CIN * Hh * Ww;
    for (int ci = 0; ci < CIN; ci++) {
        float v[9];
        #pragma unroll
        for (int dh = 0; dh < 3; dh++) {
            int hh = h + dh - 1;
            hh = hh < 0 ? 1 : (hh >= Hh ? Hh - 2 : hh);
            #pragma unroll
            for (int dw = 0; dw < 3; dw++) {
                int w2p = w + dw - 1;
                w2p = w2p < 0 ? 1 : (w2p >= Ww ? Ww - 2 : w2p);
                v[dh*3 + dw] = xb[(ci*Hh + hh)*Ww + w2p];
            }
        }
        #pragma unroll
        for (int co = 0; co < CI; co++) {
            const float* p1 = &sw1[(co*CIN + ci)*9];
            const float* p2 = &sw2[(co*CIN + ci)*9];
            float s1 = 0.f, s2 = 0.f;
            #pragma unroll
            for (int k = 0; k < 9; k++) { s1 += p1[k]*v[k]; s2 += p2[k]*v[k]; }
            acc1[co] += s1; acc2[co] += s2;
        }
    }
    size_t base = (size_t)b * CI * Hh * Ww + pix;
    #pragma unroll
    for (int co = 0; co < CI; co++) {
        g_x1[base + (size_t)co*Hh*Ww] = acc1[co];
        g_x2[base + (size_t)co*Hh*Ww] = acc2[co];
    }
}

// ---------------- conv: 1x1 theta, x1(16) -> x3(32), +bias -------------------
__global__ void conv1x1_theta_kernel(const float* __restrict__ tw, const float* __restrict__ tb)
{
    __shared__ float sw[CIN*CI];
    int t = threadIdx.x;
    for (int i = t; i < CIN*CI; i += NTHREADS) sw[i] = tw[i];
    __syncthreads();
    int pix = blockIdx.x * NTHREADS + t;
    int b = blockIdx.y;
    float in[CI];
    #pragma unroll
    for (int ci = 0; ci < CI; ci++) in[ci] = g_x1[((size_t)b*CI + ci)*Hh*Ww + pix];
    #pragma unroll
    for (int co = 0; co < CIN; co++) {
        float s = tb[co];
        #pragma unroll
        for (int ci = 0; ci < CI; ci++) s += sw[co*CI + ci]*in[ci];
        g_x3[((size_t)b*CIN + co)*Hh*Ww + pix] = s;
    }
}

// ---------------- unfold: src(B,C,H,W) -> dst(B,L,C*49) ----------------------
__global__ void unfold_kernel(const float* __restrict__ src, float* __restrict__ dst,
                              int C, size_t total)
{
    size_t t = (size_t)blockIdx.x * NTHREADS + threadIdx.x;
    if (t >= total) return;
    int F = C * 49;
    int f = (int)(t % F);
    size_t r = t / F;
    int l = (int)(r % LL);
    int b = (int)(r / LL);
    int c = f / 49, rr = f % 49, kh = rr / 7, kw = rr % 7;
    int h = (l / NHH)*4 + kh, w = (l % NHH)*4 + kw;
    dst[t] = src[(((size_t)b*C + c)*Hh + h)*Ww + w];
}

// ---------------- MsumP (stride 964) = mconv_w + mfc_w; bsum -----------------
__global__ void msum_kernel(const float* __restrict__ mw1, const float* __restrict__ mw2,
                            const float* __restrict__ mb1, const float* __restrict__ mb2)
{
    size_t t = (size_t)blockIdx.x * NTHREADS + threadIdx.x;
    if (t < (size_t)LL*LL) {
        int n = (int)(t / LL), c = (int)(t % LL);
        g_MsumP[(size_t)n*LLP + c] = mw1[t] + mw2[t];
    }
    if (t < LL) g_bsum[t] = mb1[t] + mb2[t];
}

// ============ fp32 SGEMM: 128x128x16, 8x8/thread, float4 (R4 proven) =========
template <bool BT>
__global__ void __launch_bounds__(256, 2) gemm128_kernel(
    const float* __restrict__ Ag, const float* __restrict__ Bg,
    float* __restrict__ Cg, int M, int N, int K,
    int lda, int ldb, int ldc,
    long long sA, long long sB, long long sC,
    const float* __restrict__ rowBias, const float* __restrict__ colBias)
{
    __shared__ float As[16][132];
    __shared__ float Bs[16][132];
    const int tid = threadIdx.x;
    const int tx = tid & 15, ty = tid >> 4;
    const int m0 = blockIdx.y * 128, n0 = blockIdx.x * 128;
    const float* Ab = Ag + (long long)blockIdx.z * sA;
    const float* Bb = Bg + (long long)blockIdx.z * sB;
    float*       Cb = Cg + (long long)blockIdx.z * sC;

    float acc[8][8];
    #pragma unroll
    for (int i = 0; i < 8; i++)
        #pragma unroll
        for (int j = 0; j < 8; j++) acc[i][j] = 0.f;

    const int a_c = (tid & 3) * 4;
    const int a_r = tid >> 2;
    const int bn_q = (tid & 31) * 4;
    const int bk_r = tid >> 5;

    for (int k0 = 0; k0 < K; k0 += 16) {
        const bool fullk = (k0 + 16 <= K);
        #pragma unroll
        for (int i = 0; i < 2; i++) {
            int m = a_r + 64*i;
            int gm = m0 + m;
            float4 v = make_float4(0.f,0.f,0.f,0.f);
            if (gm < M) {
                const float* p = Ab + (long long)gm*lda + k0 + a_c;
                if (fullk) v = *(const float4*)p;
                else {
                    if (k0 + a_c + 0 < K) v.x = p[0];
                    if (k0 + a_c + 1 < K) v.y = p[1];
                    if (k0 + a_c + 2 < K) v.z = p[2];
                    if (k0 + a_c + 3 < K) v.w = p[3];
                }
            }
            As[a_c+0][m] = v.x; As[a_c+1][m] = v.y;
            As[a_c+2][m] = v.z; As[a_c+3][m] = v.w;
        }
        if (BT) {
            #pragma unroll
            for (int i = 0; i < 2; i++) {
                int n = a_r + 64*i;
                int gn = n0 + n;
                float4 v = make_float4(0.f,0.f,0.f,0.f);
                if (gn < N) {
                    const float* p = Bb + (long long)gn*ldb + k0 + a_c;
                    if (fullk) v = *(const float4*)p;
                    else {
                        if (k0 + a_c + 0 < K) v.x = p[0];
                        if (k0 + a_c + 1 < K) v.y = p[1];
                        if (k0 + a_c + 2 < K) v.z = p[2];
                        if (k0 + a_c + 3 < K) v.w = p[3];
                    }
                }
                Bs[a_c+0][n] = v.x; Bs[a_c+1][n] = v.y;
                Bs[a_c+2][n] = v.z; Bs[a_c+3][n] = v.w;
            }
        } else {
            #pragma unroll
            for (int i = 0; i < 2; i++) {
                int k = bk_r + 8*i;
                int gk = k0 + k;
                int gn = n0 + bn_q;
                float4 v = make_float4(0.f,0.f,0.f,0.f);
                if (gk < K) {
                    const float* p = Bb + (long long)gk*ldb + gn;
                    if (gn + 3 < N) v = *(const float4*)p;
                    else {
                        if (gn+0 < N) v.x = p[0];
                        if (gn+1 < N) v.y = p[1];
                        if (gn+2 < N) v.z = p[2];
                    }
                }
                *(float4*)&Bs[k][bn_q] = v;
            }
        }
        __syncthreads();
        #pragma unroll
        for (int k = 0; k < 16; k++) {
            float a[8], b[8];
            *(float4*)&a[0] = *(const float4*)&As[k][ty*8];
            *(float4*)&a[4] = *(const float4*)&As[k][ty*8+4];
            *(float4*)&b[0] = *(const float4*)&Bs[k][tx*8];
            *(float4*)&b[4] = *(const float4*)&Bs[k][tx*8+4];
            #pragma unroll
            for (int i = 0; i < 8; i++)
                #pragma unroll
                for (int j = 0; j < 8; j++) acc[i][j] += a[i]*b[j];
        }
        __syncthreads();
    }
    #pragma unroll
    for (int i = 0; i < 8; i++) {
        int gm = m0 + ty*8 + i;
        if (gm >= M) continue;
        float rb = rowBias ? rowBias[gm] : 0.f;
        #pragma unroll
        for (int j = 0; j < 8; j++) {
            int gn = n0 + tx*8 + j;
            if (gn < N) {
                float v = acc[i][j] + rb;
                if (colBias) v += colBias[gn];
                Cb[(long long)gm*ldc + gn] = v;
            }
        }
    }
}

// ============ TF32 y-GEMM: double-buffered, conflict-free (stride 136) =======
// C[m,n] = sum_k A[m,k]*B[k,n]; 128x128 tile, 8 warps (2m x 4n), BK=16.
__device__ __forceinline__ unsigned f2tf32(float x) {
    unsigned r;
    asm("cvt.rna.tf32.f32 %0, %1;" : "=r"(r) : "f"(x));
    return r;
}
__device__ __forceinline__ void mma_tf32(float c[4],
    unsigned a0, unsigned a1, unsigned a2, unsigned a3, unsigned b0, unsigned b1)
{
    asm volatile("mma.sync.aligned.m16n8k8.row.col.f32.tf32.tf32.f32 "
        "{%0,%1,%2,%3}, {%4,%5,%6,%7}, {%8,%9}, {%0,%1,%2,%3};"
        : "+f"(c[0]), "+f"(c[1]), "+f"(c[2]), "+f"(c[3])
        : "r"(a0), "r"(a1), "r"(a2), "r"(a3), "r"(b0), "r"(b1));
}

__global__ void __launch_bounds__(256, 2) gemm_tf32_db_kernel(
    const float* __restrict__ Ag, const float* __restrict__ Bg,
    float* __restrict__ Cg, int M, int N, int K,
    int lda, int ldb, int ldc, long long sA, long long sB, long long sC)
{
    __shared__ unsigned As[2][16][136];   // [stage][k][m]; 136%32=8 -> conflict-free frags
    __shared__ unsigned Bs[2][16][136];   // [stage][k][n]

    const int tid = threadIdx.x;
    const int wid = tid >> 5, lane = tid & 31;
    const int wm = wid >> 2, wn = wid & 3;
    const int m_w = wm * 64, n_w = wn * 32;
    const int g = lane >> 2, tg = lane & 3;
    const int m0 = blockIdx.y * 128, n0 = blockIdx.x * 128;
    const float* Ab = Ag + (long long)blockIdx.z * sA;
    const float* Bb = Bg + (long long)blockIdx.z * sB;
    float*       Cb = Cg + (long long)blockIdx.z * sC;

    float acc[4][4][4];
    #pragma unroll
    for (int i = 0; i < 4; i++)
        #pragma unroll
        for (int j = 0; j < 4; j++)
            #pragma unroll
            for (int q = 0; q < 4; q++) acc[i][j][q] = 0.f;

    const int a_c = (tid & 3) * 4;   // k offset within chunk
    const int a_r = tid >> 2;        // 0..63 (m row group)
    const int bn_q = (tid & 31) * 4; // n offset
    const int bk_r = tid >> 5;       // 0..7 (k row group)

    const int nchunks = (K + 15) / 16;
    float4 va[2], vb[2];

    // ---- load chunk helpers (fully guarded) ----
    #define LOAD_A_CHUNK(k0)                                                   \
        _Pragma("unroll")                                                      \
        for (int i = 0; i < 2; i++) {                                          \
            int gm = m0 + a_r + 64*i;                                          \
            float4 v = make_float4(0.f,0.f,0.f,0.f);                           \
            if (gm < M) {                                                      \
                const float* p = Ab + (long long)gm*lda + (k0) + a_c;          \
                if ((k0) + a_c + 3 < K) v = *(const float4*)p;                 \
                else {                                                         \
                    if ((k0) + a_c + 0 < K) v.x = p[0];                        \
                    if ((k0) + a_c + 1 < K) v.y = p[1];                        \
                    if ((k0) + a_c + 2 < K) v.z = p[2];                        \
                }                                                              \
            }                                                                  \
            va[i] = v;                                                         \
        }
    #define LOAD_B_CHUNK(k0)                                                   \
        _Pragma("unroll")                                                      \
        for (int i = 0; i < 2; i++) {                                          \
            int gk = (k0) + bk_r + 8*i;                                        \
            int gn = n0 + bn_q;                                                \
            float4 v = make_float4(0.f,0.f,0.f,0.f);                           \
            if (gk < K) {                                                      \
                const float* p = Bb + (long long)gk*ldb + gn;                  \
                if (gn + 3 < N) v = *(const float4*)p;                         \
                else {                                                         \
                    if (gn+0 < N) v.x = p[0];                                  \
                    if (gn+1 < N) v.y = p[1];                                  \
                    if (gn+2 < N) v.z = p[2];                                  \
                }                                                              \
            }                                                                  \
            vb[i] = v;                                                         \
        }
    #define STORE_CHUNK(st)                                                    \
        _Pragma("unroll")                                                      \
        for (int i = 0; i < 2; i++) {                                          \
            int m = a_r + 64*i;                                                \
            As[st][a_c+0][m] = f2tf32(va[i].x);                                \
            As[st][a_c+1][m] = f2tf32(va[i].y);                                \
            As[st][a_c+2][m] = f2tf32(va[i].z);                                \
            As[st][a_c+3][m] = f2tf32(va[i].w);                                \
            int k = bk_r + 8*i;                                                \
            Bs[st][k][bn_q+0] = f2tf32(vb[i].x);                               \
            Bs[st][k][bn_q+1] = f2tf32(vb[i].y);                               \
            Bs[st][k][bn_q+2] = f2tf32(vb[i].z);                               \
            Bs[st][k][bn_q+3] = f2tf32(vb[i].w);                               \
        }

    // prologue
    LOAD_A_CHUNK(0)
    LOAD_B_CHUNK(0)
    STORE_CHUNK(0)
    __syncthreads();

    for (int c = 0; c < nchunks; c++) {
        const int st = c & 1;
        if (c + 1 < nchunks) {
            LOAD_A_CHUNK((c+1)*16)
            LOAD_B_CHUNK((c+1)*16)
        }
        // compute from stage st
        #pragma unroll
        for (int kk = 0; kk < 16; kk += 8) {
            unsigned bh[4][2];
            #pragma unroll
            for (int nt = 0; nt < 4; nt++) {
                int n = n_w + nt*8 + g;
                bh[nt][0] = Bs[st][kk + tg][n];
                bh[nt][1] = Bs[st][kk + tg + 4][n];
            }
            #pragma unroll
            for (int mt = 0; mt < 4; mt++) {
                int m = m_w + mt*16 + g;
                unsigned a0 = As[st][kk + tg][m];
                unsigned a1 = As[st][kk + tg][m + 8];
                unsigned a2 = As[st][kk + tg + 4][m];
                unsigned a3 = As[st][kk + tg + 4][m + 8];
                #pragma unroll
                for (int nt = 0; nt < 4; nt++)
                    mma_tf32(acc[mt][nt], a0, a1, a2, a3, bh[nt][0], bh[nt][1]);
            }
        }
        if (c + 1 < nchunks) {
            STORE_CHUNK(st ^ 1)
        }
        __syncthreads();
    }
    #undef LOAD_A_CHUNK
    #undef LOAD_B_CHUNK
    #undef STORE_CHUNK

    #pragma unroll
    for (int mt = 0; mt < 4; mt++) {
        #pragma unroll
        for (int nt = 0; nt < 4; nt++) {
            int r0 = m0 + m_w + mt*16 + g;
            int r1 = r0 + 8;
            int c  = n0 + n_w + nt*8 + 2*tg;
            if (r0 < M) {
                if (c   < N) Cb[(long long)r0*ldc + c]   = acc[mt][nt][0];
                if (c+1 < N) Cb[(long long)r0*ldc + c+1] = acc[mt][nt][1];
            }
            if (r1 < M) {
                if (c   < N) Cb[(long long)r1*ldc + c]   = acc[mt][nt][2];
                if (c+1 < N) Cb[(long long)r1*ldc + c+1] = acc[mt][nt][3];
            }
        }
    }
}

// ---------------- masked softmax -> Am (d_out) + AmP (padded) ----------------
__global__ void softmax_kernel(float* __restrict__ Am)
{
    int row = blockIdx.x;                    // b*L + l
    const float* Ar = g_A  + (size_t)row * LL;
    const float* Tr = g_Ti + (size_t)row * LL;
    int t = threadIdx.x;
    const float scale = 0.07142857142857142f;
    float v[4], mb[4];
    float mx = -INFINITY;
    #pragma unroll
    for (int i = 0; i < 4; i++) {
        int m = t + i*NTHREADS;
        v[i] = 0.f; mb[i] = 0.f;
        if (m < LL) {
            float mask = sigmoid_ref(Tr[m]);
            v[i] = Ar[m] * mask * scale;
            mb[i] = (mask != 0.f) ? 1.f : 0.f;
            mx = fmaxf(mx, v[i]);
        }
    }
    __shared__ float red[NTHREADS];
    red[t] = mx; __syncthreads();
    for (int s = NTHREADS/2; s > 0; s >>= 1) {
        if (t < s) red[t] = fmaxf(red[t], red[t+s]);
        __syncthreads();
    }
    mx = red[0]; __syncthreads();
    float e[4]; float sum = 0.f;
    #pragma unroll
    for (int i = 0; i < 4; i++) {
        int m = t + i*NTHREADS;
        if (m < LL) { e[i] = expf(v[i] - mx); sum += e[i]; } else e[i] = 0.f;
    }
    red[t] = sum; __syncthreads();
    for (int s = NTHREADS/2; s > 0; s >>= 1) {
        if (t < s) red[t] += red[t+s];
        __syncthreads();
    }
    float inv = 1.f / red[0];
    #pragma unroll
    for (int i = 0; i < 4; i++) {
        int m = t + i*NTHREADS;
        if (m < LL) {
            float val = e[i] * inv * mb[i];
            Am[(size_t)row*LL + m] = val;
            g_AmP[(size_t)row*LLP + m] = val;
        }
    }
}

// ---------------- fold (gather form, no atomics) ------------------------------
__global__ void fold_kernel()
{
    size_t t = (size_t)blockIdx.x * NTHREADS + threadIdx.x;
    if (t >= (size_t)B_*CIN*Hh*Ww) return;
    int w = (int)(t % Ww); size_t r = t / Ww;
    int h = (int)(r % Hh); r /= Hh;
    int c = (int)(r % CIN);
    int b = (int)(r / CIN);
    int i0 = (h > 6) ? (h - 3) >> 2 : 0;
    int i1 = h >> 2; if (i1 > NHH - 1) i1 = NHH - 1;
    int j0 = (w > 6) ? (w - 3) >> 2 : 0;
    int j1 = w >> 2; if (j1 > NHH - 1) j1 = NHH - 1;
    float s = 0.f;
    for (int i = i0; i <= i1; i++) {
        int kh = h - i*4;
        for (int j = j0; j <= j1; j++) {
            int kw = w - j*4;
            s += g_y[((size_t)b*LL + i*NHH + j)*FV + c*49 + kh*7 + kw];
        }
    }
    g_fold[t] = s;
}

// ---------------- conv c1: refpad 3x3, 32->16, leaky(0.2) --------------------
__global__ void conv3x3_c1_kernel(const float* __restrict__ w1)
{
    __shared__ float sw[CI*CIN*9];
    int t = threadIdx.x;
    for (int i = t; i < CI*CIN*9; i += NTHREADS) sw[i] = w1[i];
    __syncthreads();
    int pix = blockIdx.x * NTHREADS + t;
    int b = blockIdx.y;
    int h = pix >> 7, w = pix & 127;
    float acc[CI];
    #pragma unroll
    for (int co = 0; co < CI; co++) acc[co] = 0.f;
    const float* xb = g_fold + (size_t)b * CIN * Hh * Ww;
    for (int ci = 0; ci < CIN; ci++) {
        float v[9];
        #pragma unroll
        for (int dh = 0; dh < 3; dh++) {
            int hh = h + dh - 1;
            hh = hh < 0 ? 1 : (hh >= Hh ? Hh - 2 : hh);
            #pragma unroll
            for (int dw = 0; dw < 3; dw++) {
                int w2p = w + dw - 1;
                w2p = w2p < 0 ? 1 : (w2p >= Ww ? Ww - 2 : w2p);
                v[dh*3 + dw] = xb[(ci*Hh + hh)*Ww + w2p];
            }
        }
        #pragma unroll
        for (int co = 0; co < CI; co++) {
            const float* p1 = &sw[(co*CIN + ci)*9];
            float s1 = 0.f;
            #pragma unroll
            for (int k = 0; k < 9; k++) s1 += p1[k]*v[k];
            acc[co] += s1;
        }
    }
    size_t base = (size_t)b * CI * Hh * Ww + pix;
    #pragma unroll
    for (int co = 0; co < CI; co++) {
        float s = acc[co];
        g_o1[base + (size_t)co*Hh*Ww] = (s > 0.f) ? s : 0.2f*s;
    }
}

// ---------------- conv c2: 1x1 16->32, leaky(0.2), + residual ----------------
__global__ void conv1x1_c2_res_kernel(const float* __restrict__ cw,
                                      const float* __restrict__ x,
                                      float* __restrict__ outp)
{
    __shared__ float sw[CIN*CI];
    int t = threadIdx.x;
    for (int i = t; i < CIN*CI; i += NTHREADS) sw[i] = cw[i];
    __syncthreads();
    int pix = blockIdx.x * NTHREADS + t;
    int b = blockIdx.y;
    float in[CI];
    #pragma unroll
    for (int ci = 0; ci < CI; ci++) in[ci] = g_o1[((size_t)b*CI + ci)*Hh*Ww + pix];
    #pragma unroll
    for (int co = 0; co < CIN; co++) {
        float s = 0.f;
        #pragma unroll
        for (int ci = 0; ci < CI; ci++) s += sw[co*CI + ci]*in[ci];
        s = (s > 0.f) ? s : 0.2f*s;
        size_t idx = ((size_t)b*CIN + co)*Hh*Ww + pix;
        outp[idx] = x[idx] + s;
    }
}

// ---------------- launch ------------------------------------------------------
extern "C" void kernel_launch(void* const* d_in, const int* in_sizes, int n_in,
                              void* d_out, int out_size)
{
    const float* x        = (const float*)d_in[0];
    const float* g_w      = (const float*)d_in[1];
    const float* g_b      = (const float*)d_in[2];
    const float* w_w      = (const float*)d_in[3];
    const float* w_b      = (const float*)d_in[4];
    const float* theta_w  = (const float*)d_in[5];
    const float* theta_b  = (const float*)d_in[6];
    const float* fc1_w    = (const float*)d_in[7];
    const float* fc1_b    = (const float*)d_in[8];
    const float* mconv_w  = (const float*)d_in[9];
    const float* mconv_b  = (const float*)d_in[10];
    const float* mfc_w    = (const float*)d_in[11];
    const float* mfc_b    = (const float*)d_in[12];
    const float* c1_w     = (const float*)d_in[13];
    const float* c2_w     = (const float*)d_in[14];
    float* out = (float*)d_out;

    float *px1, *px2, *px3, *pp6, *pp4, *pp62, *pwf, *pxf, *pA, *pTi, *pW2,
          *pMsumP, *pbsum, *pAmP, *py;
    cudaGetSymbolAddress((void**)&px1,   g_x1);
    cudaGetSymbolAddress((void**)&px2,   g_x2);
    cudaGetSymbolAddress((void**)&px3,   g_x3);
    cudaGetSymbolAddress((void**)&pp6,   g_p6);
    cudaGetSymbolAddress((void**)&pp4,   g_p4);
    cudaGetSymbolAddress((void**)&pp62,  g_p62);
    cudaGetSymbolAddress((void**)&pwf,   g_wf);
    cudaGetSymbolAddress((void**)&pxf,   g_xf);
    cudaGetSymbolAddress((void**)&pA,    g_A);
    cudaGetSymbolAddress((void**)&pTi,   g_Ti);
    cudaGetSymbolAddress((void**)&pW2,   g_W2);
    cudaGetSymbolAddress((void**)&pMsumP,g_MsumP);
    cudaGetSymbolAddress((void**)&pbsum, g_bsum);
    cudaGetSymbolAddress((void**)&pAmP,  g_AmP);
    cudaGetSymbolAddress((void**)&py,    g_y);

    dim3 convGrid(Hh*Ww/NTHREADS, B_);

    conv3x3_dual_kernel<<<convGrid, NTHREADS>>>(x, g_w, g_b, w_w, w_b);
    conv1x1_theta_kernel<<<convGrid, NTHREADS>>>(theta_w, theta_b);

    {
        size_t tot = (size_t)B_*LL*FIN;
        int nb = (int)((tot + NTHREADS - 1) / NTHREADS);
        unfold_kernel<<<nb, NTHREADS>>>(px1, pp6,  CI, tot);
        unfold_kernel<<<nb, NTHREADS>>>(px2, pp4,  CI, tot);
    }
    {
        size_t tot = (size_t)B_*LL*FV;
        int nb = (int)((tot + NTHREADS - 1) / NTHREADS);
        unfold_kernel<<<nb, NTHREADS>>>(px3, pp62, CIN, tot);
    }

    msum_kernel<<<(int)(((size_t)LL*LL + NTHREADS - 1)/NTHREADS), NTHREADS>>>(
        mconv_w, mfc_w, mconv_b, mfc_b);

    // wf = p4 @ fc1_w^T + fc1_b ; xf = p6 @ fc1_w^T + fc1_b  (flat M = B*L)
    {
        dim3 g((FOUT + 127)/128, (B_*LL + 127)/128, 1);
        gemm128_kernel<true><<<g, 256>>>(pp4, fc1_w, pwf, B_*LL, FOUT, FIN,
                                         FIN, FIN, FOUT, 0, 0, 0, nullptr, fc1_b);
        gemm128_kernel<true><<<g, 256>>>(pp6, fc1_w, pxf, B_*LL, FOUT, FIN,
                                         FIN, FIN, FOUT, 0, 0, 0, nullptr, fc1_b);
    }
    // A[b] = wf[b] @ xf[b]^T
    {
        dim3 g((LL + 127)/128, (LL + 127)/128, B_);
        gemm128_kernel<true><<<g, 256>>>(pwf, pxf, pA, LL, LL, FOUT,
                                         FOUT, FOUT, LL,
                                         (long long)LL*FOUT, (long long)LL*FOUT,
                                         (long long)LL*LL, nullptr, nullptr);
    }
    // W2[b] = Msum @ wf[b]   (assoc. rewrite of Ti = Msum @ A)
    {
        dim3 g((FOUT + 127)/128, (LL + 127)/128, B_);
        gemm128_kernel<false><<<g, 256>>>(pMsumP, pwf, pW2, LL, FOUT, LL,
                                          LLP, FOUT, FOUT,
                                          0, (long long)LL*FOUT, (long long)LL*FOUT,
                                          nullptr, nullptr);
    }
    // Ti[b] = W2[b] @ xf[b]^T + bsum (row bias)
    {
        dim3 g((LL + 127)/128, (LL + 127)/128, B_);
        gemm128_kernel<true><<<g, 256>>>(pW2, pxf, pTi, LL, LL, FOUT,
                                         FOUT, FOUT, LL,
                                         (long long)LL*FOUT, (long long)LL*FOUT,
                                         (long long)LL*LL, pbsum, nullptr);
    }

    softmax_kernel<<<B_*LL, NTHREADS>>>(out);

    // y[b] = Am[b] @ p62[b]  (TF32 tensor cores, double-buffered)
    {
        dim3 g((FV + 127)/128, (LL + 127)/128, B_);
        gemm_tf32_db_kernel<<<g, 256>>>(pAmP, pp62, py, LL, FV, LL,
                                        LLP, FV, FV,
                                        (long long)LL*LLP, (long long)LL*FV,
                                        (long long)LL*FV);
    }

    fold_kernel<<<(int)(((size_t)B_*CIN*Hh*Ww + NTHREADS - 1)/NTHREADS), NTHREADS>>>();
    conv3x3_c1_kernel<<<convGrid, NTHREADS>>>(c1_w);
    conv1x1_c2_res_kernel<<<convGrid, NTHREADS>>>(c2_w, x, out + (size_t)B_*LL*LL);
}

// round 7
// speedup vs baseline: 1.6920x; 1.1049x over previous
#include <cuda_runtime.h>
#include <math.h>
#include <float.h>

#define B_   8
#define CIN  32
#define CI   16
#define Hh   128
#define Ww   128
#define NHH  31
#define LL   961
#define LLP  964      // padded row stride (%4==0)
#define FIN  784
#define FOUT 196
#define FV   1568
#define NTHREADS 256

// ---------------- scratch (device globals; no cudaMalloc allowed) -------------
__device__ float g_x1[(size_t)B_*CI*Hh*Ww];
__device__ float g_x2[(size_t)B_*CI*Hh*Ww];
__device__ float g_x3[(size_t)B_*CIN*Hh*Ww];
__device__ float g_p6[(size_t)B_*LL*FIN];
__device__ float g_p4[(size_t)B_*LL*FIN];
__device__ float g_p62[(size_t)B_*LL*FV];
__device__ float g_wfW2[(size_t)2*B_*LL*FOUT];   // [0..8): wf, [8..16): W2
__device__ float g_xf[(size_t)B_*LL*FOUT];
__device__ float g_ATi[(size_t)2*B_*LL*LL];      // [0..8): A,  [8..16): Ti (no bias)
__device__ float g_MsumP[(size_t)LL*LLP];
__device__ float g_bsum[LL];
__device__ float g_AmP[(size_t)B_*LL*LLP];
__device__ float g_y[(size_t)B_*LL*FV];
__device__ float g_fold[(size_t)B_*CIN*Hh*Ww];
__device__ float g_o1[(size_t)B_*CI*Hh*Ww];

// Stable logistic, zero iff expf(x) < FLT_MIN (x < ~-87.3365) — matches ref.
static __device__ __forceinline__ float sigmoid_ref(float x) {
    if (x >= 0.f) return 1.f / (1.f + expf(-x));
    float e = expf(x);
    if (e < FLT_MIN) e = 0.f;
    return e / (1.f + e);
}

// ---------------- conv: refpad 3x3, 32->16 twice (x1, x2) --------------------
__global__ void conv3x3_dual_kernel(const float* __restrict__ x,
                                    const float* __restrict__ w1, const float* __restrict__ b1,
                                    const float* __restrict__ w2, const float* __restrict__ b2)
{
    __shared__ float sw1[CI*CIN*9];
    __shared__ float sw2[CI*CIN*9];
    int t = threadIdx.x;
    for (int i = t; i < CI*CIN*9; i += NTHREADS) { sw1[i] = w1[i]; sw2[i] = w2[i]; }
    __syncthreads();
    int pix = blockIdx.x * NTHREADS + t;
    int b = blockIdx.y;
    int h = pix >> 7, w = pix & 127;
    float acc1[CI], acc2[CI];
    #pragma unroll
    for (int co = 0; co < CI; co++) { acc1[co] = b1[co]; acc2[co] = b2[co]; }
    const float* xb = x + (size_t)b * CIN * Hh * Ww;
    for (int ci = 0; ci < CIN; ci++) {
        float v[9];
        #pragma unroll
        for (int dh = 0; dh < 3; dh++) {
            int hh = h + dh - 1;
            hh = hh < 0 ? 1 : (hh >= Hh ? Hh - 2 : hh);
            #pragma unroll
            for (int dw = 0; dw < 3; dw++) {
                int w2p = w + dw - 1;
                w2p = w2p < 0 ? 1 : (w2p >= Ww ? Ww - 2 : w2p);
                v[dh*3 + dw] = xb[(ci*Hh + hh)*Ww + w2p];
            }
        }
        #pragma unroll
        for (int co = 0; co < CI; co++) {
            const float* p1 = &sw1[(co*CIN + ci)*9];
            const float* p2 = &sw2[(co*CIN + ci)*9];
            float s1 = 0.f, s2 = 0.f;
            #pragma unroll
            for (int k = 0; k < 9; k++) { s1 += p1[k]*v[k]; s2 += p2[k]*v[k]; }
            acc1[co] += s1; acc2[co] += s2;
        }
    }
    size_t base = (size_t)b * CI * Hh * Ww + pix;
    #pragma unroll
    for (int co = 0; co < CI; co++) {
        g_x1[base + (size_t)co*Hh*Ww] = acc1[co];
        g_x2[base + (size_t)co*Hh*Ww] = acc2[co];
    }
}

// ---------------- conv: 1x1 theta, x1(16) -> x3(32), +bias -------------------
__global__ void conv1x1_theta_kernel(const float* __restrict__ tw, const float* __restrict__ tb)
{
    __shared__ float sw[CIN*CI];
    int t = threadIdx.x;
    for (int i = t; i < CIN*CI; i += NTHREADS) sw[i] = tw[i];
    __syncthreads();
    int pix = blockIdx.x * NTHREADS + t;
    int b = blockIdx.y;
    float in[CI];
    #pragma unroll
    for (int ci = 0; ci < CI; ci++) in[ci] = g_x1[((size_t)b*CI + ci)*Hh*Ww + pix];
    #pragma unroll
    for (int co = 0; co < CIN; co++) {
        float s = tb[co];
        #pragma unroll
        for (int ci = 0; ci < CI; ci++) s += sw[co*CI + ci]*in[ci];
        g_x3[((size_t)b*CIN + co)*Hh*Ww + pix] = s;
    }
}

// ---------------- unfold: src(B,C,H,W) -> dst(B,L,C*49) ----------------------
__global__ void unfold_kernel(const float* __restrict__ src, float* __restrict__ dst,
                              int C, size_t total)
{
    size_t t = (size_t)blockIdx.x * NTHREADS + threadIdx.x;
    if (t >= total) return;
    int F = C * 49;
    int f = (int)(t % F);
    size_t r = t / F;
    int l = (int)(r % LL);
    int b = (int)(r / LL);
    int c = f / 49, rr = f % 49, kh = rr / 7, kw = rr % 7;
    int h = (l / NHH)*4 + kh, w = (l % NHH)*4 + kw;
    dst[t] = src[(((size_t)b*C + c)*Hh + h)*Ww + w];
}

// ---------------- MsumP (stride 964) = mconv_w + mfc_w; bsum -----------------
__global__ void msum_kernel(const float* __restrict__ mw1, const float* __restrict__ mw2,
                            const float* __restrict__ mb1, const float* __restrict__ mb2)
{
    size_t t = (size_t)blockIdx.x * NTHREADS + threadIdx.x;
    if (t < (size_t)LL*LL) {
        int n = (int)(t / LL), c = (int)(t % LL);
        g_MsumP[(size_t)n*LLP + c] = mw1[t] + mw2[t];
    }
    if (t < LL) g_bsum[t] = mb1[t] + mb2[t];
}

// ======== fp32 SGEMM: 128x128x16, 8x8/thread, float4, DOUBLE-BUFFERED ========
// BT=true : B stored (N,K) row-major  -> C[m,n] = sum_k A[m,k]*B[n,k]
// BT=false: B stored (K,N) row-major  -> C[m,n] = sum_k A[m,k]*B[k,n]
// MODB=true: B batch index = blockIdx.z & 7 (shared B across two A sets).
template <bool BT, bool MODB>
__global__ void __launch_bounds__(256, 2) gemm128_kernel(
    const float* __restrict__ Ag, const float* __restrict__ Bg,
    float* __restrict__ Cg, int M, int N, int K,
    int lda, int ldb, int ldc,
    long long sA, long long sB, long long sC,
    const float* __restrict__ colBias)
{
    __shared__ float As[2][16][132];
    __shared__ float Bs[2][16][132];
    const int tid = threadIdx.x;
    const int tx = tid & 15, ty = tid >> 4;
    const int m0 = blockIdx.y * 128, n0 = blockIdx.x * 128;
    const float* Ab = Ag + (long long)blockIdx.z * sA;
    const float* Bb = Bg + (long long)(MODB ? (blockIdx.z & 7) : blockIdx.z) * sB;
    float*       Cb = Cg + (long long)blockIdx.z * sC;

    float acc[8][8];
    #pragma unroll
    for (int i = 0; i < 8; i++)
        #pragma unroll
        for (int j = 0; j < 8; j++) acc[i][j] = 0.f;

    const int a_c = (tid & 3) * 4;   // k offset within chunk
    const int a_r = tid >> 2;        // 0..63
    const int bn_q = (tid & 31) * 4; // n offset (BT=false)
    const int bk_r = tid >> 5;       // 0..7

    const int nchunks = (K + 15) / 16;
    float4 va[2], vb[2];

    #define LOAD_A16(k0)                                                       \
        _Pragma("unroll")                                                      \
        for (int i = 0; i < 2; i++) {                                          \
            int gm = m0 + a_r + 64*i;                                          \
            float4 v = make_float4(0.f,0.f,0.f,0.f);                           \
            if (gm < M) {                                                      \
                const float* p = Ab + (long long)gm*lda + (k0) + a_c;          \
                if ((k0) + a_c + 3 < K) v = *(const float4*)p;                 \
                else {                                                         \
                    if ((k0) + a_c + 0 < K) v.x = p[0];                        \
                    if ((k0) + a_c + 1 < K) v.y = p[1];                        \
                    if ((k0) + a_c + 2 < K) v.z = p[2];                        \
                }                                                              \
            }                                                                  \
            va[i] = v;                                                         \
        }
    #define LOAD_B16(k0)                                                       \
        if (BT) {                                                              \
            _Pragma("unroll")                                                  \
            for (int i = 0; i < 2; i++) {                                      \
                int gn = n0 + a_r + 64*i;                                      \
                float4 v = make_float4(0.f,0.f,0.f,0.f);                       \
                if (gn < N) {                                                  \
                    const float* p = Bb + (long long)gn*ldb + (k0) + a_c;      \
                    if ((k0) + a_c + 3 < K) v = *(const float4*)p;             \
                    else {                                                     \
                        if ((k0) + a_c + 0 < K) v.x = p[0];                    \
                        if ((k0) + a_c + 1 < K) v.y = p[1];                    \
                        if ((k0) + a_c + 2 < K) v.z = p[2];                    \
                    }                                                          \
                }                                                              \
                vb[i] = v;                                                     \
            }                                                                  \
        } else {                                                               \
            _Pragma("unroll")                                                  \
            for (int i = 0; i < 2; i++) {                                      \
                int gk = (k0) + bk_r + 8*i;                                    \
                int gn = n0 + bn_q;                                            \
                float4 v = make_float4(0.f,0.f,0.f,0.f);                       \
                if (gk < K) {                                                  \
                    const float* p = Bb + (long long)gk*ldb + gn;              \
                    if (gn + 3 < N) v = *(const float4*)p;                     \
                    else {                                                     \
                        if (gn+0 < N) v.x = p[0];                              \
                        if (gn+1 < N) v.y = p[1];                              \
                        if (gn+2 < N) v.z = p[2];                              \
                    }                                                          \
                }                                                              \
                vb[i] = v;                                                     \
            }                                                                  \
        }
    #define STORE16(st)                                                        \
        _Pragma("unroll")                                                      \
        for (int i = 0; i < 2; i++) {                                          \
            int m = a_r + 64*i;                                                \
            As[st][a_c+0][m] = va[i].x; As[st][a_c+1][m] = va[i].y;            \
            As[st][a_c+2][m] = va[i].z; As[st][a_c+3][m] = va[i].w;            \
        }                                                                      \
        if (BT) {                                                              \
            _Pragma("unroll")                                                  \
            for (int i = 0; i < 2; i++) {                                      \
                int n = a_r + 64*i;                                            \
                Bs[st][a_c+0][n] = vb[i].x; Bs[st][a_c+1][n] = vb[i].y;        \
                Bs[st][a_c+2][n] = vb[i].z; Bs[st][a_c+3][n] = vb[i].w;        \
            }                                                                  \
        } else {                                                               \
            _Pragma("unroll")                                                  \
            for (int i = 0; i < 2; i++) {                                      \
                int k = bk_r + 8*i;                                            \
                *(float4*)&Bs[st][k][bn_q] = vb[i];                            \
            }                                                                  \
        }

    LOAD_A16(0)
    LOAD_B16(0)
    STORE16(0)
    __syncthreads();

    for (int c = 0; c < nchunks; c++) {
        const int st = c & 1;
        if (c + 1 < nchunks) {
            LOAD_A16((c+1)*16)
            LOAD_B16((c+1)*16)
        }
        #pragma unroll
        for (int k = 0; k < 16; k++) {
            float a[8], b[8];
            *(float4*)&a[0] = *(const float4*)&As[st][k][ty*8];
            *(float4*)&a[4] = *(const float4*)&As[st][k][ty*8+4];
            *(float4*)&b[0] = *(const float4*)&Bs[st][k][tx*8];
            *(float4*)&b[4] = *(const float4*)&Bs[st][k][tx*8+4];
            #pragma unroll
            for (int i = 0; i < 8; i++)
                #pragma unroll
                for (int j = 0; j < 8; j++) acc[i][j] += a[i]*b[j];
        }
        if (c + 1 < nchunks) {
            STORE16(st ^ 1)
        }
        __syncthreads();
    }
    #undef LOAD_A16
    #undef LOAD_B16
    #undef STORE16

    #pragma unroll
    for (int i = 0; i < 8; i++) {
        int gm = m0 + ty*8 + i;
        if (gm >= M) continue;
        #pragma unroll
        for (int j = 0; j < 8; j++) {
            int gn = n0 + tx*8 + j;
            if (gn < N) {
                float v = acc[i][j];
                if (colBias) v += colBias[gn];
                Cb[(long long)gm*ldc + gn] = v;
            }
        }
    }
}

// ============ TF32 y-GEMM: double-buffered, conflict-free (stride 136) =======
__device__ __forceinline__ unsigned f2tf32(float x) {
    unsigned r;
    asm("cvt.rna.tf32.f32 %0, %1;" : "=r"(r) : "f"(x));
    return r;
}
__device__ __forceinline__ void mma_tf32(float c[4],
    unsigned a0, unsigned a1, unsigned a2, unsigned a3, unsigned b0, unsigned b1)
{
    asm volatile("mma.sync.aligned.m16n8k8.row.col.f32.tf32.tf32.f32 "
        "{%0,%1,%2,%3}, {%4,%5,%6,%7}, {%8,%9}, {%0,%1,%2,%3};"
        : "+f"(c[0]), "+f"(c[1]), "+f"(c[2]), "+f"(c[3])
        : "r"(a0), "r"(a1), "r"(a2), "r"(a3), "r"(b0), "r"(b1));
}

__global__ void __launch_bounds__(256, 2) gemm_tf32_db_kernel(
    const float* __restrict__ Ag, const float* __restrict__ Bg,
    float* __restrict__ Cg, int M, int N, int K,
    int lda, int ldb, int ldc, long long sA, long long sB, long long sC)
{
    __shared__ unsigned As[2][16][136];
    __shared__ unsigned Bs[2][16][136];

    const int tid = threadIdx.x;
    const int wid = tid >> 5, lane = tid & 31;
    const int wm = wid >> 2, wn = wid & 3;
    const int m_w = wm * 64, n_w = wn * 32;
    const int g = lane >> 2, tg = lane & 3;
    const int m0 = blockIdx.y * 128, n0 = blockIdx.x * 128;
    const float* Ab = Ag + (long long)blockIdx.z * sA;
    const float* Bb = Bg + (long long)blockIdx.z * sB;
    float*       Cb = Cg + (long long)blockIdx.z * sC;

    float acc[4][4][4];
    #pragma unroll
    for (int i = 0; i < 4; i++)
        #pragma unroll
        for (int j = 0; j < 4; j++)
            #pragma unroll
            for (int q = 0; q < 4; q++) acc[i][j][q] = 0.f;

    const int a_c = (tid & 3) * 4;
    const int a_r = tid >> 2;
    const int bn_q = (tid & 31) * 4;
    const int bk_r = tid >> 5;

    const int nchunks = (K + 15) / 16;
    float4 va[2], vb[2];

    #define LOAD_A_CHUNK(k0)                                                   \
        _Pragma("unroll")                                                      \
        for (int i = 0; i < 2; i++) {                                          \
            int gm = m0 + a_r + 64*i;                                          \
            float4 v = make_float4(0.f,0.f,0.f,0.f);                           \
            if (gm < M) {                                                      \
                const float* p = Ab + (long long)gm*lda + (k0) + a_c;          \
                if ((k0) + a_c + 3 < K) v = *(const float4*)p;                 \
                else {                                                         \
                    if ((k0) + a_c + 0 < K) v.x = p[0];                        \
                    if ((k0) + a_c + 1 < K) v.y = p[1];                        \
                    if ((k0) + a_c + 2 < K) v.z = p[2];                        \
                }                                                              \
            }                                                                  \
            va[i] = v;                                                         \
        }
    #define LOAD_B_CHUNK(k0)                                                   \
        _Pragma("unroll")                                                      \
        for (int i = 0; i < 2; i++) {                                          \
            int gk = (k0) + bk_r + 8*i;                                        \
            int gn = n0 + bn_q;                                                \
            float4 v = make_float4(0.f,0.f,0.f,0.f);                           \
            if (gk < K) {                                                      \
                const float* p = Bb + (long long)gk*ldb + gn;                  \
                if (gn + 3 < N) v = *(const float4*)p;                         \
                else {                                                         \
                    if (gn+0 < N) v.x = p[0];                                  \
                    if (gn+1 < N) v.y = p[1];                                  \
                    if (gn+2 < N) v.z = p[2];                                  \
                }                                                              \
            }                                                                  \
            vb[i] = v;                                                         \
        }
    #define STORE_CHUNK(st)                                                    \
        _Pragma("unroll")                                                      \
        for (int i = 0; i < 2; i++) {                                          \
            int m = a_r + 64*i;                                                \
            As[st][a_c+0][m] = f2tf32(va[i].x);                                \
            As[st][a_c+1][m] = f2tf32(va[i].y);                                \
            As[st][a_c+2][m] = f2tf32(va[i].z);                                \
            As[st][a_c+3][m] = f2tf32(va[i].w);                                \
            int k = bk_r + 8*i;                                                \
            Bs[st][k][bn_q+0] = f2tf32(vb[i].x);                               \
            Bs[st][k][bn_q+1] = f2tf32(vb[i].y);                               \
            Bs[st][k][bn_q+2] = f2tf32(vb[i].z);                               \
            Bs[st][k][bn_q+3] = f2tf32(vb[i].w);                               \
        }

    LOAD_A_CHUNK(0)
    LOAD_B_CHUNK(0)
    STORE_CHUNK(0)
    __syncthreads();

    for (int c = 0; c < nchunks; c++) {
        const int st = c & 1;
        if (c + 1 < nchunks) {
            LOAD_A_CHUNK((c+1)*16)
            LOAD_B_CHUNK((c+1)*16)
        }
        #pragma unroll
        for (int kk = 0; kk < 16; kk += 8) {
            unsigned bh[4][2];
            #pragma unroll
            for (int nt = 0; nt < 4; nt++) {
                int n = n_w + nt*8 + g;
                bh[nt][0] = Bs[st][kk + tg][n];
                bh[nt][1] = Bs[st][kk + tg + 4][n];
            }
            #pragma unroll
            for (int mt = 0; mt < 4; mt++) {
                int m = m_w + mt*16 + g;
                unsigned a0 = As[st][kk + tg][m];
                unsigned a1 = As[st][kk + tg][m + 8];
                unsigned a2 = As[st][kk + tg + 4][m];
                unsigned a3 = As[st][kk + tg + 4][m + 8];
                #pragma unroll
                for (int nt = 0; nt < 4; nt++)
                    mma_tf32(acc[mt][nt], a0, a1, a2, a3, bh[nt][0], bh[nt][1]);
            }
        }
        if (c + 1 < nchunks) {
            STORE_CHUNK(st ^ 1)
        }
        __syncthreads();
    }
    #undef LOAD_A_CHUNK
    #undef LOAD_B_CHUNK
    #undef STORE_CHUNK

    #pragma unroll
    for (int mt = 0; mt < 4; mt++) {
        #pragma unroll
        for (int nt = 0; nt < 4; nt++) {
            int r0 = m0 + m_w + mt*16 + g;
            int r1 = r0 + 8;
            int c  = n0 + n_w + nt*8 + 2*tg;
            if (r0 < M) {
                if (c   < N) Cb[(long long)r0*ldc + c]   = acc[mt][nt][0];
                if (c+1 < N) Cb[(long long)r0*ldc + c+1] = acc[mt][nt][1];
            }
            if (r1 < M) {
                if (c   < N) Cb[(long long)r1*ldc + c]   = acc[mt][nt][2];
                if (c+1 < N) Cb[(long long)r1*ldc + c+1] = acc[mt][nt][3];
            }
        }
    }
}

// ---------------- masked softmax -> Am (d_out) + AmP (padded) ----------------
// A  = g_ATi[b]        (batches 0..7)
// Ti = g_ATi[8 + b]    (no bias; bsum[l] added here — bitwise same as epilogue)
__global__ void softmax_kernel(float* __restrict__ Am)
{
    int row = blockIdx.x;                    // b*L + l
    const float* Ar = g_ATi + (size_t)row * LL;
    const float* Tr = g_ATi + (size_t)B_*LL*LL + (size_t)row * LL;
    const float bl = g_bsum[row % LL];
    int t = threadIdx.x;
    const float scale = 0.07142857142857142f;
    float v[4], mb[4];
    float mx = -INFINITY;
    #pragma unroll
    for (int i = 0; i < 4; i++) {
        int m = t + i*NTHREADS;
        v[i] = 0.f; mb[i] = 0.f;
        if (m < LL) {
            float mask = sigmoid_ref(Tr[m] + bl);
            v[i] = Ar[m] * mask * scale;
            mb[i] = (mask != 0.f) ? 1.f : 0.f;
            mx = fmaxf(mx, v[i]);
        }
    }
    __shared__ float red[NTHREADS];
    red[t] = mx; __syncthreads();
    for (int s = NTHREADS/2; s > 0; s >>= 1) {
        if (t < s) red[t] = fmaxf(red[t], red[t+s]);
        __syncthreads();
    }
    mx = red[0]; __syncthreads();
    float e[4]; float sum = 0.f;
    #pragma unroll
    for (int i = 0; i < 4; i++) {
        int m = t + i*NTHREADS;
        if (m < LL) { e[i] = expf(v[i] - mx); sum += e[i]; } else e[i] = 0.f;
    }
    red[t] = sum; __syncthreads();
    for (int s = NTHREADS/2; s > 0; s >>= 1) {
        if (t < s) red[t] += red[t+s];
        __syncthreads();
    }
    float inv = 1.f / red[0];
    #pragma unroll
    for (int i = 0; i < 4; i++) {
        int m = t + i*NTHREADS;
        if (m < LL) {
            float val = e[i] * inv * mb[i];
            Am[(size_t)row*LL + m] = val;
            g_AmP[(size_t)row*LLP + m] = val;
        }
    }
}

// ---------------- fold (gather form, no atomics) ------------------------------
__global__ void fold_kernel()
{
    size_t t = (size_t)blockIdx.x * NTHREADS + threadIdx.x;
    if (t >= (size_t)B_*CIN*Hh*Ww) return;
    int w = (int)(t % Ww); size_t r = t / Ww;
    int h = (int)(r % Hh); r /= Hh;
    int c = (int)(r % CIN);
    int b = (int)(r / CIN);
    int i0 = (h > 6) ? (h - 3) >> 2 : 0;
    int i1 = h >> 2; if (i1 > NHH - 1) i1 = NHH - 1;
    int j0 = (w > 6) ? (w - 3) >> 2 : 0;
    int j1 = w >> 2; if (j1 > NHH - 1) j1 = NHH - 1;
    float s = 0.f;
    for (int i = i0; i <= i1; i++) {
        int kh = h - i*4;
        for (int j = j0; j <= j1; j++) {
            int kw = w - j*4;
            s += g_y[((size_t)b*LL + i*NHH + j)*FV + c*49 + kh*7 + kw];
        }
    }
    g_fold[t] = s;
}

// ---------------- conv c1: refpad 3x3, 32->16, leaky(0.2) --------------------
__global__ void conv3x3_c1_kernel(const float* __restrict__ w1)
{
    __shared__ float sw[CI*CIN*9];
    int t = threadIdx.x;
    for (int i = t; i < CI*CIN*9; i += NTHREADS) sw[i] = w1[i];
    __syncthreads();
    int pix = blockIdx.x * NTHREADS + t;
    int b = blockIdx.y;
    int h = pix >> 7, w = pix & 127;
    float acc[CI];
    #pragma unroll
    for (int co = 0; co < CI; co++) acc[co] = 0.f;
    const float* xb = g_fold + (size_t)b * CIN * Hh * Ww;
    for (int ci = 0; ci < CIN; ci++) {
        float v[9];
        #pragma unroll
        for (int dh = 0; dh < 3; dh++) {
            int hh = h + dh - 1;
            hh = hh < 0 ? 1 : (hh >= Hh ? Hh - 2 : hh);
            #pragma unroll
            for (int dw = 0; dw < 3; dw++) {
                int w2p = w + dw - 1;
                w2p = w2p < 0 ? 1 : (w2p >= Ww ? Ww - 2 : w2p);
                v[dh*3 + dw] = xb[(ci*Hh + hh)*Ww + w2p];
            }
        }
        #pragma unroll
        for (int co = 0; co < CI; co++) {
            const float* p1 = &sw[(co*CIN + ci)*9];
            float s1 = 0.f;
            #pragma unroll
            for (int k = 0; k < 9; k++) s1 += p1[k]*v[k];
            acc[co] += s1;
        }
    }
    size_t base = (size_t)b * CI * Hh * Ww + pix;
    #pragma unroll
    for (int co = 0; co < CI; co++) {
        float s = acc[co];
        g_o1[base + (size_t)co*Hh*Ww] = (s > 0.f) ? s : 0.2f*s;
    }
}

// ---------------- conv c2: 1x1 16->32, leaky(0.2), + residual ----------------
__global__ void conv1x1_c2_res_kernel(const float* __restrict__ cw,
                                      const float* __restrict__ x,
                                      float* __restrict__ outp)
{
    __shared__ float sw[CIN*CI];
    int t = threadIdx.x;
    for (int i = t; i < CIN*CI; i += NTHREADS) sw[i] = cw[i];
    __syncthreads();
    int pix = blockIdx.x * NTHREADS + t;
    int b = blockIdx.y;
    float in[CI];
    #pragma unroll
    for (int ci = 0; ci < CI; ci++) in[ci] = g_o1[((size_t)b*CI + ci)*Hh*Ww + pix];
    #pragma unroll
    for (int co = 0; co < CIN; co++) {
        float s = 0.f;
        #pragma unroll
        for (int ci = 0; ci < CI; ci++) s += sw[co*CI + ci]*in[ci];
        s = (s > 0.f) ? s : 0.2f*s;
        size_t idx = ((size_t)b*CIN + co)*Hh*Ww + pix;
        outp[idx] = x[idx] + s;
    }
}

// ---------------- launch ------------------------------------------------------
extern "C" void kernel_launch(void* const* d_in, const int* in_sizes, int n_in,
                              void* d_out, int out_size)
{
    const float* x        = (const float*)d_in[0];
    const float* g_w      = (const float*)d_in[1];
    const float* g_b      = (const float*)d_in[2];
    const float* w_w      = (const float*)d_in[3];
    const float* w_b      = (const float*)d_in[4];
    const float* theta_w  = (const float*)d_in[5];
    const float* theta_b  = (const float*)d_in[6];
    const float* fc1_w    = (const float*)d_in[7];
    const float* fc1_b    = (const float*)d_in[8];
    const float* mconv_w  = (const float*)d_in[9];
    const float* mconv_b  = (const float*)d_in[10];
    const float* mfc_w    = (const float*)d_in[11];
    const float* mfc_b    = (const float*)d_in[12];
    const float* c1_w     = (const float*)d_in[13];
    const float* c2_w     = (const float*)d_in[14];
    float* out = (float*)d_out;

    float *px1, *px2, *px3, *pp6, *pp4, *pp62, *pwfW2, *pxf, *pATi,
          *pMsumP, *pAmP, *py;
    cudaGetSymbolAddress((void**)&px1,   g_x1);
    cudaGetSymbolAddress((void**)&px2,   g_x2);
    cudaGetSymbolAddress((void**)&px3,   g_x3);
    cudaGetSymbolAddress((void**)&pp6,   g_p6);
    cudaGetSymbolAddress((void**)&pp4,   g_p4);
    cudaGetSymbolAddress((void**)&pp62,  g_p62);
    cudaGetSymbolAddress((void**)&pwfW2, g_wfW2);
    cudaGetSymbolAddress((void**)&pxf,   g_xf);
    cudaGetSymbolAddress((void**)&pATi,  g_ATi);
    cudaGetSymbolAddress((void**)&pMsumP,g_MsumP);
    cudaGetSymbolAddress((void**)&pAmP,  g_AmP);
    cudaGetSymbolAddress((void**)&py,    g_y);

    float* pwf = pwfW2;                                   // batches 0..7
    float* pW2 = pwfW2 + (size_t)B_*LL*FOUT;              // batches 8..15

    dim3 convGrid(Hh*Ww/NTHREADS, B_);

    conv3x3_dual_kernel<<<convGrid, NTHREADS>>>(x, g_w, g_b, w_w, w_b);
    conv1x1_theta_kernel<<<convGrid, NTHREADS>>>(theta_w, theta_b);

    {
        size_t tot = (size_t)B_*LL*FIN;
        int nb = (int)((tot + NTHREADS - 1) / NTHREADS);
        unfold_kernel<<<nb, NTHREADS>>>(px1, pp6,  CI, tot);
        unfold_kernel<<<nb, NTHREADS>>>(px2, pp4,  CI, tot);
    }
    {
        size_t tot = (size_t)B_*LL*FV;
        int nb = (int)((tot + NTHREADS - 1) / NTHREADS);
        unfold_kernel<<<nb, NTHREADS>>>(px3, pp62, CIN, tot);
    }

    msum_kernel<<<(int)(((size_t)LL*LL + NTHREADS - 1)/NTHREADS), NTHREADS>>>(
        mconv_w, mfc_w, mconv_b, mfc_b);

    // wf = p4 @ fc1_w^T + fc1_b ; xf = p6 @ fc1_w^T + fc1_b  (flat M = B*L)
    {
        dim3 g((FOUT + 127)/128, (B_*LL + 127)/128, 1);
        gemm128_kernel<true,false><<<g, 256>>>(pp4, fc1_w, pwf, B_*LL, FOUT, FIN,
                                               FIN, FIN, FOUT, 0, 0, 0, fc1_b);
        gemm128_kernel<true,false><<<g, 256>>>(pp6, fc1_w, pxf, B_*LL, FOUT, FIN,
                                               FIN, FIN, FOUT, 0, 0, 0, fc1_b);
    }
    // W2[b] = Msum @ wf[b]   (assoc. rewrite of Ti = Msum @ A)
    {
        dim3 g((FOUT + 127)/128, (LL + 127)/128, B_);
        gemm128_kernel<false,false><<<g, 256>>>(pMsumP, pwf, pW2, LL, FOUT, LL,
                                                LLP, FOUT, FOUT,
                                                0, (long long)LL*FOUT, (long long)LL*FOUT,
                                                nullptr);
    }
    // Batched: z in [0,8): A[b] = wf[b] @ xf[b]^T ; z in [8,16): Ti[b] = W2[b] @ xf[b]^T
    {
        dim3 g((LL + 127)/128, (LL + 127)/128, 2*B_);
        gemm128_kernel<true,true><<<g, 256>>>(pwfW2, pxf, pATi, LL, LL, FOUT,
                                              FOUT, FOUT, LL,
                                              (long long)LL*FOUT, (long long)LL*FOUT,
                                              (long long)LL*LL, nullptr);
    }

    softmax_kernel<<<B_*LL, NTHREADS>>>(out);

    // y[b] = Am[b] @ p62[b]  (TF32 tensor cores, double-buffered)
    {
        dim3 g((FV + 127)/128, (LL + 127)/128, B_);
        gemm_tf32_db_kernel<<<g, 256>>>(pAmP, pp62, py, LL, FV, LL,
                                        LLP, FV, FV,
                                        (long long)LL*LLP, (long long)LL*FV,
                                        (long long)LL*FV);
    }

    fold_kernel<<<(int)(((size_t)B_*CIN*Hh*Ww + NTHREADS - 1)/NTHREADS), NTHREADS>>>();
    conv3x3_c1_kernel<<<convGrid, NTHREADS>>>(c1_w);
    conv1x1_c2_res_kernel<<<convGrid, NTHREADS>>>(c2_w, x, out + (size_t)B_*LL*LL);
}

// round 8
// speedup vs baseline: 2.1368x; 1.2629x over previous
#include <cuda_runtime.h>
#include <math.h>
#include <float.h>

#define B_   8
#define CIN  32
#define CI   16
#define Hh   128
#define Ww   128
#define NHH  31
#define LL   961
#define LLP  964      // padded row stride (%4==0)
#define FIN  784
#define FOUT 196
#define FV   1568
#define NTHREADS 256

// ---------------- scratch (device globals; no cudaMalloc allowed) -------------
__device__ float g_x1[(size_t)B_*CI*Hh*Ww];
__device__ float g_x2[(size_t)B_*CI*Hh*Ww];
__device__ float g_x3[(size_t)B_*CIN*Hh*Ww];
__device__ float g_p6[(size_t)B_*LL*FIN];
__device__ float g_p4[(size_t)B_*LL*FIN];
__device__ float g_p62[(size_t)B_*LL*FV];
__device__ float g_wfW2[(size_t)2*B_*LL*FOUT];   // [0..8): wf, [8..16): W2
__device__ float g_xf[(size_t)B_*LL*FOUT];
__device__ float g_ATi[(size_t)2*B_*LL*LL];      // [0..8): A,  [8..16): Ti (no bias)
__device__ float g_MsumP[(size_t)LL*LLP];
__device__ float g_bsum[LL];
__device__ float g_AmP[(size_t)B_*LL*LLP];
__device__ float g_y[(size_t)B_*LL*FV];
__device__ float g_fold[(size_t)B_*CIN*Hh*Ww];
__device__ float g_o1[(size_t)B_*CI*Hh*Ww];

// Stable logistic, zero iff expf(x) < FLT_MIN (x < ~-87.3365) — matches ref.
static __device__ __forceinline__ float sigmoid_ref(float x) {
    if (x >= 0.f) return 1.f / (1.f + expf(-x));
    float e = expf(x);
    if (e < FLT_MIN) e = 0.f;
    return e / (1.f + e);
}

// ---------------- conv: refpad 3x3, 32->16 twice (x1, x2) --------------------
__global__ void conv3x3_dual_kernel(const float* __restrict__ x,
                                    const float* __restrict__ w1, const float* __restrict__ b1,
                                    const float* __restrict__ w2, const float* __restrict__ b2)
{
    __shared__ float sw1[CI*CIN*9];
    __shared__ float sw2[CI*CIN*9];
    int t = threadIdx.x;
    for (int i = t; i < CI*CIN*9; i += NTHREADS) { sw1[i] = w1[i]; sw2[i] = w2[i]; }
    __syncthreads();
    int pix = blockIdx.x * NTHREADS + t;
    int b = blockIdx.y;
    int h = pix >> 7, w = pix & 127;
    float acc1[CI], acc2[CI];
    #pragma unroll
    for (int co = 0; co < CI; co++) { acc1[co] = b1[co]; acc2[co] = b2[co]; }
    const float* xb = x + (size_t)b * CIN * Hh * Ww;
    for (int ci = 0; ci < CIN; ci++) {
        float v[9];
        #pragma unroll
        for (int dh = 0; dh < 3; dh++) {
            int hh = h + dh - 1;
            hh = hh < 0 ? 1 : (hh >= Hh ? Hh - 2 : hh);
            #pragma unroll
            for (int dw = 0; dw < 3; dw++) {
                int w2p = w + dw - 1;
                w2p = w2p < 0 ? 1 : (w2p >= Ww ? Ww - 2 : w2p);
                v[dh*3 + dw] = xb[(ci*Hh + hh)*Ww + w2p];
            }
        }
        #pragma unroll
        for (int co = 0; co < CI; co++) {
            const float* p1 = &sw1[(co*CIN + ci)*9];
            const float* p2 = &sw2[(co*CIN + ci)*9];
            float s1 = 0.f, s2 = 0.f;
            #pragma unroll
            for (int k = 0; k < 9; k++) { s1 += p1[k]*v[k]; s2 += p2[k]*v[k]; }
            acc1[co] += s1; acc2[co] += s2;
        }
    }
    size_t base = (size_t)b * CI * Hh * Ww + pix;
    #pragma unroll
    for (int co = 0; co < CI; co++) {
        g_x1[base + (size_t)co*Hh*Ww] = acc1[co];
        g_x2[base + (size_t)co*Hh*Ww] = acc2[co];
    }
}

// ---------------- conv: 1x1 theta, x1(16) -> x3(32), +bias -------------------
__global__ void conv1x1_theta_kernel(const float* __restrict__ tw, const float* __restrict__ tb)
{
    __shared__ float sw[CIN*CI];
    int t = threadIdx.x;
    for (int i = t; i < CIN*CI; i += NTHREADS) sw[i] = tw[i];
    __syncthreads();
    int pix = blockIdx.x * NTHREADS + t;
    int b = blockIdx.y;
    float in[CI];
    #pragma unroll
    for (int ci = 0; ci < CI; ci++) in[ci] = g_x1[((size_t)b*CI + ci)*Hh*Ww + pix];
    #pragma unroll
    for (int co = 0; co < CIN; co++) {
        float s = tb[co];
        #pragma unroll
        for (int ci = 0; ci < CI; ci++) s += sw[co*CI + ci]*in[ci];
        g_x3[((size_t)b*CIN + co)*Hh*Ww + pix] = s;
    }
}

// ---------------- unfold: src(B,C,H,W) -> dst(B,L,C*49) ----------------------
__global__ void unfold_kernel(const float* __restrict__ src, float* __restrict__ dst,
                              int C, size_t total)
{
    size_t t = (size_t)blockIdx.x * NTHREADS + threadIdx.x;
    if (t >= total) return;
    int F = C * 49;
    int f = (int)(t % F);
    size_t r = t / F;
    int l = (int)(r % LL);
    int b = (int)(r / LL);
    int c = f / 49, rr = f % 49, kh = rr / 7, kw = rr % 7;
    int h = (l / NHH)*4 + kh, w = (l % NHH)*4 + kw;
    dst[t] = src[(((size_t)b*C + c)*Hh + h)*Ww + w];
}

// ---------------- MsumP (stride 964) = mconv_w + mfc_w; bsum -----------------
__global__ void msum_kernel(const float* __restrict__ mw1, const float* __restrict__ mw2,
                            const float* __restrict__ mb1, const float* __restrict__ mb2)
{
    size_t t = (size_t)blockIdx.x * NTHREADS + threadIdx.x;
    if (t < (size_t)LL*LL) {
        int n = (int)(t / LL), c = (int)(t % LL);
        g_MsumP[(size_t)n*LLP + c] = mw1[t] + mw2[t];
    }
    if (t < LL) g_bsum[t] = mb1[t] + mb2[t];
}

// =================== bf16 / tf32 mma primitives ==============================
__device__ __forceinline__ unsigned packbf(float x, float y) {
    // result: low half = bf16(x), high half = bf16(y)
    unsigned r;
    asm("cvt.rn.bf16x2.f32 %0, %1, %2;" : "=r"(r) : "f"(y), "f"(x));
    return r;
}
// split pair (x,y) into hi (bf16) and lo (bf16 of residual)
__device__ __forceinline__ void split2(float x, float y, unsigned& hi, unsigned& lo) {
    hi = packbf(x, y);
    float hx = __uint_as_float(hi << 16);
    float hy = __uint_as_float(hi & 0xFFFF0000u);
    lo = packbf(x - hx, y - hy);
}
__device__ __forceinline__ void mma_bf16(float c[4],
    unsigned a0, unsigned a1, unsigned a2, unsigned a3, unsigned b0, unsigned b1)
{
    asm volatile("mma.sync.aligned.m16n8k16.row.col.f32.bf16.bf16.f32 "
        "{%0,%1,%2,%3}, {%4,%5,%6,%7}, {%8,%9}, {%0,%1,%2,%3};"
        : "+f"(c[0]), "+f"(c[1]), "+f"(c[2]), "+f"(c[3])
        : "r"(a0), "r"(a1), "r"(a2), "r"(a3), "r"(b0), "r"(b1));
}
__device__ __forceinline__ unsigned f2tf32(float x) {
    unsigned r;
    asm("cvt.rna.tf32.f32 %0, %1;" : "=r"(r) : "f"(x));
    return r;
}
__device__ __forceinline__ void mma_tf32(float c[4],
    unsigned a0, unsigned a1, unsigned a2, unsigned a3, unsigned b0, unsigned b1)
{
    asm volatile("mma.sync.aligned.m16n8k8.row.col.f32.tf32.tf32.f32 "
        "{%0,%1,%2,%3}, {%4,%5,%6,%7}, {%8,%9}, {%0,%1,%2,%3};"
        : "+f"(c[0]), "+f"(c[1]), "+f"(c[2]), "+f"(c[3])
        : "r"(a0), "r"(a1), "r"(a2), "r"(a3), "r"(b0), "r"(b1));
}

// ========= bf16x3 split GEMM (fp32-accuracy on tensor cores) =================
// C[m,n] = sum_k A[m,k] * opB; 128x128 tile, 8 warps (2m x 4n, 64x32 each).
// Smem holds k-pair-packed bf16x2: Xpk[kk][i] = {bf16(X[2kk]), bf16(X[2kk+1])}.
// BT=true : B stored (N,K) row-major ; BT=false: B stored (K,N) row-major.
// MODB=true: B batch index = blockIdx.z & 7.
template <bool BT, bool MODB>
__global__ void __launch_bounds__(256, 2) gemm_bf16x3_kernel(
    const float* __restrict__ Ag, const float* __restrict__ Bg,
    float* __restrict__ Cg, int M, int N, int K,
    int lda, int ldb, int ldc,
    long long sA, long long sB, long long sC,
    const float* __restrict__ colBias)
{
    __shared__ unsigned Ah[2][8][136], Al[2][8][136];
    __shared__ unsigned Bh[2][8][136], Bl[2][8][136];

    const int tid = threadIdx.x;
    const int wid = tid >> 5, lane = tid & 31;
    const int wm = wid >> 2, wn = wid & 3;
    const int m_w = wm * 64, n_w = wn * 32;
    const int g = lane >> 2, tg = lane & 3;
    const int m0 = blockIdx.y * 128, n0 = blockIdx.x * 128;
    const float* Ab = Ag + (long long)blockIdx.z * sA;
    const float* Bb = Bg + (long long)(MODB ? (blockIdx.z & 7) : blockIdx.z) * sB;
    float*       Cb = Cg + (long long)blockIdx.z * sC;

    float acc[4][4][4];
    #pragma unroll
    for (int i = 0; i < 4; i++)
        #pragma unroll
        for (int j = 0; j < 4; j++)
            #pragma unroll
            for (int q = 0; q < 4; q++) acc[i][j][q] = 0.f;

    const int a_c = (tid & 3) * 4;   // k offset within 16-chunk (0,4,8,12)
    const int a_r = tid >> 2;        // 0..63
    const int bn_q = (tid & 31) * 4; // n offset (BT=false)
    const int bk_r = tid >> 5;       // 0..7 => kk row (BT=false)

    const int nchunks = (K + 15) / 16;
    float4 va[2], vb[2];

    #define LOAD_A16(k0)                                                       \
        _Pragma("unroll")                                                      \
        for (int i = 0; i < 2; i++) {                                          \
            int gm = m0 + a_r + 64*i;                                          \
            float4 v = make_float4(0.f,0.f,0.f,0.f);                           \
            if (gm < M) {                                                      \
                const float* p = Ab + (long long)gm*lda + (k0) + a_c;          \
                if ((k0) + a_c + 3 < K) v = *(const float4*)p;                 \
                else {                                                         \
                    if ((k0) + a_c + 0 < K) v.x = p[0];                        \
                    if ((k0) + a_c + 1 < K) v.y = p[1];                        \
                    if ((k0) + a_c + 2 < K) v.z = p[2];                        \
                }                                                              \
            }                                                                  \
            va[i] = v;                                                         \
        }
    #define LOAD_B16(k0)                                                       \
        if (BT) {                                                              \
            _Pragma("unroll")                                                  \
            for (int i = 0; i < 2; i++) {                                      \
                int gn = n0 + a_r + 64*i;                                      \
                float4 v = make_float4(0.f,0.f,0.f,0.f);                       \
                if (gn < N) {                                                  \
                    const float* p = Bb + (long long)gn*ldb + (k0) + a_c;      \
                    if ((k0) + a_c + 3 < K) v = *(const float4*)p;             \
                    else {                                                     \
                        if ((k0) + a_c + 0 < K) v.x = p[0];                    \
                        if ((k0) + a_c + 1 < K) v.y = p[1];                    \
                        if ((k0) + a_c + 2 < K) v.z = p[2];                    \
                    }                                                          \
                }                                                              \
                vb[i] = v;                                                     \
            }                                                                  \
        } else {                                                               \
            _Pragma("unroll")                                                  \
            for (int i = 0; i < 2; i++) {                                      \
                int gk = (k0) + 2*bk_r + i;                                    \
                int gn = n0 + bn_q;                                            \
                float4 v = make_float4(0.f,0.f,0.f,0.f);                       \
                if (gk < K) {                                                  \
                    const float* p = Bb + (long long)gk*ldb + gn;              \
                    if (gn + 3 < N) v = *(const float4*)p;                     \
                    else {                                                     \
                        if (gn+0 < N) v.x = p[0];                              \
                        if (gn+1 < N) v.y = p[1];                              \
                        if (gn+2 < N) v.z = p[2];                              \
                    }                                                          \
                }                                                              \
                vb[i] = v;                                                     \
            }                                                                  \
        }
    #define STORE16(st)                                                        \
        _Pragma("unroll")                                                      \
        for (int i = 0; i < 2; i++) {                                          \
            int m = a_r + 64*i;                                                \
            unsigned h0, l0, h1, l1;                                           \
            split2(va[i].x, va[i].y, h0, l0);                                  \
            split2(va[i].z, va[i].w, h1, l1);                                  \
            Ah[st][a_c/2  ][m] = h0;  Al[st][a_c/2  ][m] = l0;                 \
            Ah[st][a_c/2+1][m] = h1;  Al[st][a_c/2+1][m] = l1;                 \
        }                                                                      \
        if (BT) {                                                              \
            _Pragma("unroll")                                                  \
            for (int i = 0; i < 2; i++) {                                      \
                int n = a_r + 64*i;                                            \
                unsigned h0, l0, h1, l1;                                       \
                split2(vb[i].x, vb[i].y, h0, l0);                              \
                split2(vb[i].z, vb[i].w, h1, l1);                              \
                Bh[st][a_c/2  ][n] = h0;  Bl[st][a_c/2  ][n] = l0;             \
                Bh[st][a_c/2+1][n] = h1;  Bl[st][a_c/2+1][n] = l1;             \
            }                                                                  \
        } else {                                                               \
            unsigned h, l;                                                     \
            split2(vb[0].x, vb[1].x, h, l);                                    \
            Bh[st][bk_r][bn_q+0] = h;  Bl[st][bk_r][bn_q+0] = l;               \
            split2(vb[0].y, vb[1].y, h, l);                                    \
            Bh[st][bk_r][bn_q+1] = h;  Bl[st][bk_r][bn_q+1] = l;               \
            split2(vb[0].z, vb[1].z, h, l);                                    \
            Bh[st][bk_r][bn_q+2] = h;  Bl[st][bk_r][bn_q+2] = l;               \
            split2(vb[0].w, vb[1].w, h, l);                                    \
            Bh[st][bk_r][bn_q+3] = h;  Bl[st][bk_r][bn_q+3] = l;               \
        }

    LOAD_A16(0)
    LOAD_B16(0)
    STORE16(0)
    __syncthreads();

    for (int c = 0; c < nchunks; c++) {
        const int st = c & 1;
        if (c + 1 < nchunks) {
            LOAD_A16((c+1)*16)
            LOAD_B16((c+1)*16)
        }
        // one k16 step per chunk
        unsigned bh0[4], bh1[4], bl0[4], bl1[4];
        #pragma unroll
        for (int nt = 0; nt < 4; nt++) {
            int n = n_w + nt*8 + g;
            bh0[nt] = Bh[st][tg  ][n];
            bh1[nt] = Bh[st][tg+4][n];
            bl0[nt] = Bl[st][tg  ][n];
            bl1[nt] = Bl[st][tg+4][n];
        }
        #pragma unroll
        for (int mt = 0; mt < 4; mt++) {
            int m = m_w + mt*16 + g;
            unsigned ah0 = Ah[st][tg  ][m];
            unsigned ah1 = Ah[st][tg  ][m+8];
            unsigned ah2 = Ah[st][tg+4][m];
            unsigned ah3 = Ah[st][tg+4][m+8];
            unsigned al0 = Al[st][tg  ][m];
            unsigned al1 = Al[st][tg  ][m+8];
            unsigned al2 = Al[st][tg+4][m];
            unsigned al3 = Al[st][tg+4][m+8];
            #pragma unroll
            for (int nt = 0; nt < 4; nt++) {
                mma_bf16(acc[mt][nt], ah0, ah1, ah2, ah3, bh0[nt], bh1[nt]); // hh
                mma_bf16(acc[mt][nt], ah0, ah1, ah2, ah3, bl0[nt], bl1[nt]); // hl
                mma_bf16(acc[mt][nt], al0, al1, al2, al3, bh0[nt], bh1[nt]); // lh
            }
        }
        if (c + 1 < nchunks) {
            STORE16(st ^ 1)
        }
        __syncthreads();
    }
    #undef LOAD_A16
    #undef LOAD_B16
    #undef STORE16

    #pragma unroll
    for (int mt = 0; mt < 4; mt++) {
        #pragma unroll
        for (int nt = 0; nt < 4; nt++) {
            int r0 = m0 + m_w + mt*16 + g;
            int r1 = r0 + 8;
            int c  = n0 + n_w + nt*8 + 2*tg;
            float cb0 = (colBias && c   < N) ? colBias[c]   : 0.f;
            float cb1 = (colBias && c+1 < N) ? colBias[c+1] : 0.f;
            if (r0 < M) {
                if (c   < N) Cb[(long long)r0*ldc + c]   = acc[mt][nt][0] + cb0;
                if (c+1 < N) Cb[(long long)r0*ldc + c+1] = acc[mt][nt][1] + cb1;
            }
            if (r1 < M) {
                if (c   < N) Cb[(long long)r1*ldc + c]   = acc[mt][nt][2] + cb0;
                if (c+1 < N) Cb[(long long)r1*ldc + c+1] = acc[mt][nt][3] + cb1;
            }
        }
    }
}

// ============ TF32 y-GEMM: double-buffered, conflict-free (stride 136) =======
__global__ void __launch_bounds__(256, 2) gemm_tf32_db_kernel(
    const float* __restrict__ Ag, const float* __restrict__ Bg,
    float* __restrict__ Cg, int M, int N, int K,
    int lda, int ldb, int ldc, long long sA, long long sB, long long sC)
{
    __shared__ unsigned As[2][16][136];
    __shared__ unsigned Bs[2][16][136];

    const int tid = threadIdx.x;
    const int wid = tid >> 5, lane = tid & 31;
    const int wm = wid >> 2, wn = wid & 3;
    const int m_w = wm * 64, n_w = wn * 32;
    const int g = lane >> 2, tg = lane & 3;
    const int m0 = blockIdx.y * 128, n0 = blockIdx.x * 128;
    const float* Ab = Ag + (long long)blockIdx.z * sA;
    const float* Bb = Bg + (long long)blockIdx.z * sB;
    float*       Cb = Cg + (long long)blockIdx.z * sC;

    float acc[4][4][4];
    #pragma unroll
    for (int i = 0; i < 4; i++)
        #pragma unroll
        for (int j = 0; j < 4; j++)
            #pragma unroll
            for (int q = 0; q < 4; q++) acc[i][j][q] = 0.f;

    const int a_c = (tid & 3) * 4;
    const int a_r = tid >> 2;
    const int bn_q = (tid & 31) * 4;
    const int bk_r = tid >> 5;

    const int nchunks = (K + 15) / 16;
    float4 va[2], vb[2];

    #define LOAD_A_CHUNK(k0)                                                   \
        _Pragma("unroll")                                                      \
        for (int i = 0; i < 2; i++) {                                          \
            int gm = m0 + a_r + 64*i;                                          \
            float4 v = make_float4(0.f,0.f,0.f,0.f);                           \
            if (gm < M) {                                                      \
                const float* p = Ab + (long long)gm*lda + (k0) + a_c;          \
                if ((k0) + a_c + 3 < K) v = *(const float4*)p;                 \
                else {                                                         \
                    if ((k0) + a_c + 0 < K) v.x = p[0];                        \
                    if ((k0) + a_c + 1 < K) v.y = p[1];                        \
                    if ((k0) + a_c + 2 < K) v.z = p[2];                        \
                }                                                              \
            }                                                                  \
            va[i] = v;                                                         \
        }
    #define LOAD_B_CHUNK(k0)                                                   \
        _Pragma("unroll")                                                      \
        for (int i = 0; i < 2; i++) {                                          \
            int gk = (k0) + bk_r + 8*i;                                        \
            int gn = n0 + bn_q;                                                \
            float4 v = make_float4(0.f,0.f,0.f,0.f);                           \
            if (gk < K) {                                                      \
                const float* p = Bb + (long long)gk*ldb + gn;                  \
                if (gn + 3 < N) v = *(const float4*)p;                         \
                else {                                                         \
                    if (gn+0 < N) v.x = p[0];                                  \
                    if (gn+1 < N) v.y = p[1];                                  \
                    if (gn+2 < N) v.z = p[2];                                  \
                }                                                              \
            }                                                                  \
            vb[i] = v;                                                         \
        }
    #define STORE_CHUNK(st)                                                    \
        _Pragma("unroll")                                                      \
        for (int i = 0; i < 2; i++) {                                          \
            int m = a_r + 64*i;                                                \
            As[st][a_c+0][m] = f2tf32(va[i].x);                                \
            As[st][a_c+1][m] = f2tf32(va[i].y);                                \
            As[st][a_c+2][m] = f2tf32(va[i].z);                                \
            As[st][a_c+3][m] = f2tf32(va[i].w);                                \
            int k = bk_r + 8*i;                                                \
            Bs[st][k][bn_q+0] = f2tf32(vb[i].x);                               \
            Bs[st][k][bn_q+1] = f2tf32(vb[i].y);                               \
            Bs[st][k][bn_q+2] = f2tf32(vb[i].z);                               \
            Bs[st][k][bn_q+3] = f2tf32(vb[i].w);                               \
        }

    LOAD_A_CHUNK(0)
    LOAD_B_CHUNK(0)
    STORE_CHUNK(0)
    __syncthreads();

    for (int c = 0; c < nchunks; c++) {
        const int st = c & 1;
        if (c + 1 < nchunks) {
            LOAD_A_CHUNK((c+1)*16)
            LOAD_B_CHUNK((c+1)*16)
        }
        #pragma unroll
        for (int kk = 0; kk < 16; kk += 8) {
            unsigned bh[4][2];
            #pragma unroll
            for (int nt = 0; nt < 4; nt++) {
                int n = n_w + nt*8 + g;
                bh[nt][0] = Bs[st][kk + tg][n];
                bh[nt][1] = Bs[st][kk + tg + 4][n];
            }
            #pragma unroll
            for (int mt = 0; mt < 4; mt++) {
                int m = m_w + mt*16 + g;
                unsigned a0 = As[st][kk + tg][m];
                unsigned a1 = As[st][kk + tg][m + 8];
                unsigned a2 = As[st][kk + tg + 4][m];
                unsigned a3 = As[st][kk + tg + 4][m + 8];
                #pragma unroll
                for (int nt = 0; nt < 4; nt++)
                    mma_tf32(acc[mt][nt], a0, a1, a2, a3, bh[nt][0], bh[nt][1]);
            }
        }
        if (c + 1 < nchunks) {
            STORE_CHUNK(st ^ 1)
        }
        __syncthreads();
    }
    #undef LOAD_A_CHUNK
    #undef LOAD_B_CHUNK
    #undef STORE_CHUNK

    #pragma unroll
    for (int mt = 0; mt < 4; mt++) {
        #pragma unroll
        for (int nt = 0; nt < 4; nt++) {
            int r0 = m0 + m_w + mt*16 + g;
            int r1 = r0 + 8;
            int c  = n0 + n_w + nt*8 + 2*tg;
            if (r0 < M) {
                if (c   < N) Cb[(long long)r0*ldc + c]   = acc[mt][nt][0];
                if (c+1 < N) Cb[(long long)r0*ldc + c+1] = acc[mt][nt][1];
            }
            if (r1 < M) {
                if (c   < N) Cb[(long long)r1*ldc + c]   = acc[mt][nt][2];
                if (c+1 < N) Cb[(long long)r1*ldc + c+1] = acc[mt][nt][3];
            }
        }
    }
}

// ---------------- masked softmax -> Am (d_out) + AmP (padded) ----------------
__global__ void softmax_kernel(float* __restrict__ Am)
{
    int row = blockIdx.x;                    // b*L + l
    const float* Ar = g_ATi + (size_t)row * LL;
    const float* Tr = g_ATi + (size_t)B_*LL*LL + (size_t)row * LL;
    const float bl = g_bsum[row % LL];
    int t = threadIdx.x;
    const float scale = 0.07142857142857142f;
    float v[4], mb[4];
    float mx = -INFINITY;
    #pragma unroll
    for (int i = 0; i < 4; i++) {
        int m = t + i*NTHREADS;
        v[i] = 0.f; mb[i] = 0.f;
        if (m < LL) {
            float mask = sigmoid_ref(Tr[m] + bl);
            v[i] = Ar[m] * mask * scale;
            mb[i] = (mask != 0.f) ? 1.f : 0.f;
            mx = fmaxf(mx, v[i]);
        }
    }
    __shared__ float red[NTHREADS];
    red[t] = mx; __syncthreads();
    for (int s = NTHREADS/2; s > 0; s >>= 1) {
        if (t < s) red[t] = fmaxf(red[t], red[t+s]);
        __syncthreads();
    }
    mx = red[0]; __syncthreads();
    float e[4]; float sum = 0.f;
    #pragma unroll
    for (int i = 0; i < 4; i++) {
        int m = t + i*NTHREADS;
        if (m < LL) { e[i] = expf(v[i] - mx); sum += e[i]; } else e[i] = 0.f;
    }
    red[t] = sum; __syncthreads();
    for (int s = NTHREADS/2; s > 0; s >>= 1) {
        if (t < s) red[t] += red[t+s];
        __syncthreads();
    }
    float inv = 1.f / red[0];
    #pragma unroll
    for (int i = 0; i < 4; i++) {
        int m = t + i*NTHREADS;
        if (m < LL) {
            float val = e[i] * inv * mb[i];
            Am[(size_t)row*LL + m] = val;
            g_AmP[(size_t)row*LLP + m] = val;
        }
    }
}

// ---------------- fold (gather form, no atomics) ------------------------------
__global__ void fold_kernel()
{
    size_t t = (size_t)blockIdx.x * NTHREADS + threadIdx.x;
    if (t >= (size_t)B_*CIN*Hh*Ww) return;
    int w = (int)(t % Ww); size_t r = t / Ww;
    int h = (int)(r % Hh); r /= Hh;
    int c = (int)(r % CIN);
    int b = (int)(r / CIN);
    int i0 = (h > 6) ? (h - 3) >> 2 : 0;
    int i1 = h >> 2; if (i1 > NHH - 1) i1 = NHH - 1;
    int j0 = (w > 6) ? (w - 3) >> 2 : 0;
    int j1 = w >> 2; if (j1 > NHH - 1) j1 = NHH - 1;
    float s = 0.f;
    for (int i = i0; i <= i1; i++) {
        int kh = h - i*4;
        for (int j = j0; j <= j1; j++) {
            int kw = w - j*4;
            s += g_y[((size_t)b*LL + i*NHH + j)*FV + c*49 + kh*7 + kw];
        }
    }
    g_fold[t] = s;
}

// ---------------- conv c1: refpad 3x3, 32->16, leaky(0.2) --------------------
__global__ void conv3x3_c1_kernel(const float* __restrict__ w1)
{
    __shared__ float sw[CI*CIN*9];
    int t = threadIdx.x;
    for (int i = t; i < CI*CIN*9; i += NTHREADS) sw[i] = w1[i];
    __syncthreads();
    int pix = blockIdx.x * NTHREADS + t;
    int b = blockIdx.y;
    int h = pix >> 7, w = pix & 127;
    float acc[CI];
    #pragma unroll
    for (int co = 0; co < CI; co++) acc[co] = 0.f;
    const float* xb = g_fold + (size_t)b * CIN * Hh * Ww;
    for (int ci = 0; ci < CIN; ci++) {
        float v[9];
        #pragma unroll
        for (int dh = 0; dh < 3; dh++) {
            int hh = h + dh - 1;
            hh = hh < 0 ? 1 : (hh >= Hh ? Hh - 2 : hh);
            #pragma unroll
            for (int dw = 0; dw < 3; dw++) {
                int w2p = w + dw - 1;
                w2p = w2p < 0 ? 1 : (w2p >= Ww ? Ww - 2 : w2p);
                v[dh*3 + dw] = xb[(ci*Hh + hh)*Ww + w2p];
            }
        }
        #pragma unroll
        for (int co = 0; co < CI; co++) {
            const float* p1 = &sw[(co*CIN + ci)*9];
            float s1 = 0.f;
            #pragma unroll
            for (int k = 0; k < 9; k++) s1 += p1[k]*v[k];
            acc[co] += s1;
        }
    }
    size_t base = (size_t)b * CI * Hh * Ww + pix;
    #pragma unroll
    for (int co = 0; co < CI; co++) {
        float s = acc[co];
        g_o1[base + (size_t)co*Hh*Ww] = (s > 0.f) ? s : 0.2f*s;
    }
}

// ---------------- conv c2: 1x1 16->32, leaky(0.2), + residual ----------------
__global__ void conv1x1_c2_res_kernel(const float* __restrict__ cw,
                                      const float* __restrict__ x,
                                      float* __restrict__ outp)
{
    __shared__ float sw[CIN*CI];
    int t = threadIdx.x;
    for (int i = t; i < CIN*CI; i += NTHREADS) sw[i] = cw[i];
    __syncthreads();
    int pix = blockIdx.x * NTHREADS + t;
    int b = blockIdx.y;
    float in[CI];
    #pragma unroll
    for (int ci = 0; ci < CI; ci++) in[ci] = g_o1[((size_t)b*CI + ci)*Hh*Ww + pix];
    #pragma unroll
    for (int co = 0; co < CIN; co++) {
        float s = 0.f;
        #pragma unroll
        for (int ci = 0; ci < CI; ci++) s += sw[co*CI + ci]*in[ci];
        s = (s > 0.f) ? s : 0.2f*s;
        size_t idx = ((size_t)b*CIN + co)*Hh*Ww + pix;
        outp[idx] = x[idx] + s;
    }
}

// ---------------- launch ------------------------------------------------------
extern "C" void kernel_launch(void* const* d_in, const int* in_sizes, int n_in,
                              void* d_out, int out_size)
{
    const float* x        = (const float*)d_in[0];
    const float* g_w      = (const float*)d_in[1];
    const float* g_b      = (const float*)d_in[2];
    const float* w_w      = (const float*)d_in[3];
    const float* w_b      = (const float*)d_in[4];
    const float* theta_w  = (const float*)d_in[5];
    const float* theta_b  = (const float*)d_in[6];
    const float* fc1_w    = (const float*)d_in[7];
    const float* fc1_b    = (const float*)d_in[8];
    const float* mconv_w  = (const float*)d_in[9];
    const float* mconv_b  = (const float*)d_in[10];
    const float* mfc_w    = (const float*)d_in[11];
    const float* mfc_b    = (const float*)d_in[12];
    const float* c1_w     = (const float*)d_in[13];
    const float* c2_w     = (const float*)d_in[14];
    float* out = (float*)d_out;

    float *px1, *px2, *px3, *pp6, *pp4, *pp62, *pwfW2, *pxf, *pATi,
          *pMsumP, *pAmP, *py;
    cudaGetSymbolAddress((void**)&px1,   g_x1);
    cudaGetSymbolAddress((void**)&px2,   g_x2);
    cudaGetSymbolAddress((void**)&px3,   g_x3);
    cudaGetSymbolAddress((void**)&pp6,   g_p6);
    cudaGetSymbolAddress((void**)&pp4,   g_p4);
    cudaGetSymbolAddress((void**)&pp62,  g_p62);
    cudaGetSymbolAddress((void**)&pwfW2, g_wfW2);
    cudaGetSymbolAddress((void**)&pxf,   g_xf);
    cudaGetSymbolAddress((void**)&pATi,  g_ATi);
    cudaGetSymbolAddress((void**)&pMsumP,g_MsumP);
    cudaGetSymbolAddress((void**)&pAmP,  g_AmP);
    cudaGetSymbolAddress((void**)&py,    g_y);

    float* pwf = pwfW2;                                   // batches 0..7
    float* pW2 = pwfW2 + (size_t)B_*LL*FOUT;              // batches 8..15

    dim3 convGrid(Hh*Ww/NTHREADS, B_);

    conv3x3_dual_kernel<<<convGrid, NTHREADS>>>(x, g_w, g_b, w_w, w_b);
    conv1x1_theta_kernel<<<convGrid, NTHREADS>>>(theta_w, theta_b);

    {
        size_t tot = (size_t)B_*LL*FIN;
        int nb = (int)((tot + NTHREADS - 1) / NTHREADS);
        unfold_kernel<<<nb, NTHREADS>>>(px1, pp6,  CI, tot);
        unfold_kernel<<<nb, NTHREADS>>>(px2, pp4,  CI, tot);
    }
    {
        size_t tot = (size_t)B_*LL*FV;
        int nb = (int)((tot + NTHREADS - 1) / NTHREADS);
        unfold_kernel<<<nb, NTHREADS>>>(px3, pp62, CIN, tot);
    }

    msum_kernel<<<(int)(((size_t)LL*LL + NTHREADS - 1)/NTHREADS), NTHREADS>>>(
        mconv_w, mfc_w, mconv_b, mfc_b);

    // wf = p4 @ fc1_w^T + fc1_b ; xf = p6 @ fc1_w^T + fc1_b  (bf16x3, flat M)
    {
        dim3 g((FOUT + 127)/128, (B_*LL + 127)/128, 1);
        gemm_bf16x3_kernel<true,false><<<g, 256>>>(pp4, fc1_w, pwf, B_*LL, FOUT, FIN,
                                                   FIN, FIN, FOUT, 0, 0, 0, fc1_b);
        gemm_bf16x3_kernel<true,false><<<g, 256>>>(pp6, fc1_w, pxf, B_*LL, FOUT, FIN,
                                                   FIN, FIN, FOUT, 0, 0, 0, fc1_b);
    }
    // W2[b] = Msum @ wf[b]   (assoc. rewrite; bf16x3)
    {
        dim3 g((FOUT + 127)/128, (LL + 127)/128, B_);
        gemm_bf16x3_kernel<false,false><<<g, 256>>>(pMsumP, pwf, pW2, LL, FOUT, LL,
                                                    LLP, FOUT, FOUT,
                                                    0, (long long)LL*FOUT,
                                                    (long long)LL*FOUT, nullptr);
    }
    // Batched (bf16x3): z<8: A[b] = wf[b]@xf[b]^T ; z>=8: Ti[b] = W2[b]@xf[b]^T
    {
        dim3 g((LL + 127)/128, (LL + 127)/128, 2*B_);
        gemm_bf16x3_kernel<true,true><<<g, 256>>>(pwfW2, pxf, pATi, LL, LL, FOUT,
                                                  FOUT, FOUT, LL,
                                                  (long long)LL*FOUT, (long long)LL*FOUT,
                                                  (long long)LL*LL, nullptr);
    }

    softmax_kernel<<<B_*LL, NTHREADS>>>(out);

    // y[b] = Am[b] @ p62[b]  (TF32 tensor cores, double-buffered)
    {
        dim3 g((FV + 127)/128, (LL + 127)/128, B_);
        gemm_tf32_db_kernel<<<g, 256>>>(pAmP, pp62, py, LL, FV, LL,
                                        LLP, FV, FV,
                                        (long long)LL*LLP, (long long)LL*FV,
                                        (long long)LL*FV);
    }

    fold_kernel<<<(int)(((size_t)B_*CIN*Hh*Ww + NTHREADS - 1)/NTHREADS), NTHREADS>>>();
    conv3x3_c1_kernel<<<convGrid, NTHREADS>>>(c1_w);
    conv1x1_c2_res_kernel<<<convGrid, NTHREADS>>>(c2_w, x, out + (size_t)B_*LL*LL);
}

// round 9
// speedup vs baseline: 2.1681x; 1.0146x over previous
#include <cuda_runtime.h>
#include <math.h>
#include <float.h>

#define B_   8
#define CIN  32
#define CI   16
#define Hh   128
#define Ww   128
#define NHH  31
#define LL   961
#define LLP  964
#define FIN  784
#define FOUT 196
#define FV   1568
#define NTHREADS 256

// packed-pair row lengths (u32 pairs, padded to 8-pair chunks)
#define KP2_FIN   392   // 49 chunks
#define KP2_FOUT  104   // 13 chunks (98 valid + 6 pad)
#define KP2_LL    488   // 61 chunks (481 valid incl. half pair + pad)
#define NPAD_VERT 256   // padded N for vertpacked wf

// ---------------- scratch (device globals) ------------------------------------
__device__ float    g_x1[(size_t)B_*CI*Hh*Ww];
__device__ float    g_x2[(size_t)B_*CI*Hh*Ww];
__device__ float    g_x3[(size_t)B_*CIN*Hh*Ww];
__device__ unsigned g_p4h[(size_t)B_*LL*KP2_FIN], g_p4l[(size_t)B_*LL*KP2_FIN];
__device__ unsigned g_p6h[(size_t)B_*LL*KP2_FIN], g_p6l[(size_t)B_*LL*KP2_FIN];
__device__ float    g_p62[(size_t)B_*LL*FV];
__device__ unsigned g_fc1h[(size_t)FOUT*KP2_FIN], g_fc1l[(size_t)FOUT*KP2_FIN];
__device__ float    g_wf[(size_t)B_*LL*FOUT];
__device__ float    g_xf[(size_t)B_*LL*FOUT];
__device__ float    g_W2[(size_t)B_*LL*FOUT];
__device__ unsigned g_awh[(size_t)2*B_*LL*KP2_FOUT], g_awl[(size_t)2*B_*LL*KP2_FOUT]; // wf|W2 rowpacked
__device__ unsigned g_xfh[(size_t)B_*LL*KP2_FOUT],   g_xfl[(size_t)B_*LL*KP2_FOUT];
__device__ unsigned g_wvh[(size_t)B_*KP2_LL*NPAD_VERT], g_wvl[(size_t)B_*KP2_LL*NPAD_VERT]; // wf vertpacked
__device__ unsigned g_msh[(size_t)LL*KP2_LL], g_msl[(size_t)LL*KP2_LL];  // Msum rowpacked
__device__ float    g_bsum[LL];
__device__ float    g_ATi[(size_t)2*B_*LL*LL];
__device__ float    g_AmP[(size_t)B_*LL*LLP];
__device__ float    g_y[(size_t)B_*LL*FV];
__device__ float    g_fold[(size_t)B_*CIN*Hh*Ww];
__device__ float    g_o1[(size_t)B_*CI*Hh*Ww];

static __device__ __forceinline__ float sigmoid_ref(float x) {
    if (x >= 0.f) return 1.f / (1.f + expf(-x));
    float e = expf(x);
    if (e < FLT_MIN) e = 0.f;
    return e / (1.f + e);
}

// =================== bf16 split helpers ======================================
__device__ __forceinline__ unsigned packbf(float x, float y) {
    unsigned r;
    asm("cvt.rn.bf16x2.f32 %0, %1, %2;" : "=r"(r) : "f"(y), "f"(x));
    return r;   // low = bf16(x), high = bf16(y)
}
__device__ __forceinline__ void split2(float x, float y, unsigned& hi, unsigned& lo) {
    hi = packbf(x, y);
    float hx = __uint_as_float(hi << 16);
    float hy = __uint_as_float(hi & 0xFFFF0000u);
    lo = packbf(x - hx, y - hy);
}
__device__ __forceinline__ void mma_bf16(float c[4],
    unsigned a0, unsigned a1, unsigned a2, unsigned a3, unsigned b0, unsigned b1)
{
    asm volatile("mma.sync.aligned.m16n8k16.row.col.f32.bf16.bf16.f32 "
        "{%0,%1,%2,%3}, {%4,%5,%6,%7}, {%8,%9}, {%0,%1,%2,%3};"
        : "+f"(c[0]), "+f"(c[1]), "+f"(c[2]), "+f"(c[3])
        : "r"(a0), "r"(a1), "r"(a2), "r"(a3), "r"(b0), "r"(b1));
}
__device__ __forceinline__ void mma_tf32(float c[4],
    unsigned a0, unsigned a1, unsigned a2, unsigned a3, unsigned b0, unsigned b1)
{
    asm volatile("mma.sync.aligned.m16n8k8.row.col.f32.tf32.tf32.f32 "
        "{%0,%1,%2,%3}, {%4,%5,%6,%7}, {%8,%9}, {%0,%1,%2,%3};"
        : "+f"(c[0]), "+f"(c[1]), "+f"(c[2]), "+f"(c[3])
        : "r"(a0), "r"(a1), "r"(a2), "r"(a3), "r"(b0), "r"(b1));
}

// ---------------- conv: refpad 3x3, 32->16 twice ------------------------------
__global__ void conv3x3_dual_kernel(const float* __restrict__ x,
                                    const float* __restrict__ w1, const float* __restrict__ b1,
                                    const float* __restrict__ w2, const float* __restrict__ b2)
{
    __shared__ float sw1[CI*CIN*9];
    __shared__ float sw2[CI*CIN*9];
    int t = threadIdx.x;
    for (int i = t; i < CI*CIN*9; i += NTHREADS) { sw1[i] = w1[i]; sw2[i] = w2[i]; }
    __syncthreads();
    int pix = blockIdx.x * NTHREADS + t;
    int b = blockIdx.y;
    int h = pix >> 7, w = pix & 127;
    float acc1[CI], acc2[CI];
    #pragma unroll
    for (int co = 0; co < CI; co++) { acc1[co] = b1[co]; acc2[co] = b2[co]; }
    const float* xb = x + (size_t)b * CIN * Hh * Ww;
    for (int ci = 0; ci < CIN; ci++) {
        float v[9];
        #pragma unroll
        for (int dh = 0; dh < 3; dh++) {
            int hh = h + dh - 1;
            hh = hh < 0 ? 1 : (hh >= Hh ? Hh - 2 : hh);
            #pragma unroll
            for (int dw = 0; dw < 3; dw++) {
                int w2p = w + dw - 1;
                w2p = w2p < 0 ? 1 : (w2p >= Ww ? Ww - 2 : w2p);
                v[dh*3 + dw] = xb[(ci*Hh + hh)*Ww + w2p];
            }
        }
        #pragma unroll
        for (int co = 0; co < CI; co++) {
            const float* p1 = &sw1[(co*CIN + ci)*9];
            const float* p2 = &sw2[(co*CIN + ci)*9];
            float s1 = 0.f, s2 = 0.f;
            #pragma unroll
            for (int k = 0; k < 9; k++) { s1 += p1[k]*v[k]; s2 += p2[k]*v[k]; }
            acc1[co] += s1; acc2[co] += s2;
        }
    }
    size_t base = (size_t)b * CI * Hh * Ww + pix;
    #pragma unroll
    for (int co = 0; co < CI; co++) {
        g_x1[base + (size_t)co*Hh*Ww] = acc1[co];
        g_x2[base + (size_t)co*Hh*Ww] = acc2[co];
    }
}

// ---------------- conv: 1x1 theta --------------------------------------------
__global__ void conv1x1_theta_kernel(const float* __restrict__ tw, const float* __restrict__ tb)
{
    __shared__ float sw[CIN*CI];
    int t = threadIdx.x;
    for (int i = t; i < CIN*CI; i += NTHREADS) sw[i] = tw[i];
    __syncthreads();
    int pix = blockIdx.x * NTHREADS + t;
    int b = blockIdx.y;
    float in[CI];
    #pragma unroll
    for (int ci = 0; ci < CI; ci++) in[ci] = g_x1[((size_t)b*CI + ci)*Hh*Ww + pix];
    #pragma unroll
    for (int co = 0; co < CIN; co++) {
        float s = tb[co];
        #pragma unroll
        for (int ci = 0; ci < CI; ci++) s += sw[co*CI + ci]*in[ci];
        g_x3[((size_t)b*CIN + co)*Hh*Ww + pix] = s;
    }
}

// ---------------- unfold fp32 (p62 only) -------------------------------------
__global__ void unfold_kernel(const float* __restrict__ src, float* __restrict__ dst,
                              int C, size_t total)
{
    size_t t = (size_t)blockIdx.x * NTHREADS + threadIdx.x;
    if (t >= total) return;
    int F = C * 49;
    int f = (int)(t % F);
    size_t r = t / F;
    int l = (int)(r % LL);
    int b = (int)(r / LL);
    int c = f / 49, rr = f % 49, kh = rr / 7, kw = rr % 7;
    int h = (l / NHH)*4 + kh, w = (l % NHH)*4 + kw;
    dst[t] = src[(((size_t)b*C + c)*Hh + h)*Ww + w];
}

// ---------------- unfold + split-pack (p4/p6; C=16, F=784) --------------------
__global__ void unfold_pk_kernel(const float* __restrict__ src,
                                 unsigned* __restrict__ dsth, unsigned* __restrict__ dstl)
{
    size_t t = (size_t)blockIdx.x * NTHREADS + threadIdx.x;
    if (t >= (size_t)B_*LL*KP2_FIN) return;
    int j = (int)(t % KP2_FIN);
    size_t r = t / KP2_FIN;
    int l = (int)(r % LL);
    int b = (int)(r / LL);
    float v[2];
    #pragma unroll
    for (int i = 0; i < 2; i++) {
        int f = 2*j + i;
        int c = f / 49, rr = f % 49, kh = rr / 7, kw = rr % 7;
        int h = (l / NHH)*4 + kh, w = (l % NHH)*4 + kw;
        v[i] = src[(((size_t)b*CI + c)*Hh + h)*Ww + w];
    }
    unsigned hi, lo;
    split2(v[0], v[1], hi, lo);
    dsth[t] = hi; dstl[t] = lo;
}

// ---------------- Msum split-pack + bsum ---------------------------------------
__global__ void msum_pk_kernel(const float* __restrict__ mw1, const float* __restrict__ mw2,
                               const float* __restrict__ mb1, const float* __restrict__ mb2)
{
    size_t t = (size_t)blockIdx.x * NTHREADS + threadIdx.x;
    if (t < (size_t)LL*KP2_LL) {
        int j = (int)(t % KP2_LL);
        int n = (int)(t / KP2_LL);
        int c0 = 2*j, c1 = 2*j + 1;
        float v0 = (c0 < LL) ? mw1[(size_t)n*LL + c0] + mw2[(size_t)n*LL + c0] : 0.f;
        float v1 = (c1 < LL) ? mw1[(size_t)n*LL + c1] + mw2[(size_t)n*LL + c1] : 0.f;
        unsigned hi, lo;
        split2(v0, v1, hi, lo);
        g_msh[t] = hi; g_msl[t] = lo;
    }
    if (t < LL) g_bsum[t] = mb1[t] + mb2[t];
}

// ---------------- generic rowpack: fp32 (R x K, lda) -> packed (R x KP2) ------
__global__ void pack_row_kernel(const float* __restrict__ src,
                                unsigned* __restrict__ dsth, unsigned* __restrict__ dstl,
                                int R, int K, int KP2, int lda)
{
    size_t t = (size_t)blockIdx.x * NTHREADS + threadIdx.x;
    if (t >= (size_t)R*KP2) return;
    int j = (int)(t % KP2);
    int r = (int)(t / KP2);
    int k0 = 2*j;
    float v0 = (k0     < K) ? src[(size_t)r*lda + k0]     : 0.f;
    float v1 = (k0 + 1 < K) ? src[(size_t)r*lda + k0 + 1] : 0.f;
    unsigned hi, lo;
    split2(v0, v1, hi, lo);
    dsth[t] = hi; dstl[t] = lo;
}

// ---------------- wf vertical pack: [b][l][f] -> [b][kk][n] (n padded 256) ----
__global__ void pack_vert_kernel(const float* __restrict__ wf)
{
    size_t t = (size_t)blockIdx.x * NTHREADS + threadIdx.x;
    if (t >= (size_t)B_*KP2_LL*NPAD_VERT) return;
    int n = (int)(t % NPAD_VERT);
    size_t r = t / NPAD_VERT;
    int kk = (int)(r % KP2_LL);
    int b  = (int)(r / KP2_LL);
    int l0 = 2*kk, l1 = 2*kk + 1;
    float v0 = 0.f, v1 = 0.f;
    if (n < FOUT) {
        const float* wb = wf + (size_t)b*LL*FOUT;
        if (l0 < LL) v0 = wb[(size_t)l0*FOUT + n];
        if (l1 < LL) v1 = wb[(size_t)l1*FOUT + n];
    }
    unsigned hi, lo;
    split2(v0, v1, hi, lo);
    g_wvh[t] = hi; g_wvl[t] = lo;
}

// ========= packed bf16x3 GEMM ==================================================
// A rowpacked [batch][M][lda2]. BVERT=false: B rowpacked [batch][N][ldb2]
// (C[m,n]=sum A[m,k]B[n,k]); BVERT=true: B vertpacked [batch][kk][ldb2]
// (C[m,n]=sum A[m,k]B[k,n]). MODB: B batch = z&7.
template <bool BVERT, bool MODB>
__global__ void __launch_bounds__(256, 2) gemm_bf16pk_kernel(
    const unsigned* __restrict__ Ahg, const unsigned* __restrict__ Alg,
    const unsigned* __restrict__ Bhg, const unsigned* __restrict__ Blg,
    float* __restrict__ Cg,
    int M, int N, int nchunks,
    int lda2, int ldb2, int ldc,
    long long sA2, long long sB2, long long sC,
    const float* __restrict__ colBias)
{
    __shared__ unsigned Ah[2][8][136], Al[2][8][136];
    __shared__ unsigned Bh[2][8][136], Bl[2][8][136];

    const int tid = threadIdx.x;
    const int wid = tid >> 5, lane = tid & 31;
    const int wm = wid >> 2, wn = wid & 3;
    const int m_w = wm * 64, n_w = wn * 32;
    const int g = lane >> 2, tg = lane & 3;
    const int m0 = blockIdx.y * 128, n0 = blockIdx.x * 128;
    const unsigned* Ahb = Ahg + (long long)blockIdx.z * sA2;
    const unsigned* Alb = Alg + (long long)blockIdx.z * sA2;
    const long long zb = (long long)(MODB ? (blockIdx.z & 7) : blockIdx.z) * sB2;
    const unsigned* Bhb = Bhg + zb;
    const unsigned* Blb = Blg + zb;
    float* Cb = Cg + (long long)blockIdx.z * sC;

    float acc[4][4][4];
    #pragma unroll
    for (int i = 0; i < 4; i++)
        #pragma unroll
        for (int j = 0; j < 4; j++)
            #pragma unroll
            for (int q = 0; q < 4; q++) acc[i][j][q] = 0.f;

    const int a_c = (tid & 3) * 2;   // pair offset within 8-pair chunk (0,2,4,6)
    const int a_r = tid >> 2;        // 0..63
    const int bn_q = (tid & 31) * 4; // n offset (BVERT)
    const int bk_r = tid >> 5;       // 0..7 (BVERT)

    uint2 vah[2], val[2], vbh[2], vbl[2];
    uint4 bvh, bvl;

    #define LOAD_PK(p0)                                                        \
        _Pragma("unroll")                                                      \
        for (int i = 0; i < 2; i++) {                                          \
            int gm = m0 + a_r + 64*i;                                          \
            if (gm < M) {                                                      \
                long long idx = (long long)gm*lda2 + (p0) + a_c;               \
                vah[i] = *(const uint2*)(Ahb + idx);                           \
                val[i] = *(const uint2*)(Alb + idx);                           \
            } else { vah[i] = make_uint2(0,0); val[i] = make_uint2(0,0); }     \
        }                                                                      \
        if (!BVERT) {                                                          \
            _Pragma("unroll")                                                  \
            for (int i = 0; i < 2; i++) {                                      \
                int gn = n0 + a_r + 64*i;                                      \
                if (gn < N) {                                                  \
                    long long idx = (long long)gn*ldb2 + (p0) + a_c;           \
                    vbh[i] = *(const uint2*)(Bhb + idx);                       \
                    vbl[i] = *(const uint2*)(Blb + idx);                       \
                } else { vbh[i] = make_uint2(0,0); vbl[i] = make_uint2(0,0); } \
            }                                                                  \
        } else {                                                               \
            long long idx = (long long)((p0) + bk_r)*ldb2 + n0 + bn_q;         \
            bvh = *(const uint4*)(Bhb + idx);                                  \
            bvl = *(const uint4*)(Blb + idx);                                  \
        }
    #define STORE_PK(st)                                                       \
        _Pragma("unroll")                                                      \
        for (int i = 0; i < 2; i++) {                                          \
            int m = a_r + 64*i;                                                \
            Ah[st][a_c  ][m] = vah[i].x;  Ah[st][a_c+1][m] = vah[i].y;         \
            Al[st][a_c  ][m] = val[i].x;  Al[st][a_c+1][m] = val[i].y;         \
        }                                                                      \
        if (!BVERT) {                                                          \
            _Pragma("unroll")                                                  \
            for (int i = 0; i < 2; i++) {                                      \
                int n = a_r + 64*i;                                            \
                Bh[st][a_c  ][n] = vbh[i].x;  Bh[st][a_c+1][n] = vbh[i].y;     \
                Bl[st][a_c  ][n] = vbl[i].x;  Bl[st][a_c+1][n] = vbl[i].y;     \
            }                                                                  \
        } else {                                                               \
            *(uint4*)&Bh[st][bk_r][bn_q] = bvh;                                \
            *(uint4*)&Bl[st][bk_r][bn_q] = bvl;                                \
        }

    LOAD_PK(0)
    STORE_PK(0)
    __syncthreads();

    for (int c = 0; c < nchunks; c++) {
        const int st = c & 1;
        if (c + 1 < nchunks) { LOAD_PK((c+1)*8) }
        unsigned bh0[4], bh1[4], bl0[4], bl1[4];
        #pragma unroll
        for (int nt = 0; nt < 4; nt++) {
            int n = n_w + nt*8 + g;
            bh0[nt] = Bh[st][tg  ][n];
            bh1[nt] = Bh[st][tg+4][n];
            bl0[nt] = Bl[st][tg  ][n];
            bl1[nt] = Bl[st][tg+4][n];
        }
        #pragma unroll
        for (int mt = 0; mt < 4; mt++) {
            int m = m_w + mt*16 + g;
            unsigned ah0 = Ah[st][tg  ][m];
            unsigned ah1 = Ah[st][tg  ][m+8];
            unsigned ah2 = Ah[st][tg+4][m];
            unsigned ah3 = Ah[st][tg+4][m+8];
            unsigned al0 = Al[st][tg  ][m];
            unsigned al1 = Al[st][tg  ][m+8];
            unsigned al2 = Al[st][tg+4][m];
            unsigned al3 = Al[st][tg+4][m+8];
            #pragma unroll
            for (int nt = 0; nt < 4; nt++) {
                mma_bf16(acc[mt][nt], ah0, ah1, ah2, ah3, bh0[nt], bh1[nt]);
                mma_bf16(acc[mt][nt], ah0, ah1, ah2, ah3, bl0[nt], bl1[nt]);
                mma_bf16(acc[mt][nt], al0, al1, al2, al3, bh0[nt], bh1[nt]);
            }
        }
        if (c + 1 < nchunks) { STORE_PK(st ^ 1) }
        __syncthreads();
    }
    #undef LOAD_PK
    #undef STORE_PK

    #pragma unroll
    for (int mt = 0; mt < 4; mt++) {
        #pragma unroll
        for (int nt = 0; nt < 4; nt++) {
            int r0 = m0 + m_w + mt*16 + g;
            int r1 = r0 + 8;
            int c  = n0 + n_w + nt*8 + 2*tg;
            float cb0 = (colBias && c   < N) ? colBias[c]   : 0.f;
            float cb1 = (colBias && c+1 < N) ? colBias[c+1] : 0.f;
            if (r0 < M) {
                if (c   < N) Cb[(long long)r0*ldc + c]   = acc[mt][nt][0] + cb0;
                if (c+1 < N) Cb[(long long)r0*ldc + c+1] = acc[mt][nt][1] + cb1;
            }
            if (r1 < M) {
                if (c   < N) Cb[(long long)r1*ldc + c]   = acc[mt][nt][2] + cb0;
                if (c+1 < N) Cb[(long long)r1*ldc + c+1] = acc[mt][nt][3] + cb1;
            }
        }
    }
}

// ============ TF32 y-GEMM: raw-bit tf32 (HW truncation), double-buffered ======
__global__ void __launch_bounds__(256, 2) gemm_tf32_db_kernel(
    const float* __restrict__ Ag, const float* __restrict__ Bg,
    float* __restrict__ Cg, int M, int N, int K,
    int lda, int ldb, int ldc, long long sA, long long sB, long long sC)
{
    __shared__ unsigned As[2][16][136];
    __shared__ unsigned Bs[2][16][136];

    const int tid = threadIdx.x;
    const int wid = tid >> 5, lane = tid & 31;
    const int wm = wid >> 2, wn = wid & 3;
    const int m_w = wm * 64, n_w = wn * 32;
    const int g = lane >> 2, tg = lane & 3;
    const int m0 = blockIdx.y * 128, n0 = blockIdx.x * 128;
    const float* Ab = Ag + (long long)blockIdx.z * sA;
    const float* Bb = Bg + (long long)blockIdx.z * sB;
    float*       Cb = Cg + (long long)blockIdx.z * sC;

    float acc[4][4][4];
    #pragma unroll
    for (int i = 0; i < 4; i++)
        #pragma unroll
        for (int j = 0; j < 4; j++)
            #pragma unroll
            for (int q = 0; q < 4; q++) acc[i][j][q] = 0.f;

    const int a_c = (tid & 3) * 4;
    const int a_r = tid >> 2;
    const int bn_q = (tid & 31) * 4;
    const int bk_r = tid >> 5;

    const int nchunks = (K + 15) / 16;
    float4 va[2], vb[2];

    #define LOAD_A_CHUNK(k0)                                                   \
        _Pragma("unroll")                                                      \
        for (int i = 0; i < 2; i++) {                                          \
            int gm = m0 + a_r + 64*i;                                          \
            float4 v = make_float4(0.f,0.f,0.f,0.f);                           \
            if (gm < M) {                                                      \
                const float* p = Ab + (long long)gm*lda + (k0) + a_c;          \
                if ((k0) + a_c + 3 < K) v = *(const float4*)p;                 \
                else {                                                         \
                    if ((k0) + a_c + 0 < K) v.x = p[0];                        \
                    if ((k0) + a_c + 1 < K) v.y = p[1];                        \
                    if ((k0) + a_c + 2 < K) v.z = p[2];                        \
                }                                                              \
            }                                                                  \
            va[i] = v;                                                         \
        }
    #define LOAD_B_CHUNK(k0)                                                   \
        _Pragma("unroll")                                                      \
        for (int i = 0; i < 2; i++) {                                          \
            int gk = (k0) + bk_r + 8*i;                                        \
            int gn = n0 + bn_q;                                                \
            float4 v = make_float4(0.f,0.f,0.f,0.f);                           \
            if (gk < K) {                                                      \
                const float* p = Bb + (long long)gk*ldb + gn;                  \
                if (gn + 3 < N) v = *(const float4*)p;                         \
                else {                                                         \
                    if (gn+0 < N) v.x = p[0];                                  \
                    if (gn+1 < N) v.y = p[1];                                  \
                    if (gn+2 < N) v.z = p[2];                                  \
                }                                                              \
            }                                                                  \
            vb[i] = v;                                                         \
        }
    #define STORE_CHUNK(st)                                                    \
        _Pragma("unroll")                                                      \
        for (int i = 0; i < 2; i++) {                                          \
            int m = a_r + 64*i;                                                \
            As[st][a_c+0][m] = __float_as_uint(va[i].x);                       \
            As[st][a_c+1][m] = __float_as_uint(va[i].y);                       \
            As[st][a_c+2][m] = __float_as_uint(va[i].z);                       \
            As[st][a_c+3][m] = __float_as_uint(va[i].w);                       \
            int k = bk_r + 8*i;                                                \
            Bs[st][k][bn_q+0] = __float_as_uint(vb[i].x);                      \
            Bs[st][k][bn_q+1] = __float_as_uint(vb[i].y);                      \
            Bs[st][k][bn_q+2] = __float_as_uint(vb[i].z);                      \
            Bs[st][k][bn_q+3] = __float_as_uint(vb[i].w);                      \
        }

    LOAD_A_CHUNK(0)
    LOAD_B_CHUNK(0)
    STORE_CHUNK(0)
    __syncthreads();

    for (int c = 0; c < nchunks; c++) {
        const int st = c & 1;
        if (c + 1 < nchunks) {
            LOAD_A_CHUNK((c+1)*16)
            LOAD_B_CHUNK((c+1)*16)
        }
        #pragma unroll
        for (int kk = 0; kk < 16; kk += 8) {
            unsigned bh[4][2];
            #pragma unroll
            for (int nt = 0; nt < 4; nt++) {
                int n = n_w + nt*8 + g;
                bh[nt][0] = Bs[st][kk + tg][n];
                bh[nt][1] = Bs[st][kk + tg + 4][n];
            }
            #pragma unroll
            for (int mt = 0; mt < 4; mt++) {
                int m = m_w + mt*16 + g;
                unsigned a0 = As[st][kk + tg][m];
                unsigned a1 = As[st][kk + tg][m + 8];
                unsigned a2 = As[st][kk + tg + 4][m];
                unsigned a3 = As[st][kk + tg + 4][m + 8];
                #pragma unroll
                for (int nt = 0; nt < 4; nt++)
                    mma_tf32(acc[mt][nt], a0, a1, a2, a3, bh[nt][0], bh[nt][1]);
            }
        }
        if (c + 1 < nchunks) {
            STORE_CHUNK(st ^ 1)
        }
        __syncthreads();
    }
    #undef LOAD_A_CHUNK
    #undef LOAD_B_CHUNK
    #undef STORE_CHUNK

    #pragma unroll
    for (int mt = 0; mt < 4; mt++) {
        #pragma unroll
        for (int nt = 0; nt < 4; nt++) {
            int r0 = m0 + m_w + mt*16 + g;
            int r1 = r0 + 8;
            int c  = n0 + n_w + nt*8 + 2*tg;
            if (r0 < M) {
                if (c   < N) Cb[(long long)r0*ldc + c]   = acc[mt][nt][0];
                if (c+1 < N) Cb[(long long)r0*ldc + c+1] = acc[mt][nt][1];
            }
            if (r1 < M) {
                if (c   < N) Cb[(long long)r1*ldc + c]   = acc[mt][nt][2];
                if (c+1 < N) Cb[(long long)r1*ldc + c+1] = acc[mt][nt][3];
            }
        }
    }
}

// ---------------- masked softmax -> Am (d_out) + AmP ---------------------------
__global__ void softmax_kernel(float* __restrict__ Am)
{
    int row = blockIdx.x;                    // b*L + l
    const float* Ar = g_ATi + (size_t)row * LL;
    const float* Tr = g_ATi + (size_t)B_*LL*LL + (size_t)row * LL;
    const float bl = g_bsum[row % LL];
    int t = threadIdx.x;
    const float scale = 0.07142857142857142f;
    float v[4], mb[4];
    float mx = -INFINITY;
    #pragma unroll
    for (int i = 0; i < 4; i++) {
        int m = t + i*NTHREADS;
        v[i] = 0.f; mb[i] = 0.f;
        if (m < LL) {
            float mask = sigmoid_ref(Tr[m] + bl);
            v[i] = Ar[m] * mask * scale;
            mb[i] = (mask != 0.f) ? 1.f : 0.f;
            mx = fmaxf(mx, v[i]);
        }
    }
    __shared__ float red[NTHREADS];
    red[t] = mx; __syncthreads();
    for (int s = NTHREADS/2; s > 0; s >>= 1) {
        if (t < s) red[t] = fmaxf(red[t], red[t+s]);
        __syncthreads();
    }
    mx = red[0]; __syncthreads();
    float e[4]; float sum = 0.f;
    #pragma unroll
    for (int i = 0; i < 4; i++) {
        int m = t + i*NTHREADS;
        if (m < LL) { e[i] = expf(v[i] - mx); sum += e[i]; } else e[i] = 0.f;
    }
    red[t] = sum; __syncthreads();
    for (int s = NTHREADS/2; s > 0; s >>= 1) {
        if (t < s) red[t] += red[t+s];
        __syncthreads();
    }
    float inv = 1.f / red[0];
    #pragma unroll
    for (int i = 0; i < 4; i++) {
        int m = t + i*NTHREADS;
        if (m < LL) {
            float val = e[i] * inv * mb[i];
            Am[(size_t)row*LL + m] = val;
            g_AmP[(size_t)row*LLP + m] = val;
        }
    }
}

// ---------------- fold (gather form) -------------------------------------------
__global__ void fold_kernel()
{
    size_t t = (size_t)blockIdx.x * NTHREADS + threadIdx.x;
    if (t >= (size_t)B_*CIN*Hh*Ww) return;
    int w = (int)(t % Ww); size_t r = t / Ww;
    int h = (int)(r % Hh); r /= Hh;
    int c = (int)(r % CIN);
    int b = (int)(r / CIN);
    int i0 = (h > 6) ? (h - 3) >> 2 : 0;
    int i1 = h >> 2; if (i1 > NHH - 1) i1 = NHH - 1;
    int j0 = (w > 6) ? (w - 3) >> 2 : 0;
    int j1 = w >> 2; if (j1 > NHH - 1) j1 = NHH - 1;
    float s = 0.f;
    for (int i = i0; i <= i1; i++) {
        int kh = h - i*4;
        for (int j = j0; j <= j1; j++) {
            int kw = w - j*4;
            s += g_y[((size_t)b*LL + i*NHH + j)*FV + c*49 + kh*7 + kw];
        }
    }
    g_fold[t] = s;
}

// ---------------- conv c1 -------------------------------------------------------
__global__ void conv3x3_c1_kernel(const float* __restrict__ w1)
{
    __shared__ float sw[CI*CIN*9];
    int t = threadIdx.x;
    for (int i = t; i < CI*CIN*9; i += NTHREADS) sw[i] = w1[i];
    __syncthreads();
    int pix = blockIdx.x * NTHREADS + t;
    int b = blockIdx.y;
    int h = pix >> 7, w = pix & 127;
    float acc[CI];
    #pragma unroll
    for (int co = 0; co < CI; co++) acc[co] = 0.f;
    const float* xb = g_fold + (size_t)b * CIN * Hh * Ww;
    for (int ci = 0; ci < CIN; ci++) {
        float v[9];
        #pragma unroll
        for (int dh = 0; dh < 3; dh++) {
            int hh = h + dh - 1;
            hh = hh < 0 ? 1 : (hh >= Hh ? Hh - 2 : hh);
            #pragma unroll
            for (int dw = 0; dw < 3; dw++) {
                int w2p = w + dw - 1;
                w2p = w2p < 0 ? 1 : (w2p >= Ww ? Ww - 2 : w2p);
                v[dh*3 + dw] = xb[(ci*Hh + hh)*Ww + w2p];
            }
        }
        #pragma unroll
        for (int co = 0; co < CI; co++) {
            const float* p1 = &sw[(co*CIN + ci)*9];
            float s1 = 0.f;
            #pragma unroll
            for (int k = 0; k < 9; k++) s1 += p1[k]*v[k];
            acc[co] += s1;
        }
    }
    size_t base = (size_t)b * CI * Hh * Ww + pix;
    #pragma unroll
    for (int co = 0; co < CI; co++) {
        float s = acc[co];
        g_o1[base + (size_t)co*Hh*Ww] = (s > 0.f) ? s : 0.2f*s;
    }
}

// ---------------- conv c2 + residual --------------------------------------------
__global__ void conv1x1_c2_res_kernel(const float* __restrict__ cw,
                                      const float* __restrict__ x,
                                      float* __restrict__ outp)
{
    __shared__ float sw[CIN*CI];
    int t = threadIdx.x;
    for (int i = t; i < CIN*CI; i += NTHREADS) sw[i] = cw[i];
    __syncthreads();
    int pix = blockIdx.x * NTHREADS + t;
    int b = blockIdx.y;
    float in[CI];
    #pragma unroll
    for (int ci = 0; ci < CI; ci++) in[ci] = g_o1[((size_t)b*CI + ci)*Hh*Ww + pix];
    #pragma unroll
    for (int co = 0; co < CIN; co++) {
        float s = 0.f;
        #pragma unroll
        for (int ci = 0; ci < CI; ci++) s += sw[co*CI + ci]*in[ci];
        s = (s > 0.f) ? s : 0.2f*s;
        size_t idx = ((size_t)b*CIN + co)*Hh*Ww + pix;
        outp[idx] = x[idx] + s;
    }
}

// ---------------- launch ---------------------------------------------------------
extern "C" void kernel_launch(void* const* d_in, const int* in_sizes, int n_in,
                              void* d_out, int out_size)
{
    const float* x        = (const float*)d_in[0];
    const float* g_w      = (const float*)d_in[1];
    const float* g_b      = (const float*)d_in[2];
    const float* w_w      = (const float*)d_in[3];
    const float* w_b      = (const float*)d_in[4];
    const float* theta_w  = (const float*)d_in[5];
    const float* theta_b  = (const float*)d_in[6];
    const float* fc1_w    = (const float*)d_in[7];
    const float* fc1_b    = (const float*)d_in[8];
    const float* mconv_w  = (const float*)d_in[9];
    const float* mconv_b  = (const float*)d_in[10];
    const float* mfc_w    = (const float*)d_in[11];
    const float* mfc_b    = (const float*)d_in[12];
    const float* c1_w     = (const float*)d_in[13];
    const float* c2_w     = (const float*)d_in[14];
    float* out = (float*)d_out;

    float *px1, *px2, *px3, *pp62, *pwf, *pxf, *pW2, *pATi, *pAmP, *py;
    unsigned *pp4h, *pp4l, *pp6h, *pp6l, *pfc1h, *pfc1l,
             *pawh, *pawl, *pxfh, *pxfl, *pwvh, *pwvl, *pmsh, *pmsl;
    cudaGetSymbolAddress((void**)&px1,  g_x1);
    cudaGetSymbolAddress((void**)&px2,  g_x2);
    cudaGetSymbolAddress((void**)&px3,  g_x3);
    cudaGetSymbolAddress((void**)&pp62, g_p62);
    cudaGetSymbolAddress((void**)&pwf,  g_wf);
    cudaGetSymbolAddress((void**)&pxf,  g_xf);
    cudaGetSymbolAddress((void**)&pW2,  g_W2);
    cudaGetSymbolAddress((void**)&pATi, g_ATi);
    cudaGetSymbolAddress((void**)&pAmP, g_AmP);
    cudaGetSymbolAddress((void**)&py,   g_y);
    cudaGetSymbolAddress((void**)&pp4h, g_p4h);
    cudaGetSymbolAddress((void**)&pp4l, g_p4l);
    cudaGetSymbolAddress((void**)&pp6h, g_p6h);
    cudaGetSymbolAddress((void**)&pp6l, g_p6l);
    cudaGetSymbolAddress((void**)&pfc1h,g_fc1h);
    cudaGetSymbolAddress((void**)&pfc1l,g_fc1l);
    cudaGetSymbolAddress((void**)&pawh, g_awh);
    cudaGetSymbolAddress((void**)&pawl, g_awl);
    cudaGetSymbolAddress((void**)&pxfh, g_xfh);
    cudaGetSymbolAddress((void**)&pxfl, g_xfl);
    cudaGetSymbolAddress((void**)&pwvh, g_wvh);
    cudaGetSymbolAddress((void**)&pwvl, g_wvl);
    cudaGetSymbolAddress((void**)&pmsh, g_msh);
    cudaGetSymbolAddress((void**)&pmsl, g_msl);

    dim3 convGrid(Hh*Ww/NTHREADS, B_);
    #define GBLK(n) ((int)(((size_t)(n) + NTHREADS - 1) / NTHREADS))

    conv3x3_dual_kernel<<<convGrid, NTHREADS>>>(x, g_w, g_b, w_w, w_b);
    conv1x1_theta_kernel<<<convGrid, NTHREADS>>>(theta_w, theta_b);

    // packed unfolds (p4 from x2, p6 from x1) + fp32 unfold for p62 (x3)
    unfold_pk_kernel<<<GBLK((size_t)B_*LL*KP2_FIN), NTHREADS>>>(px2, pp4h, pp4l);
    unfold_pk_kernel<<<GBLK((size_t)B_*LL*KP2_FIN), NTHREADS>>>(px1, pp6h, pp6l);
    unfold_kernel<<<GBLK((size_t)B_*LL*FV), NTHREADS>>>(px3, pp62, CIN, (size_t)B_*LL*FV);

    // packed Msum + bsum; packed fc1_w
    msum_pk_kernel<<<GBLK((size_t)LL*KP2_LL), NTHREADS>>>(mconv_w, mfc_w, mconv_b, mfc_b);
    pack_row_kernel<<<GBLK((size_t)FOUT*KP2_FIN), NTHREADS>>>(fc1_w, pfc1h, pfc1l,
                                                              FOUT, FIN, KP2_FIN, FIN);

    // wf = p4 ⊗ fc1^T + b ; xf = p6 ⊗ fc1^T + b (packed bf16x3, flat M = B*L)
    {
        dim3 g((FOUT + 127)/128, (B_*LL + 127)/128, 1);
        gemm_bf16pk_kernel<false,false><<<g, 256>>>(pp4h, pp4l, pfc1h, pfc1l, pwf,
                                                    B_*LL, FOUT, FIN/16,
                                                    KP2_FIN, KP2_FIN, FOUT,
                                                    0, 0, 0, fc1_b);
        gemm_bf16pk_kernel<false,false><<<g, 256>>>(pp6h, pp6l, pfc1h, pfc1l, pxf,
                                                    B_*LL, FOUT, FIN/16,
                                                    KP2_FIN, KP2_FIN, FOUT,
                                                    0, 0, 0, fc1_b);
    }

    // pack wf (rowpack -> aw batches 0..8, vertpack) and xf (rowpack)
    pack_row_kernel<<<GBLK((size_t)B_*LL*KP2_FOUT), NTHREADS>>>(pwf, pawh, pawl,
                                                                B_*LL, FOUT, KP2_FOUT, FOUT);
    pack_row_kernel<<<GBLK((size_t)B_*LL*KP2_FOUT), NTHREADS>>>(pxf, pxfh, pxfl,
                                                                B_*LL, FOUT, KP2_FOUT, FOUT);
    pack_vert_kernel<<<GBLK((size_t)B_*KP2_LL*NPAD_VERT), NTHREADS>>>(pwf);

    // W2[b] = Msum ⊗ wf[b] (A rowpacked shared, B vertpacked per batch)
    {
        dim3 g((FOUT + 127)/128, (LL + 127)/128, B_);
        gemm_bf16pk_kernel<true,false><<<g, 256>>>(pmsh, pmsl, pwvh, pwvl, pW2,
                                                   LL, FOUT, 61,
                                                   KP2_LL, NPAD_VERT, FOUT,
                                                   0, (long long)KP2_LL*NPAD_VERT,
                                                   (long long)LL*FOUT, nullptr);
    }
    // pack W2 -> aw batches 8..16
    pack_row_kernel<<<GBLK((size_t)B_*LL*KP2_FOUT), NTHREADS>>>(pW2,
        pawh + (size_t)B_*LL*KP2_FOUT, pawl + (size_t)B_*LL*KP2_FOUT,
        B_*LL, FOUT, KP2_FOUT, FOUT);

    // Batched: z<8: A[b] = wf[b]⊗xf[b]^T ; z>=8: Ti[b] = W2[b]⊗xf[b]^T
    {
        dim3 g((LL + 127)/128, (LL + 127)/128, 2*B_);
        gemm_bf16pk_kernel<false,true><<<g, 256>>>(pawh, pawl, pxfh, pxfl, pATi,
                                                   LL, LL, 13,
                                                   KP2_FOUT, KP2_FOUT, LL,
                                                   (long long)LL*KP2_FOUT,
                                                   (long long)LL*KP2_FOUT,
                                                   (long long)LL*LL, nullptr);
    }

    softmax_kernel<<<B_*LL, NTHREADS>>>(out);

    // y[b] = Am[b] @ p62[b]  (tf32 raw-bit, double-buffered)
    {
        dim3 g((FV + 127)/128, (LL + 127)/128, B_);
        gemm_tf32_db_kernel<<<g, 256>>>(pAmP, pp62, py, LL, FV, LL,
                                        LLP, FV, FV,
                                        (long long)LL*LLP, (long long)LL*FV,
                                        (long long)LL*FV);
    }

    fold_kernel<<<GBLK((size_t)B_*CIN*Hh*Ww), NTHREADS>>>();
    conv3x3_c1_kernel<<<convGrid, NTHREADS>>>(c1_w);
    conv1x1_c2_res_kernel<<<convGrid, NTHREADS>>>(c2_w, x, out + (size_t)B_*LL*LL);
    #undef GBLK
}

// round 12
// speedup vs baseline: 2.4076x; 1.1105x over previous
#include <cuda_runtime.h>
#include <cstdint>
#include <math.h>
#include <float.h>

#define B_   8
#define CIN  32
#define CI   16
#define Hh   128
#define Ww   128
#define NHH  31
#define LL   961
#define FIN  784
#define FOUT 196
#define FV   1568
#define NTHREADS 256

// packed-pair row lengths (u32 pairs, padded to 8-pair chunks)
#define KP2_FIN   392   // 49 chunks
#define KP2_FOUT  104   // 13 chunks
#define KP2_LL    488   // 61 chunks (Msum rowpack / y K-pairs)
#define NPAD_VERT 256
#define KP2_Y     488   // y-GEMM K pairs (61 chunks); 481..487 zero

// ---------------- scratch (device globals) ------------------------------------
__device__ float    g_x1[(size_t)B_*CI*Hh*Ww];
__device__ float    g_x2[(size_t)B_*CI*Hh*Ww];
__device__ float    g_x3[(size_t)B_*CIN*Hh*Ww];
__device__ unsigned g_p4h[(size_t)B_*LL*KP2_FIN], g_p4l[(size_t)B_*LL*KP2_FIN];
__device__ unsigned g_p6h[(size_t)B_*LL*KP2_FIN], g_p6l[(size_t)B_*LL*KP2_FIN];
__device__ unsigned g_fc1h[(size_t)FOUT*KP2_FIN], g_fc1l[(size_t)FOUT*KP2_FIN];
__device__ float    g_wf[(size_t)B_*LL*FOUT];
__device__ float    g_xf[(size_t)B_*LL*FOUT];
__device__ float    g_W2[(size_t)B_*LL*FOUT];
__device__ unsigned g_awh[(size_t)2*B_*LL*KP2_FOUT], g_awl[(size_t)2*B_*LL*KP2_FOUT];
__device__ unsigned g_xfh[(size_t)B_*LL*KP2_FOUT],   g_xfl[(size_t)B_*LL*KP2_FOUT];
__device__ unsigned g_wvh[(size_t)B_*KP2_LL*NPAD_VERT], g_wvl[(size_t)B_*KP2_LL*NPAD_VERT];
__device__ unsigned g_msh[(size_t)LL*KP2_LL], g_msl[(size_t)LL*KP2_LL];
__device__ float    g_bsum[LL];
__device__ float    g_ATi[(size_t)2*B_*LL*LL];
__device__ unsigned g_amf[(size_t)B_*LL*KP2_Y];    // Am fp16 pairs
__device__ unsigned g_ptf[(size_t)B_*FV*KP2_Y];    // p62^T fp16 pairs
__device__ float    g_y[(size_t)B_*LL*FV];
__device__ float    g_fold[(size_t)B_*CIN*Hh*Ww];
__device__ float    g_o1[(size_t)B_*CI*Hh*Ww];

static __device__ __forceinline__ float sigmoid_ref(float x) {
    if (x >= 0.f) return 1.f / (1.f + expf(-x));
    float e = expf(x);
    if (e < FLT_MIN) e = 0.f;
    return e / (1.f + e);
}

// =================== pack / mma helpers ========================================
__device__ __forceinline__ unsigned packbf(float x, float y) {
    unsigned r;
    asm("cvt.rn.bf16x2.f32 %0, %1, %2;" : "=r"(r) : "f"(y), "f"(x));
    return r;   // low = bf16(x), high = bf16(y)
}
__device__ __forceinline__ unsigned packf16(float x, float y) {
    unsigned r;
    asm("cvt.rn.f16x2.f32 %0, %1, %2;" : "=r"(r) : "f"(y), "f"(x));
    return r;   // low = f16(x), high = f16(y)
}
__device__ __forceinline__ void split2(float x, float y, unsigned& hi, unsigned& lo) {
    hi = packbf(x, y);
    float hx = __uint_as_float(hi << 16);
    float hy = __uint_as_float(hi & 0xFFFF0000u);
    lo = packbf(x - hx, y - hy);
}
__device__ __forceinline__ void mma_bf16(float c[4],
    unsigned a0, unsigned a1, unsigned a2, unsigned a3, unsigned b0, unsigned b1)
{
    asm volatile("mma.sync.aligned.m16n8k16.row.col.f32.bf16.bf16.f32 "
        "{%0,%1,%2,%3}, {%4,%5,%6,%7}, {%8,%9}, {%0,%1,%2,%3};"
        : "+f"(c[0]), "+f"(c[1]), "+f"(c[2]), "+f"(c[3])
        : "r"(a0), "r"(a1), "r"(a2), "r"(a3), "r"(b0), "r"(b1));
}
__device__ __forceinline__ void mma_f16(float c[4],
    unsigned a0, unsigned a1, unsigned a2, unsigned a3, unsigned b0, unsigned b1)
{
    asm volatile("mma.sync.aligned.m16n8k16.row.col.f32.f16.f16.f32 "
        "{%0,%1,%2,%3}, {%4,%5,%6,%7}, {%8,%9}, {%0,%1,%2,%3};"
        : "+f"(c[0]), "+f"(c[1]), "+f"(c[2]), "+f"(c[3])
        : "r"(a0), "r"(a1), "r"(a2), "r"(a3), "r"(b0), "r"(b1));
}

// ---------------- conv: refpad 3x3, 32->16 twice ------------------------------
__global__ void conv3x3_dual_kernel(const float* __restrict__ x,
                                    const float* __restrict__ w1, const float* __restrict__ b1,
                                    const float* __restrict__ w2, const float* __restrict__ b2)
{
    __shared__ float sw1[CI*CIN*9];
    __shared__ float sw2[CI*CIN*9];
    int t = threadIdx.x;
    for (int i = t; i < CI*CIN*9; i += NTHREADS) { sw1[i] = w1[i]; sw2[i] = w2[i]; }
    __syncthreads();
    int pix = blockIdx.x * NTHREADS + t;
    int b = blockIdx.y;
    int h = pix >> 7, w = pix & 127;
    float acc1[CI], acc2[CI];
    #pragma unroll
    for (int co = 0; co < CI; co++) { acc1[co] = b1[co]; acc2[co] = b2[co]; }
    const float* xb = x + (size_t)b * CIN * Hh * Ww;
    for (int ci = 0; ci < CIN; ci++) {
        float v[9];
        #pragma unroll
        for (int dh = 0; dh < 3; dh++) {
            int hh = h + dh - 1;
            hh = hh < 0 ? 1 : (hh >= Hh ? Hh - 2 : hh);
            #pragma unroll
            for (int dw = 0; dw < 3; dw++) {
                int w2p = w + dw - 1;
                w2p = w2p < 0 ? 1 : (w2p >= Ww ? Ww - 2 : w2p);
                v[dh*3 + dw] = xb[(ci*Hh + hh)*Ww + w2p];
            }
        }
        #pragma unroll
        for (int co = 0; co < CI; co++) {
            const float* p1 = &sw1[(co*CIN + ci)*9];
            const float* p2 = &sw2[(co*CIN + ci)*9];
            float s1 = 0.f, s2 = 0.f;
            #pragma unroll
            for (int k = 0; k < 9; k++) { s1 += p1[k]*v[k]; s2 += p2[k]*v[k]; }
            acc1[co] += s1; acc2[co] += s2;
        }
    }
    size_t base = (size_t)b * CI * Hh * Ww + pix;
    #pragma unroll
    for (int co = 0; co < CI; co++) {
        g_x1[base + (size_t)co*Hh*Ww] = acc1[co];
        g_x2[base + (size_t)co*Hh*Ww] = acc2[co];
    }
}

// ---------------- conv: 1x1 theta ---------------------------------------------
__global__ void conv1x1_theta_kernel(const float* __restrict__ tw, const float* __restrict__ tb)
{
    __shared__ float sw[CIN*CI];
    int t = threadIdx.x;
    for (int i = t; i < CIN*CI; i += NTHREADS) sw[i] = tw[i];
    __syncthreads();
    int pix = blockIdx.x * NTHREADS + t;
    int b = blockIdx.y;
    float in[CI];
    #pragma unroll
    for (int ci = 0; ci < CI; ci++) in[ci] = g_x1[((size_t)b*CI + ci)*Hh*Ww + pix];
    #pragma unroll
    for (int co = 0; co < CIN; co++) {
        float s = tb[co];
        #pragma unroll
        for (int ci = 0; ci < CI; ci++) s += sw[co*CI + ci]*in[ci];
        g_x3[((size_t)b*CIN + co)*Hh*Ww + pix] = s;
    }
}

// ---------------- unfold + split-pack (p4/p6; C=16) ---------------------------
__global__ void unfold_pk_kernel(const float* __restrict__ src,
                                 unsigned* __restrict__ dsth, unsigned* __restrict__ dstl)
{
    size_t t = (size_t)blockIdx.x * NTHREADS + threadIdx.x;
    if (t >= (size_t)B_*LL*KP2_FIN) return;
    int j = (int)(t % KP2_FIN);
    size_t r = t / KP2_FIN;
    int l = (int)(r % LL);
    int b = (int)(r / LL);
    float v[2];
    #pragma unroll
    for (int i = 0; i < 2; i++) {
        int f = 2*j + i;
        int c = f / 49, rr = f % 49, kh = rr / 7, kw = rr % 7;
        int h = (l / NHH)*4 + kh, w = (l % NHH)*4 + kw;
        v[i] = src[(((size_t)b*CI + c)*Hh + h)*Ww + w];
    }
    unsigned hi, lo;
    split2(v[0], v[1], hi, lo);
    dsth[t] = hi; dstl[t] = lo;
}

// ---------------- p62^T fp16 pack: [b][f][j], k = l pairs ----------------------
__global__ void unfold_p62t_f16_kernel()
{
    size_t t = (size_t)blockIdx.x * NTHREADS + threadIdx.x;
    if (t >= (size_t)B_*FV*KP2_Y) return;
    int j = (int)(t % KP2_Y);
    size_t r = t / KP2_Y;
    int f = (int)(r % FV);
    int b = (int)(r / FV);
    int c = f / 49, rr = f % 49, kh = rr / 7, kw = rr % 7;
    float v[2] = {0.f, 0.f};
    #pragma unroll
    for (int i = 0; i < 2; i++) {
        int l = 2*j + i;
        if (l < LL) {
            int h = (l / NHH)*4 + kh, w = (l % NHH)*4 + kw;
            v[i] = g_x3[(((size_t)b*CIN + c)*Hh + h)*Ww + w];
        }
    }
    g_ptf[t] = packf16(v[0], v[1]);
}

// ---------------- Am fp16 pack: [b*L rows][KP2_Y] ------------------------------
__global__ void pack_am_f16_kernel(const float* __restrict__ Am)
{
    size_t t = (size_t)blockIdx.x * NTHREADS + threadIdx.x;
    if (t >= (size_t)B_*LL*KP2_Y) return;
    int j = (int)(t % KP2_Y);
    size_t row = t / KP2_Y;
    int l0 = 2*j, l1 = 2*j + 1;
    float v0 = (l0 < LL) ? Am[row*LL + l0] : 0.f;
    float v1 = (l1 < LL) ? Am[row*LL + l1] : 0.f;
    g_amf[t] = packf16(v0, v1);
}

// ---------------- Msum split-pack + bsum ---------------------------------------
__global__ void msum_pk_kernel(const float* __restrict__ mw1, const float* __restrict__ mw2,
                               const float* __restrict__ mb1, const float* __restrict__ mb2)
{
    size_t t = (size_t)blockIdx.x * NTHREADS + threadIdx.x;
    if (t < (size_t)LL*KP2_LL) {
        int j = (int)(t % KP2_LL);
        int n = (int)(t / KP2_LL);
        int c0 = 2*j, c1 = 2*j + 1;
        float v0 = (c0 < LL) ? mw1[(size_t)n*LL + c0] + mw2[(size_t)n*LL + c0] : 0.f;
        float v1 = (c1 < LL) ? mw1[(size_t)n*LL + c1] + mw2[(size_t)n*LL + c1] : 0.f;
        unsigned hi, lo;
        split2(v0, v1, hi, lo);
        g_msh[t] = hi; g_msl[t] = lo;
    }
    if (t < LL) g_bsum[t] = mb1[t] + mb2[t];
}

// ---------------- generic rowpack ----------------------------------------------
__global__ void pack_row_kernel(const float* __restrict__ src,
                                unsigned* __restrict__ dsth, unsigned* __restrict__ dstl,
                                int R, int K, int KP2, int lda)
{
    size_t t = (size_t)blockIdx.x * NTHREADS + threadIdx.x;
    if (t >= (size_t)R*KP2) return;
    int j = (int)(t % KP2);
    int r = (int)(t / KP2);
    int k0 = 2*j;
    float v0 = (k0     < K) ? src[(size_t)r*lda + k0]     : 0.f;
    float v1 = (k0 + 1 < K) ? src[(size_t)r*lda + k0 + 1] : 0.f;
    unsigned hi, lo;
    split2(v0, v1, hi, lo);
    dsth[t] = hi; dstl[t] = lo;
}

// ---------------- wf vertical pack ----------------------------------------------
__global__ void pack_vert_kernel(const float* __restrict__ wf)
{
    size_t t = (size_t)blockIdx.x * NTHREADS + threadIdx.x;
    if (t >= (size_t)B_*KP2_LL*NPAD_VERT) return;
    int n = (int)(t % NPAD_VERT);
    size_t r = t / NPAD_VERT;
    int kk = (int)(r % KP2_LL);
    int b  = (int)(r / KP2_LL);
    int l0 = 2*kk, l1 = 2*kk + 1;
    float v0 = 0.f, v1 = 0.f;
    if (n < FOUT) {
        const float* wb = wf + (size_t)b*LL*FOUT;
        if (l0 < LL) v0 = wb[(size_t)l0*FOUT + n];
        if (l1 < LL) v1 = wb[(size_t)l1*FOUT + n];
    }
    unsigned hi, lo;
    split2(v0, v1, hi, lo);
    g_wvh[t] = hi; g_wvl[t] = lo;
}

// ========= packed pair GEMM (bf16x3 split OR single-pass fp16) =================
// A rowpacked [batch][M][lda2]. BVERT=false: B rowpacked [batch][N][ldb2]
// (C[m,n]=sum A[m,k]B[n,k]); BVERT=true: B vertpacked [batch][kk][ldb2].
// MODB: B batch = z&7. SPLIT: 3-pass hi/lo (bf16x3). F16: use f16 mma.
template <bool BVERT, bool MODB, bool SPLIT, bool F16>
__global__ void __launch_bounds__(256, 2) gemm_pk_kernel(
    const unsigned* __restrict__ Ahg, const unsigned* __restrict__ Alg,
    const unsigned* __restrict__ Bhg, const unsigned* __restrict__ Blg,
    float* __restrict__ Cg,
    int M, int N, int nchunks,
    int lda2, int ldb2, int ldc,
    long long sA2, long long sB2, long long sC,
    const float* __restrict__ colBias)
{
    __shared__ unsigned Ah[2][8][136];
    __shared__ unsigned Bh[2][8][136];
    __shared__ unsigned Al[SPLIT ? 2 : 1][SPLIT ? 8 : 1][SPLIT ? 136 : 1];
    __shared__ unsigned Bl[SPLIT ? 2 : 1][SPLIT ? 8 : 1][SPLIT ? 136 : 1];

    const int tid = threadIdx.x;
    const int wid = tid >> 5, lane = tid & 31;
    const int wm = wid >> 2, wn = wid & 3;
    const int m_w = wm * 64, n_w = wn * 32;
    const int g = lane >> 2, tg = lane & 3;
    const int m0 = blockIdx.y * 128, n0 = blockIdx.x * 128;
    const unsigned* Ahb = Ahg + (long long)blockIdx.z * sA2;
    const unsigned* Alb = SPLIT ? (Alg + (long long)blockIdx.z * sA2) : Ahg;
    const long long zb = (long long)(MODB ? (blockIdx.z & 7) : blockIdx.z) * sB2;
    const unsigned* Bhb = Bhg + zb;
    const unsigned* Blb = SPLIT ? (Blg + zb) : Bhg;
    float* Cb = Cg + (long long)blockIdx.z * sC;

    float acc[4][4][4];
    #pragma unroll
    for (int i = 0; i < 4; i++)
        #pragma unroll
        for (int j = 0; j < 4; j++)
            #pragma unroll
            for (int q = 0; q < 4; q++) acc[i][j][q] = 0.f;

    const int a_c = (tid & 3) * 2;   // pair offset within 8-pair chunk
    const int a_r = tid >> 2;        // 0..63
    const int bn_q = (tid & 31) * 4; // n offset (BVERT)
    const int bk_r = tid >> 5;       // 0..7 (BVERT)

    uint2 vah[2], val[2], vbh[2], vbl[2];
    uint4 bvh, bvl;

    #define LOAD_PK(p0)                                                        \
        _Pragma("unroll")                                                      \
        for (int i = 0; i < 2; i++) {                                          \
            int gm = m0 + a_r + 64*i;                                          \
            if (gm < M) {                                                      \
                long long idx = (long long)gm*lda2 + (p0) + a_c;               \
                vah[i] = *(const uint2*)(Ahb + idx);                           \
                if (SPLIT) val[i] = *(const uint2*)(Alb + idx);                \
            } else { vah[i] = make_uint2(0,0); val[i] = make_uint2(0,0); }     \
        }                                                                      \
        if (!BVERT) {                                                          \
            _Pragma("unroll")                                                  \
            for (int i = 0; i < 2; i++) {                                      \
                int gn = n0 + a_r + 64*i;                                      \
                if (gn < N) {                                                  \
                    long long idx = (long long)gn*ldb2 + (p0) + a_c;           \
                    vbh[i] = *(const uint2*)(Bhb + idx);                       \
                    if (SPLIT) vbl[i] = *(const uint2*)(Blb + idx);            \
                } else { vbh[i] = make_uint2(0,0); vbl[i] = make_uint2(0,0); } \
            }                                                                  \
        } else {                                                               \
            long long idx = (long long)((p0) + bk_r)*ldb2 + n0 + bn_q;         \
            bvh = *(const uint4*)(Bhb + idx);                                  \
            if (SPLIT) bvl = *(const uint4*)(Blb + idx);                       \
        }
    #define STORE_PK(st)                                                       \
        _Pragma("unroll")                                                      \
        for (int i = 0; i < 2; i++) {                                          \
            int m = a_r + 64*i;                                                \
            Ah[st][a_c  ][m] = vah[i].x;  Ah[st][a_c+1][m] = vah[i].y;         \
            if (SPLIT) { Al[st][a_c  ][m] = val[i].x;                          \
                         Al[st][a_c+1][m] = val[i].y; }                        \
        }                                                                      \
        if (!BVERT) {                                                          \
            _Pragma("unroll")                                                  \
            for (int i = 0; i < 2; i++) {                                      \
                int n = a_r + 64*i;                                            \
                Bh[st][a_c  ][n] = vbh[i].x;  Bh[st][a_c+1][n] = vbh[i].y;     \
                if (SPLIT) { Bl[st][a_c  ][n] = vbl[i].x;                      \
                             Bl[st][a_c+1][n] = vbl[i].y; }                    \
            }                                                                  \
        } else {                                                               \
            *(uint4*)&Bh[st][bk_r][bn_q] = bvh;                                \
            if (SPLIT) { *(uint4*)&Bl[st][bk_r][bn_q] = bvl; }                 \
        }

    LOAD_PK(0)
    STORE_PK(0)
    __syncthreads();

    for (int c = 0; c < nchunks; c++) {
        const int st = c & 1;
        if (c + 1 < nchunks) { LOAD_PK((c+1)*8) }
        unsigned bh0[4], bh1[4], bl0[4], bl1[4];
        #pragma unroll
        for (int nt = 0; nt < 4; nt++) {
            int n = n_w + nt*8 + g;
            bh0[nt] = Bh[st][tg  ][n];
            bh1[nt] = Bh[st][tg+4][n];
            if (SPLIT) {
                bl0[nt] = Bl[st][tg  ][n];
                bl1[nt] = Bl[st][tg+4][n];
            }
        }
        #pragma unroll
        for (int mt = 0; mt < 4; mt++) {
            int m = m_w + mt*16 + g;
            unsigned ah0 = Ah[st][tg  ][m];
            unsigned ah1 = Ah[st][tg  ][m+8];
            unsigned ah2 = Ah[st][tg+4][m];
            unsigned ah3 = Ah[st][tg+4][m+8];
            if (SPLIT) {
                unsigned al0 = Al[st][tg  ][m];
                unsigned al1 = Al[st][tg  ][m+8];
                unsigned al2 = Al[st][tg+4][m];
                unsigned al3 = Al[st][tg+4][m+8];
                #pragma unroll
                for (int nt = 0; nt < 4; nt++) {
                    mma_bf16(acc[mt][nt], ah0, ah1, ah2, ah3, bh0[nt], bh1[nt]);
                    mma_bf16(acc[mt][nt], ah0, ah1, ah2, ah3, bl0[nt], bl1[nt]);
                    mma_bf16(acc[mt][nt], al0, al1, al2, al3, bh0[nt], bh1[nt]);
                }
            } else {
                #pragma unroll
                for (int nt = 0; nt < 4; nt++) {
                    if (F16) mma_f16(acc[mt][nt], ah0, ah1, ah2, ah3, bh0[nt], bh1[nt]);
                    else     mma_bf16(acc[mt][nt], ah0, ah1, ah2, ah3, bh0[nt], bh1[nt]);
                }
            }
        }
        if (c + 1 < nchunks) { STORE_PK(st ^ 1) }
        __syncthreads();
    }
    #undef LOAD_PK
    #undef STORE_PK

    #pragma unroll
    for (int mt = 0; mt < 4; mt++) {
        #pragma unroll
        for (int nt = 0; nt < 4; nt++) {
            int r0 = m0 + m_w + mt*16 + g;
            int r1 = r0 + 8;
            int c  = n0 + n_w + nt*8 + 2*tg;
            float cb0 = (colBias && c   < N) ? colBias[c]   : 0.f;
            float cb1 = (colBias && c+1 < N) ? colBias[c+1] : 0.f;
            if (r0 < M) {
                if (c   < N) Cb[(long long)r0*ldc + c]   = acc[mt][nt][0] + cb0;
                if (c+1 < N) Cb[(long long)r0*ldc + c+1] = acc[mt][nt][1] + cb1;
            }
            if (r1 < M) {
                if (c   < N) Cb[(long long)r1*ldc + c]   = acc[mt][nt][2] + cb0;
                if (c+1 < N) Cb[(long long)r1*ldc + c+1] = acc[mt][nt][3] + cb1;
            }
        }
    }
}

// ---------------- masked softmax -> Am (d_out) ---------------------------------
__global__ void softmax_kernel(float* __restrict__ Am)
{
    int row = blockIdx.x;
    const float* Ar = g_ATi + (size_t)row * LL;
    const float* Tr = g_ATi + (size_t)B_*LL*LL + (size_t)row * LL;
    const float bl = g_bsum[row % LL];
    int t = threadIdx.x;
    const float scale = 0.07142857142857142f;
    float v[4], mb[4];
    float mx = -INFINITY;
    #pragma unroll
    for (int i = 0; i < 4; i++) {
        int m = t + i*NTHREADS;
        v[i] = 0.f; mb[i] = 0.f;
        if (m < LL) {
            float mask = sigmoid_ref(Tr[m] + bl);
            v[i] = Ar[m] * mask * scale;
            mb[i] = (mask != 0.f) ? 1.f : 0.f;
            mx = fmaxf(mx, v[i]);
        }
    }
    __shared__ float red[NTHREADS];
    red[t] = mx; __syncthreads();
    for (int s = NTHREADS/2; s > 0; s >>= 1) {
        if (t < s) red[t] = fmaxf(red[t], red[t+s]);
        __syncthreads();
    }
    mx = red[0]; __syncthreads();
    float e[4]; float sum = 0.f;
    #pragma unroll
    for (int i = 0; i < 4; i++) {
        int m = t + i*NTHREADS;
        if (m < LL) { e[i] = expf(v[i] - mx); sum += e[i]; } else e[i] = 0.f;
    }
    red[t] = sum; __syncthreads();
    for (int s = NTHREADS/2; s > 0; s >>= 1) {
        if (t < s) red[t] += red[t+s];
        __syncthreads();
    }
    float inv = 1.f / red[0];
    #pragma unroll
    for (int i = 0; i < 4; i++) {
        int m = t + i*NTHREADS;
        if (m < LL) Am[(size_t)row*LL + m] = e[i] * inv * mb[i];
    }
}

// ---------------- fold (gather form) --------------------------------------------
__global__ void fold_kernel()
{
    size_t t = (size_t)blockIdx.x * NTHREADS + threadIdx.x;
    if (t >= (size_t)B_*CIN*Hh*Ww) return;
    int w = (int)(t % Ww); size_t r = t / Ww;
    int h = (int)(r % Hh); r /= Hh;
    int c = (int)(r % CIN);
    int b = (int)(r / CIN);
    int i0 = (h > 6) ? (h - 3) >> 2 : 0;
    int i1 = h >> 2; if (i1 > NHH - 1) i1 = NHH - 1;
    int j0 = (w > 6) ? (w - 3) >> 2 : 0;
    int j1 = w >> 2; if (j1 > NHH - 1) j1 = NHH - 1;
    float s = 0.f;
    for (int i = i0; i <= i1; i++) {
        int kh = h - i*4;
        for (int j = j0; j <= j1; j++) {
            int kw = w - j*4;
            s += g_y[((size_t)b*LL + i*NHH + j)*FV + c*49 + kh*7 + kw];
        }
    }
    g_fold[t] = s;
}

// ---------------- conv c1 ---------------------------------------------------------
__global__ void conv3x3_c1_kernel(const float* __restrict__ w1)
{
    __shared__ float sw[CI*CIN*9];
    int t = threadIdx.x;
    for (int i = t; i < CI*CIN*9; i += NTHREADS) sw[i] = w1[i];
    __syncthreads();
    int pix = blockIdx.x * NTHREADS + t;
    int b = blockIdx.y;
    int h = pix >> 7, w = pix & 127;
    float acc[CI];
    #pragma unroll
    for (int co = 0; co < CI; co++) acc[co] = 0.f;
    const float* xb = g_fold + (size_t)b * CIN * Hh * Ww;
    for (int ci = 0; ci < CIN; ci++) {
        float v[9];
        #pragma unroll
        for (int dh = 0; dh < 3; dh++) {
            int hh = h + dh - 1;
            hh = hh < 0 ? 1 : (hh >= Hh ? Hh - 2 : hh);
            #pragma unroll
            for (int dw = 0; dw < 3; dw++) {
                int w2p = w + dw - 1;
                w2p = w2p < 0 ? 1 : (w2p >= Ww ? Ww - 2 : w2p);
                v[dh*3 + dw] = xb[(ci*Hh + hh)*Ww + w2p];
            }
        }
        #pragma unroll
        for (int co = 0; co < CI; co++) {
            const float* p1 = &sw[(co*CIN + ci)*9];
            float s1 = 0.f;
            #pragma unroll
            for (int k = 0; k < 9; k++) s1 += p1[k]*v[k];
            acc[co] += s1;
        }
    }
    size_t base = (size_t)b * CI * Hh * Ww + pix;
    #pragma unroll
    for (int co = 0; co < CI; co++) {
        float s = acc[co];
        g_o1[base + (size_t)co*Hh*Ww] = (s > 0.f) ? s : 0.2f*s;
    }
}

// ---------------- conv c2 + residual ----------------------------------------------
__global__ void conv1x1_c2_res_kernel(const float* __restrict__ cw,
                                      const float* __restrict__ x,
                                      float* __restrict__ outp)
{
    __shared__ float sw[CIN*CI];
    int t = threadIdx.x;
    for (int i = t; i < CIN*CI; i += NTHREADS) sw[i] = cw[i];
    __syncthreads();
    int pix = blockIdx.x * NTHREADS + t;
    int b = blockIdx.y;
    float in[CI];
    #pragma unroll
    for (int ci = 0; ci < CI; ci++) in[ci] = g_o1[((size_t)b*CI + ci)*Hh*Ww + pix];
    #pragma unroll
    for (int co = 0; co < CIN; co++) {
        float s = 0.f;
        #pragma unroll
        for (int ci = 0; ci < CI; ci++) s += sw[co*CI + ci]*in[ci];
        s = (s > 0.f) ? s : 0.2f*s;
        size_t idx = ((size_t)b*CIN + co)*Hh*Ww + pix;
        outp[idx] = x[idx] + s;
    }
}

// ---------------- launch -----------------------------------------------------------
extern "C" void kernel_launch(void* const* d_in, const int* in_sizes, int n_in,
                              void* d_out, int out_size)
{
    const float* x        = (const float*)d_in[0];
    const float* g_w      = (const float*)d_in[1];
    const float* g_b      = (const float*)d_in[2];
    const float* w_w      = (const float*)d_in[3];
    const float* w_b      = (const float*)d_in[4];
    const float* theta_w  = (const float*)d_in[5];
    const float* theta_b  = (const float*)d_in[6];
    const float* fc1_w    = (const float*)d_in[7];
    const float* fc1_b    = (const float*)d_in[8];
    const float* mconv_w  = (const float*)d_in[9];
    const float* mconv_b  = (const float*)d_in[10];
    const float* mfc_w    = (const float*)d_in[11];
    const float* mfc_b    = (const float*)d_in[12];
    const float* c1_w     = (const float*)d_in[13];
    const float* c2_w     = (const float*)d_in[14];
    float* out = (float*)d_out;

    float *px1, *px2, *pwf, *pxf, *pW2, *pATi, *py;
    unsigned *pp4h, *pp4l, *pp6h, *pp6l, *pfc1h, *pfc1l,
             *pawh, *pawl, *pxfh, *pxfl, *pwvh, *pwvl, *pmsh, *pmsl,
             *pamf, *pptf;
    cudaGetSymbolAddress((void**)&px1,  g_x1);
    cudaGetSymbolAddress((void**)&px2,  g_x2);
    cudaGetSymbolAddress((void**)&pwf,  g_wf);
    cudaGetSymbolAddress((void**)&pxf,  g_xf);
    cudaGetSymbolAddress((void**)&pW2,  g_W2);
    cudaGetSymbolAddress((void**)&pATi, g_ATi);
    cudaGetSymbolAddress((void**)&py,   g_y);
    cudaGetSymbolAddress((void**)&pp4h, g_p4h);
    cudaGetSymbolAddress((void**)&pp4l, g_p4l);
    cudaGetSymbolAddress((void**)&pp6h, g_p6h);
    cudaGetSymbolAddress((void**)&pp6l, g_p6l);
    cudaGetSymbolAddress((void**)&pfc1h,g_fc1h);
    cudaGetSymbolAddress((void**)&pfc1l,g_fc1l);
    cudaGetSymbolAddress((void**)&pawh, g_awh);
    cudaGetSymbolAddress((void**)&pawl, g_awl);
    cudaGetSymbolAddress((void**)&pxfh, g_xfh);
    cudaGetSymbolAddress((void**)&pxfl, g_xfl);
    cudaGetSymbolAddress((void**)&pwvh, g_wvh);
    cudaGetSymbolAddress((void**)&pwvl, g_wvl);
    cudaGetSymbolAddress((void**)&pmsh, g_msh);
    cudaGetSymbolAddress((void**)&pmsl, g_msl);
    cudaGetSymbolAddress((void**)&pamf, g_amf);
    cudaGetSymbolAddress((void**)&pptf, g_ptf);

    dim3 convGrid(Hh*Ww/NTHREADS, B_);
    #define GBLK(n) ((int)(((size_t)(n) + NTHREADS - 1) / NTHREADS))

    conv3x3_dual_kernel<<<convGrid, NTHREADS>>>(x, g_w, g_b, w_w, w_b);
    conv1x1_theta_kernel<<<convGrid, NTHREADS>>>(theta_w, theta_b);

    unfold_pk_kernel<<<GBLK((size_t)B_*LL*KP2_FIN), NTHREADS>>>(px2, pp4h, pp4l);
    unfold_pk_kernel<<<GBLK((size_t)B_*LL*KP2_FIN), NTHREADS>>>(px1, pp6h, pp6l);
    unfold_p62t_f16_kernel<<<GBLK((size_t)B_*FV*KP2_Y), NTHREADS>>>();

    msum_pk_kernel<<<GBLK((size_t)LL*KP2_LL), NTHREADS>>>(mconv_w, mfc_w, mconv_b, mfc_b);
    pack_row_kernel<<<GBLK((size_t)FOUT*KP2_FIN), NTHREADS>>>(fc1_w, pfc1h, pfc1l,
                                                              FOUT, FIN, KP2_FIN, FIN);

    // wf / xf (bf16x3)
    {
        dim3 g((FOUT + 127)/128, (B_*LL + 127)/128, 1);
        gemm_pk_kernel<false,false,true,false><<<g, 256>>>(pp4h, pp4l, pfc1h, pfc1l, pwf,
                                                           B_*LL, FOUT, FIN/16,
                                                           KP2_FIN, KP2_FIN, FOUT,
                                                           0, 0, 0, fc1_b);
        gemm_pk_kernel<false,false,true,false><<<g, 256>>>(pp6h, pp6l, pfc1h, pfc1l, pxf,
                                                           B_*LL, FOUT, FIN/16,
                                                           KP2_FIN, KP2_FIN, FOUT,
                                                           0, 0, 0, fc1_b);
    }

    pack_row_kernel<<<GBLK((size_t)B_*LL*KP2_FOUT), NTHREADS>>>(pwf, pawh, pawl,
                                                                B_*LL, FOUT, KP2_FOUT, FOUT);
    pack_row_kernel<<<GBLK((size_t)B_*LL*KP2_FOUT), NTHREADS>>>(pxf, pxfh, pxfl,
                                                                B_*LL, FOUT, KP2_FOUT, FOUT);
    pack_vert_kernel<<<GBLK((size_t)B_*KP2_LL*NPAD_VERT), NTHREADS>>>(pwf);

    // W2[b] = Msum ⊗ wf[b]  (bf16x3)
    {
        dim3 g((FOUT + 127)/128, (LL + 127)/128, B_);
        gemm_pk_kernel<true,false,true,false><<<g, 256>>>(pmsh, pmsl, pwvh, pwvl, pW2,
                                                          LL, FOUT, 61,
                                                          KP2_LL, NPAD_VERT, FOUT,
                                                          0, (long long)KP2_LL*NPAD_VERT,
                                                          (long long)LL*FOUT, nullptr);
    }
    pack_row_kernel<<<GBLK((size_t)B_*LL*KP2_FOUT), NTHREADS>>>(pW2,
        pawh + (size_t)B_*LL*KP2_FOUT, pawl + (size_t)B_*LL*KP2_FOUT,
        B_*LL, FOUT, KP2_FOUT, FOUT);

    // Batched A / Ti (bf16x3)
    {
        dim3 g((LL + 127)/128, (LL + 127)/128, 2*B_);
        gemm_pk_kernel<false,true,true,false><<<g, 256>>>(pawh, pawl, pxfh, pxfl, pATi,
                                                          LL, LL, 13,
                                                          KP2_FOUT, KP2_FOUT, LL,
                                                          (long long)LL*KP2_FOUT,
                                                          (long long)LL*KP2_FOUT,
                                                          (long long)LL*LL, nullptr);
    }

    softmax_kernel<<<B_*LL, NTHREADS>>>(out);
    pack_am_f16_kernel<<<GBLK((size_t)B_*LL*KP2_Y), NTHREADS>>>(out);

    // y[b] = Am[b] @ p62[b]  — single-pass fp16 k16 mma (tf32-level accuracy)
    {
        dim3 g((FV + 127)/128, (LL + 127)/128, B_);
        gemm_pk_kernel<false,false,false,true><<<g, 256>>>(pamf, nullptr, pptf, nullptr, py,
                                                           LL, FV, 61,
                                                           KP2_Y, KP2_Y, FV,
                                                           (long long)LL*KP2_Y,
                                                           (long long)FV*KP2_Y,
                                                           (long long)LL*FV, nullptr);
    }

    fold_kernel<<<GBLK((size_t)B_*CIN*Hh*Ww), NTHREADS>>>();
    conv3x3_c1_kernel<<<convGrid, NTHREADS>>>(c1_w);
    conv1x1_c2_res_kernel<<<convGrid, NTHREADS>>>(c2_w, x, out + (size_t)B_*LL*LL);
    #undef GBLK
}

// round 13
// speedup vs baseline: 2.4683x; 1.0252x over previous
#include <cuda_runtime.h>
#include <cstdint>
#include <math.h>
#include <float.h>

#define B_   8
#define CIN  32
#define CI   16
#define Hh   128
#define Ww   128
#define NHH  31
#define LL   961
#define FIN  784
#define FOUT 196
#define FV   1568
#define NTHREADS 256

#define KP2_FIN   392
#define KP2_FOUT  104
#define KP2_LL    488
#define NPAD_VERT 256
#define KP2_Y     488

// ---------------- scratch (device globals) ------------------------------------
__device__ float    g_x1[(size_t)B_*CI*Hh*Ww];
__device__ float    g_x2[(size_t)B_*CI*Hh*Ww];
__device__ float    g_x3[(size_t)B_*CIN*Hh*Ww];
__device__ unsigned g_p4h[(size_t)B_*LL*KP2_FIN], g_p4l[(size_t)B_*LL*KP2_FIN];
__device__ unsigned g_p6h[(size_t)B_*LL*KP2_FIN], g_p6l[(size_t)B_*LL*KP2_FIN];
__device__ unsigned g_fc1h[(size_t)FOUT*KP2_FIN], g_fc1l[(size_t)FOUT*KP2_FIN];
__device__ float    g_wf[(size_t)B_*LL*FOUT];
__device__ unsigned g_awh[(size_t)2*B_*LL*KP2_FOUT], g_awl[(size_t)2*B_*LL*KP2_FOUT];
__device__ unsigned g_xfh[(size_t)B_*LL*KP2_FOUT],   g_xfl[(size_t)B_*LL*KP2_FOUT];
__device__ unsigned g_wvh[(size_t)B_*KP2_LL*NPAD_VERT], g_wvl[(size_t)B_*KP2_LL*NPAD_VERT];
__device__ unsigned g_msh[(size_t)LL*KP2_LL], g_msl[(size_t)LL*KP2_LL];
__device__ float    g_bsum[LL];
__device__ float    g_ATi[(size_t)2*B_*LL*LL];
__device__ unsigned g_amf[(size_t)B_*LL*KP2_Y];
__device__ unsigned g_ptf[(size_t)B_*FV*KP2_Y];
__device__ float    g_y[(size_t)B_*LL*FV];
__device__ float    g_fold[(size_t)B_*CIN*Hh*Ww];
__device__ float    g_o1[(size_t)B_*CI*Hh*Ww];

static __device__ __forceinline__ float sigmoid_ref(float x) {
    if (x >= 0.f) return 1.f / (1.f + expf(-x));
    float e = expf(x);
    if (e < FLT_MIN) e = 0.f;
    return e / (1.f + e);
}

// =================== pack / mma helpers ========================================
__device__ __forceinline__ unsigned packbf(float x, float y) {
    unsigned r;
    asm("cvt.rn.bf16x2.f32 %0, %1, %2;" : "=r"(r) : "f"(y), "f"(x));
    return r;
}
__device__ __forceinline__ unsigned packf16(float x, float y) {
    unsigned r;
    asm("cvt.rn.f16x2.f32 %0, %1, %2;" : "=r"(r) : "f"(y), "f"(x));
    return r;
}
__device__ __forceinline__ void split2(float x, float y, unsigned& hi, unsigned& lo) {
    hi = packbf(x, y);
    float hx = __uint_as_float(hi << 16);
    float hy = __uint_as_float(hi & 0xFFFF0000u);
    lo = packbf(x - hx, y - hy);
}
__device__ __forceinline__ void mma_bf16(float c[4],
    unsigned a0, unsigned a1, unsigned a2, unsigned a3, unsigned b0, unsigned b1)
{
    asm volatile("mma.sync.aligned.m16n8k16.row.col.f32.bf16.bf16.f32 "
        "{%0,%1,%2,%3}, {%4,%5,%6,%7}, {%8,%9}, {%0,%1,%2,%3};"
        : "+f"(c[0]), "+f"(c[1]), "+f"(c[2]), "+f"(c[3])
        : "r"(a0), "r"(a1), "r"(a2), "r"(a3), "r"(b0), "r"(b1));
}
__device__ __forceinline__ void mma_f16(float c[4],
    unsigned a0, unsigned a1, unsigned a2, unsigned a3, unsigned b0, unsigned b1)
{
    asm volatile("mma.sync.aligned.m16n8k16.row.col.f32.f16.f16.f32 "
        "{%0,%1,%2,%3}, {%4,%5,%6,%7}, {%8,%9}, {%0,%1,%2,%3};"
        : "+f"(c[0]), "+f"(c[1]), "+f"(c[2]), "+f"(c[3])
        : "r"(a0), "r"(a1), "r"(a2), "r"(a3), "r"(b0), "r"(b1));
}

// ---------------- conv: refpad 3x3, 32->16 twice ------------------------------
__global__ void conv3x3_dual_kernel(const float* __restrict__ x,
                                    const float* __restrict__ w1, const float* __restrict__ b1,
                                    const float* __restrict__ w2, const float* __restrict__ b2)
{
    __shared__ float sw1[CI*CIN*9];
    __shared__ float sw2[CI*CIN*9];
    int t = threadIdx.x;
    for (int i = t; i < CI*CIN*9; i += NTHREADS) { sw1[i] = w1[i]; sw2[i] = w2[i]; }
    __syncthreads();
    int pix = blockIdx.x * NTHREADS + t;
    int b = blockIdx.y;
    int h = pix >> 7, w = pix & 127;
    float acc1[CI], acc2[CI];
    #pragma unroll
    for (int co = 0; co < CI; co++) { acc1[co] = b1[co]; acc2[co] = b2[co]; }
    const float* xb = x + (size_t)b * CIN * Hh * Ww;
    for (int ci = 0; ci < CIN; ci++) {
        float v[9];
        #pragma unroll
        for (int dh = 0; dh < 3; dh++) {
            int hh = h + dh - 1;
            hh = hh < 0 ? 1 : (hh >= Hh ? Hh - 2 : hh);
            #pragma unroll
            for (int dw = 0; dw < 3; dw++) {
                int w2p = w + dw - 1;
                w2p = w2p < 0 ? 1 : (w2p >= Ww ? Ww - 2 : w2p);
                v[dh*3 + dw] = xb[(ci*Hh + hh)*Ww + w2p];
            }
        }
        #pragma unroll
        for (int co = 0; co < CI; co++) {
            const float* p1 = &sw1[(co*CIN + ci)*9];
            const float* p2 = &sw2[(co*CIN + ci)*9];
            float s1 = 0.f, s2 = 0.f;
            #pragma unroll
            for (int k = 0; k < 9; k++) { s1 += p1[k]*v[k]; s2 += p2[k]*v[k]; }
            acc1[co] += s1; acc2[co] += s2;
        }
    }
    size_t base = (size_t)b * CI * Hh * Ww + pix;
    #pragma unroll
    for (int co = 0; co < CI; co++) {
        g_x1[base + (size_t)co*Hh*Ww] = acc1[co];
        g_x2[base + (size_t)co*Hh*Ww] = acc2[co];
    }
}

// ---------------- conv: 1x1 theta ---------------------------------------------
__global__ void conv1x1_theta_kernel(const float* __restrict__ tw, const float* __restrict__ tb)
{
    __shared__ float sw[CIN*CI];
    int t = threadIdx.x;
    for (int i = t; i < CIN*CI; i += NTHREADS) sw[i] = tw[i];
    __syncthreads();
    int pix = blockIdx.x * NTHREADS + t;
    int b = blockIdx.y;
    float in[CI];
    #pragma unroll
    for (int ci = 0; ci < CI; ci++) in[ci] = g_x1[((size_t)b*CI + ci)*Hh*Ww + pix];
    #pragma unroll
    for (int co = 0; co < CIN; co++) {
        float s = tb[co];
        #pragma unroll
        for (int ci = 0; ci < CI; ci++) s += sw[co*CI + ci]*in[ci];
        g_x3[((size_t)b*CIN + co)*Hh*Ww + pix] = s;
    }
}

// ---------------- unfold + split-pack (p4/p6; C=16) ---------------------------
__global__ void unfold_pk_kernel(const float* __restrict__ src,
                                 unsigned* __restrict__ dsth, unsigned* __restrict__ dstl)
{
    size_t t = (size_t)blockIdx.x * NTHREADS + threadIdx.x;
    if (t >= (size_t)B_*LL*KP2_FIN) return;
    int j = (int)(t % KP2_FIN);
    size_t r = t / KP2_FIN;
    int l = (int)(r % LL);
    int b = (int)(r / LL);
    float v[2];
    #pragma unroll
    for (int i = 0; i < 2; i++) {
        int f = 2*j + i;
        int c = f / 49, rr = f % 49, kh = rr / 7, kw = rr % 7;
        int h = (l / NHH)*4 + kh, w = (l % NHH)*4 + kw;
        v[i] = src[(((size_t)b*CI + c)*Hh + h)*Ww + w];
    }
    unsigned hi, lo;
    split2(v[0], v[1], hi, lo);
    dsth[t] = hi; dstl[t] = lo;
}

// ---------------- p62^T fp16 pack ----------------------------------------------
__global__ void unfold_p62t_f16_kernel()
{
    size_t t = (size_t)blockIdx.x * NTHREADS + threadIdx.x;
    if (t >= (size_t)B_*FV*KP2_Y) return;
    int j = (int)(t % KP2_Y);
    size_t r = t / KP2_Y;
    int f = (int)(r % FV);
    int b = (int)(r / FV);
    int c = f / 49, rr = f % 49, kh = rr / 7, kw = rr % 7;
    float v[2] = {0.f, 0.f};
    #pragma unroll
    for (int i = 0; i < 2; i++) {
        int l = 2*j + i;
        if (l < LL) {
            int h = (l / NHH)*4 + kh, w = (l % NHH)*4 + kw;
            v[i] = g_x3[(((size_t)b*CIN + c)*Hh + h)*Ww + w];
        }
    }
    g_ptf[t] = packf16(v[0], v[1]);
}

// ---------------- Am fp16 pack ---------------------------------------------------
__global__ void pack_am_f16_kernel(const float* __restrict__ Am)
{
    size_t t = (size_t)blockIdx.x * NTHREADS + threadIdx.x;
    if (t >= (size_t)B_*LL*KP2_Y) return;
    int j = (int)(t % KP2_Y);
    size_t row = t / KP2_Y;
    int l0 = 2*j, l1 = 2*j + 1;
    float v0 = (l0 < LL) ? Am[row*LL + l0] : 0.f;
    float v1 = (l1 < LL) ? Am[row*LL + l1] : 0.f;
    g_amf[t] = packf16(v0, v1);
}

// ---------------- Msum split-pack + bsum ---------------------------------------
__global__ void msum_pk_kernel(const float* __restrict__ mw1, const float* __restrict__ mw2,
                               const float* __restrict__ mb1, const float* __restrict__ mb2)
{
    size_t t = (size_t)blockIdx.x * NTHREADS + threadIdx.x;
    if (t < (size_t)LL*KP2_LL) {
        int j = (int)(t % KP2_LL);
        int n = (int)(t / KP2_LL);
        int c0 = 2*j, c1 = 2*j + 1;
        float v0 = (c0 < LL) ? mw1[(size_t)n*LL + c0] + mw2[(size_t)n*LL + c0] : 0.f;
        float v1 = (c1 < LL) ? mw1[(size_t)n*LL + c1] + mw2[(size_t)n*LL + c1] : 0.f;
        unsigned hi, lo;
        split2(v0, v1, hi, lo);
        g_msh[t] = hi; g_msl[t] = lo;
    }
    if (t < LL) g_bsum[t] = mb1[t] + mb2[t];
}

// ---------------- generic rowpack (fc1 only now) ---------------------------------
__global__ void pack_row_kernel(const float* __restrict__ src,
                                unsigned* __restrict__ dsth, unsigned* __restrict__ dstl,
                                int R, int K, int KP2, int lda)
{
    size_t t = (size_t)blockIdx.x * NTHREADS + threadIdx.x;
    if (t >= (size_t)R*KP2) return;
    int j = (int)(t % KP2);
    int r = (int)(t / KP2);
    int k0 = 2*j;
    float v0 = (k0     < K) ? src[(size_t)r*lda + k0]     : 0.f;
    float v1 = (k0 + 1 < K) ? src[(size_t)r*lda + k0 + 1] : 0.f;
    unsigned hi, lo;
    split2(v0, v1, hi, lo);
    dsth[t] = hi; dstl[t] = lo;
}

// ---------------- wf vertical pack ----------------------------------------------
__global__ void pack_vert_kernel(const float* __restrict__ wf)
{
    size_t t = (size_t)blockIdx.x * NTHREADS + threadIdx.x;
    if (t >= (size_t)B_*KP2_LL*NPAD_VERT) return;
    int n = (int)(t % NPAD_VERT);
    size_t r = t / NPAD_VERT;
    int kk = (int)(r % KP2_LL);
    int b  = (int)(r / KP2_LL);
    int l0 = 2*kk, l1 = 2*kk + 1;
    float v0 = 0.f, v1 = 0.f;
    if (n < FOUT) {
        const float* wb = wf + (size_t)b*LL*FOUT;
        if (l0 < LL) v0 = wb[(size_t)l0*FOUT + n];
        if (l1 < LL) v1 = wb[(size_t)l1*FOUT + n];
    }
    unsigned hi, lo;
    split2(v0, v1, hi, lo);
    g_wvh[t] = hi; g_wvl[t] = lo;
}

// ========= packed pair GEMM (bf16x3 split OR single-pass fp16) =================
// Pass-major mma ordering (hh,hl,lh outer) to break accumulator RAW chains.
// Optional fused pack epilogue: Ph/Pl (pair index j=c/2; pad pairs untouched).
template <bool BVERT, bool MODB, bool SPLIT, bool F16>
__global__ void __launch_bounds__(256, 2) gemm_pk_kernel(
    const unsigned* __restrict__ Ahg, const unsigned* __restrict__ Alg,
    const unsigned* __restrict__ Bhg, const unsigned* __restrict__ Blg,
    float* __restrict__ Cg,
    unsigned* __restrict__ Ph, unsigned* __restrict__ Pl,
    int M, int N, int nchunks,
    int lda2, int ldb2, int ldc, int ldp2,
    long long sA2, long long sB2, long long sC, long long sP,
    const float* __restrict__ colBias)
{
    __shared__ unsigned Ah[2][8][136];
    __shared__ unsigned Bh[2][8][136];
    __shared__ unsigned Al[SPLIT ? 2 : 1][SPLIT ? 8 : 1][SPLIT ? 136 : 1];
    __shared__ unsigned Bl[SPLIT ? 2 : 1][SPLIT ? 8 : 1][SPLIT ? 136 : 1];

    const int tid = threadIdx.x;
    const int wid = tid >> 5, lane = tid & 31;
    const int wm = wid >> 2, wn = wid & 3;
    const int m_w = wm * 64, n_w = wn * 32;
    const int g = lane >> 2, tg = lane & 3;
    const int m0 = blockIdx.y * 128, n0 = blockIdx.x * 128;
    const unsigned* Ahb = Ahg + (long long)blockIdx.z * sA2;
    const unsigned* Alb = SPLIT ? (Alg + (long long)blockIdx.z * sA2) : Ahg;
    const long long zb = (long long)(MODB ? (blockIdx.z & 7) : blockIdx.z) * sB2;
    const unsigned* Bhb = Bhg + zb;
    const unsigned* Blb = SPLIT ? (Blg + zb) : Bhg;
    float* Cb = Cg ? (Cg + (long long)blockIdx.z * sC) : nullptr;

    float acc[4][4][4];
    #pragma unroll
    for (int i = 0; i < 4; i++)
        #pragma unroll
        for (int j = 0; j < 4; j++)
            #pragma unroll
            for (int q = 0; q < 4; q++) acc[i][j][q] = 0.f;

    const int a_c = (tid & 3) * 2;
    const int a_r = tid >> 2;
    const int bn_q = (tid & 31) * 4;
    const int bk_r = tid >> 5;

    uint2 vah[2], val[2], vbh[2], vbl[2];
    uint4 bvh, bvl;

    #define LOAD_PK(p0)                                                        \
        _Pragma("unroll")                                                      \
        for (int i = 0; i < 2; i++) {                                          \
            int gm = m0 + a_r + 64*i;                                          \
            if (gm < M) {                                                      \
                long long idx = (long long)gm*lda2 + (p0) + a_c;               \
                vah[i] = *(const uint2*)(Ahb + idx);                           \
                if (SPLIT) val[i] = *(const uint2*)(Alb + idx);                \
            } else { vah[i] = make_uint2(0,0); val[i] = make_uint2(0,0); }     \
        }                                                                      \
        if (!BVERT) {                                                          \
            _Pragma("unroll")                                                  \
            for (int i = 0; i < 2; i++) {                                      \
                int gn = n0 + a_r + 64*i;                                      \
                if (gn < N) {                                                  \
                    long long idx = (long long)gn*ldb2 + (p0) + a_c;           \
                    vbh[i] = *(const uint2*)(Bhb + idx);                       \
                    if (SPLIT) vbl[i] = *(const uint2*)(Blb + idx);            \
                } else { vbh[i] = make_uint2(0,0); vbl[i] = make_uint2(0,0); } \
            }                                                                  \
        } else {                                                               \
            long long idx = (long long)((p0) + bk_r)*ldb2 + n0 + bn_q;         \
            bvh = *(const uint4*)(Bhb + idx);                                  \
            if (SPLIT) bvl = *(const uint4*)(Blb + idx);                       \
        }
    #define STORE_PK(st)                                                       \
        _Pragma("unroll")                                                      \
        for (int i = 0; i < 2; i++) {                                          \
            int m = a_r + 64*i;                                                \
            Ah[st][a_c  ][m] = vah[i].x;  Ah[st][a_c+1][m] = vah[i].y;         \
            if (SPLIT) { Al[st][a_c  ][m] = val[i].x;                          \
                         Al[st][a_c+1][m] = val[i].y; }                        \
        }                                                                      \
        if (!BVERT) {                                                          \
            _Pragma("unroll")                                                  \
            for (int i = 0; i < 2; i++) {                                      \
                int n = a_r + 64*i;                                            \
                Bh[st][a_c  ][n] = vbh[i].x;  Bh[st][a_c+1][n] = vbh[i].y;     \
                if (SPLIT) { Bl[st][a_c  ][n] = vbl[i].x;                      \
                             Bl[st][a_c+1][n] = vbl[i].y; }                    \
            }                                                                  \
        } else {                                                               \
            *(uint4*)&Bh[st][bk_r][bn_q] = bvh;                                \
            if (SPLIT) { *(uint4*)&Bl[st][bk_r][bn_q] = bvl; }                 \
        }

    LOAD_PK(0)
    STORE_PK(0)
    __syncthreads();

    for (int c = 0; c < nchunks; c++) {
        const int st = c & 1;
        if (c + 1 < nchunks) { LOAD_PK((c+1)*8) }
        unsigned bh0[4], bh1[4], bl0[4], bl1[4];
        #pragma unroll
        for (int nt = 0; nt < 4; nt++) {
            int n = n_w + nt*8 + g;
            bh0[nt] = Bh[st][tg  ][n];
            bh1[nt] = Bh[st][tg+4][n];
            if (SPLIT) {
                bl0[nt] = Bl[st][tg  ][n];
                bl1[nt] = Bl[st][tg+4][n];
            }
        }
        #pragma unroll
        for (int mt = 0; mt < 4; mt++) {
            int m = m_w + mt*16 + g;
            unsigned ah0 = Ah[st][tg  ][m];
            unsigned ah1 = Ah[st][tg  ][m+8];
            unsigned ah2 = Ah[st][tg+4][m];
            unsigned ah3 = Ah[st][tg+4][m+8];
            if (SPLIT) {
                unsigned al0 = Al[st][tg  ][m];
                unsigned al1 = Al[st][tg  ][m+8];
                unsigned al2 = Al[st][tg+4][m];
                unsigned al3 = Al[st][tg+4][m+8];
                // pass-major: consecutive mma hit different accumulators
                #pragma unroll
                for (int nt = 0; nt < 4; nt++)
                    mma_bf16(acc[mt][nt], ah0, ah1, ah2, ah3, bh0[nt], bh1[nt]);
                #pragma unroll
                for (int nt = 0; nt < 4; nt++)
                    mma_bf16(acc[mt][nt], ah0, ah1, ah2, ah3, bl0[nt], bl1[nt]);
                #pragma unroll
                for (int nt = 0; nt < 4; nt++)
                    mma_bf16(acc[mt][nt], al0, al1, al2, al3, bh0[nt], bh1[nt]);
            } else {
                #pragma unroll
                for (int nt = 0; nt < 4; nt++) {
                    if (F16) mma_f16(acc[mt][nt], ah0, ah1, ah2, ah3, bh0[nt], bh1[nt]);
                    else     mma_bf16(acc[mt][nt], ah0, ah1, ah2, ah3, bh0[nt], bh1[nt]);
                }
            }
        }
        if (c + 1 < nchunks) { STORE_PK(st ^ 1) }
        __syncthreads();
    }
    #undef LOAD_PK
    #undef STORE_PK

    unsigned* Phb = Ph ? (Ph + (long long)blockIdx.z * sP) : nullptr;
    unsigned* Plb = Pl ? (Pl + (long long)blockIdx.z * sP) : nullptr;

    #pragma unroll
    for (int mt = 0; mt < 4; mt++) {
        #pragma unroll
        for (int nt = 0; nt < 4; nt++) {
            int r0 = m0 + m_w + mt*16 + g;
            int r1 = r0 + 8;
            int c  = n0 + n_w + nt*8 + 2*tg;
            float cb0 = (colBias && c   < N) ? colBias[c]   : 0.f;
            float cb1 = (colBias && c+1 < N) ? colBias[c+1] : 0.f;
            float v00 = acc[mt][nt][0] + cb0, v01 = acc[mt][nt][1] + cb1;
            float v10 = acc[mt][nt][2] + cb0, v11 = acc[mt][nt][3] + cb1;
            if (Cb) {
                if (r0 < M) {
                    if (c   < N) Cb[(long long)r0*ldc + c]   = v00;
                    if (c+1 < N) Cb[(long long)r0*ldc + c+1] = v01;
                }
                if (r1 < M) {
                    if (c   < N) Cb[(long long)r1*ldc + c]   = v10;
                    if (c+1 < N) Cb[(long long)r1*ldc + c+1] = v11;
                }
            }
            if (Phb && c + 1 < N) {          // full pair only (N even)
                int j = c >> 1;
                unsigned h, l;
                if (r0 < M) {
                    split2(v00, v01, h, l);
                    Phb[(long long)r0*ldp2 + j] = h;
                    Plb[(long long)r0*ldp2 + j] = l;
                }
                if (r1 < M) {
                    split2(v10, v11, h, l);
                    Phb[(long long)r1*ldp2 + j] = h;
                    Plb[(long long)r1*ldp2 + j] = l;
                }
            }
        }
    }
}

// ---------------- masked softmax -> Am (d_out) ---------------------------------
__global__ void softmax_kernel(float* __restrict__ Am)
{
    int row = blockIdx.x;
    const float* Ar = g_ATi + (size_t)row * LL;
    const float* Tr = g_ATi + (size_t)B_*LL*LL + (size_t)row * LL;
    const float bl = g_bsum[row % LL];
    int t = threadIdx.x;
    const float scale = 0.07142857142857142f;
    float v[4], mb[4];
    float mx = -INFINITY;
    #pragma unroll
    for (int i = 0; i < 4; i++) {
        int m = t + i*NTHREADS;
        v[i] = 0.f; mb[i] = 0.f;
        if (m < LL) {
            float mask = sigmoid_ref(Tr[m] + bl);
            v[i] = Ar[m] * mask * scale;
            mb[i] = (mask != 0.f) ? 1.f : 0.f;
            mx = fmaxf(mx, v[i]);
        }
    }
    __shared__ float red[NTHREADS];
    red[t] = mx; __syncthreads();
    for (int s = NTHREADS/2; s > 0; s >>= 1) {
        if (t < s) red[t] = fmaxf(red[t], red[t+s]);
        __syncthreads();
    }
    mx = red[0]; __syncthreads();
    float e[4]; float sum = 0.f;
    #pragma unroll
    for (int i = 0; i < 4; i++) {
        int m = t + i*NTHREADS;
        if (m < LL) { e[i] = expf(v[i] - mx); sum += e[i]; } else e[i] = 0.f;
    }
    red[t] = sum; __syncthreads();
    for (int s = NTHREADS/2; s > 0; s >>= 1) {
        if (t < s) red[t] += red[t+s];
        __syncthreads();
    }
    float inv = 1.f / red[0];
    #pragma unroll
    for (int i = 0; i < 4; i++) {
        int m = t + i*NTHREADS;
        if (m < LL) Am[(size_t)row*LL + m] = e[i] * inv * mb[i];
    }
}

// ---------------- fold (gather form) --------------------------------------------
__global__ void fold_kernel()
{
    size_t t = (size_t)blockIdx.x * NTHREADS + threadIdx.x;
    if (t >= (size_t)B_*CIN*Hh*Ww) return;
    int w = (int)(t % Ww); size_t r = t / Ww;
    int h = (int)(r % Hh); r /= Hh;
    int c = (int)(r % CIN);
    int b = (int)(r / CIN);
    int i0 = (h > 6) ? (h - 3) >> 2 : 0;
    int i1 = h >> 2; if (i1 > NHH - 1) i1 = NHH - 1;
    int j0 = (w > 6) ? (w - 3) >> 2 : 0;
    int j1 = w >> 2; if (j1 > NHH - 1) j1 = NHH - 1;
    float s = 0.f;
    for (int i = i0; i <= i1; i++) {
        int kh = h - i*4;
        for (int j = j0; j <= j1; j++) {
            int kw = w - j*4;
            s += g_y[((size_t)b*LL + i*NHH + j)*FV + c*49 + kh*7 + kw];
        }
    }
    g_fold[t] = s;
}

// ---------------- conv c1 ---------------------------------------------------------
__global__ void conv3x3_c1_kernel(const float* __restrict__ w1)
{
    __shared__ float sw[CI*CIN*9];
    int t = threadIdx.x;
    for (int i = t; i < CI*CIN*9; i += NTHREADS) sw[i] = w1[i];
    __syncthreads();
    int pix = blockIdx.x * NTHREADS + t;
    int b = blockIdx.y;
    int h = pix >> 7, w = pix & 127;
    float acc[CI];
    #pragma unroll
    for (int co = 0; co < CI; co++) acc[co] = 0.f;
    const float* xb = g_fold + (size_t)b * CIN * Hh * Ww;
    for (int ci = 0; ci < CIN; ci++) {
        float v[9];
        #pragma unroll
        for (int dh = 0; dh < 3; dh++) {
            int hh = h + dh - 1;
            hh = hh < 0 ? 1 : (hh >= Hh ? Hh - 2 : hh);
            #pragma unroll
            for (int dw = 0; dw < 3; dw++) {
                int w2p = w + dw - 1;
                w2p = w2p < 0 ? 1 : (w2p >= Ww ? Ww - 2 : w2p);
                v[dh*3 + dw] = xb[(ci*Hh + hh)*Ww + w2p];
            }
        }
        #pragma unroll
        for (int co = 0; co < CI; co++) {
            const float* p1 = &sw[(co*CIN + ci)*9];
            float s1 = 0.f;
            #pragma unroll
            for (int k = 0; k < 9; k++) s1 += p1[k]*v[k];
            acc[co] += s1;
        }
    }
    size_t base = (size_t)b * CI * Hh * Ww + pix;
    #pragma unroll
    for (int co = 0; co < CI; co++) {
        float s = acc[co];
        g_o1[base + (size_t)co*Hh*Ww] = (s > 0.f) ? s : 0.2f*s;
    }
}

// ---------------- conv c2 + residual ----------------------------------------------
__global__ void conv1x1_c2_res_kernel(const float* __restrict__ cw,
                                      const float* __restrict__ x,
                                      float* __restrict__ outp)
{
    __shared__ float sw[CIN*CI];
    int t = threadIdx.x;
    for (int i = t; i < CIN*CI; i += NTHREADS) sw[i] = cw[i];
    __syncthreads();
    int pix = blockIdx.x * NTHREADS + t;
    int b = blockIdx.y;
    float in[CI];
    #pragma unroll
    for (int ci = 0; ci < CI; ci++) in[ci] = g_o1[((size_t)b*CI + ci)*Hh*Ww + pix];
    #pragma unroll
    for (int co = 0; co < CIN; co++) {
        float s = 0.f;
        #pragma unroll
        for (int ci = 0; ci < CI; ci++) s += sw[co*CI + ci]*in[ci];
        s = (s > 0.f) ? s : 0.2f*s;
        size_t idx = ((size_t)b*CIN + co)*Hh*Ww + pix;
        outp[idx] = x[idx] + s;
    }
}

// ---------------- launch -----------------------------------------------------------
extern "C" void kernel_launch(void* const* d_in, const int* in_sizes, int n_in,
                              void* d_out, int out_size)
{
    const float* x        = (const float*)d_in[0];
    const float* g_w      = (const float*)d_in[1];
    const float* g_b      = (const float*)d_in[2];
    const float* w_w      = (const float*)d_in[3];
    const float* w_b      = (const float*)d_in[4];
    const float* theta_w  = (const float*)d_in[5];
    const float* theta_b  = (const float*)d_in[6];
    const float* fc1_w    = (const float*)d_in[7];
    const float* fc1_b    = (const float*)d_in[8];
    const float* mconv_w  = (const float*)d_in[9];
    const float* mconv_b  = (const float*)d_in[10];
    const float* mfc_w    = (const float*)d_in[11];
    const float* mfc_b    = (const float*)d_in[12];
    const float* c1_w     = (const float*)d_in[13];
    const float* c2_w     = (const float*)d_in[14];
    float* out = (float*)d_out;

    float *px1, *px2, *pwf, *pATi, *py;
    unsigned *pp4h, *pp4l, *pp6h, *pp6l, *pfc1h, *pfc1l,
             *pawh, *pawl, *pxfh, *pxfl, *pwvh, *pwvl, *pmsh, *pmsl,
             *pamf, *pptf;
    cudaGetSymbolAddress((void**)&px1,  g_x1);
    cudaGetSymbolAddress((void**)&px2,  g_x2);
    cudaGetSymbolAddress((void**)&pwf,  g_wf);
    cudaGetSymbolAddress((void**)&pATi, g_ATi);
    cudaGetSymbolAddress((void**)&py,   g_y);
    cudaGetSymbolAddress((void**)&pp4h, g_p4h);
    cudaGetSymbolAddress((void**)&pp4l, g_p4l);
    cudaGetSymbolAddress((void**)&pp6h, g_p6h);
    cudaGetSymbolAddress((void**)&pp6l, g_p6l);
    cudaGetSymbolAddress((void**)&pfc1h,g_fc1h);
    cudaGetSymbolAddress((void**)&pfc1l,g_fc1l);
    cudaGetSymbolAddress((void**)&pawh, g_awh);
    cudaGetSymbolAddress((void**)&pawl, g_awl);
    cudaGetSymbolAddress((void**)&pxfh, g_xfh);
    cudaGetSymbolAddress((void**)&pxfl, g_xfl);
    cudaGetSymbolAddress((void**)&pwvh, g_wvh);
    cudaGetSymbolAddress((void**)&pwvl, g_wvl);
    cudaGetSymbolAddress((void**)&pmsh, g_msh);
    cudaGetSymbolAddress((void**)&pmsl, g_msl);
    cudaGetSymbolAddress((void**)&pamf, g_amf);
    cudaGetSymbolAddress((void**)&pptf, g_ptf);

    dim3 convGrid(Hh*Ww/NTHREADS, B_);
    #define GBLK(n) ((int)(((size_t)(n) + NTHREADS - 1) / NTHREADS))

    conv3x3_dual_kernel<<<convGrid, NTHREADS>>>(x, g_w, g_b, w_w, w_b);
    conv1x1_theta_kernel<<<convGrid, NTHREADS>>>(theta_w, theta_b);

    unfold_pk_kernel<<<GBLK((size_t)B_*LL*KP2_FIN), NTHREADS>>>(px2, pp4h, pp4l);
    unfold_pk_kernel<<<GBLK((size_t)B_*LL*KP2_FIN), NTHREADS>>>(px1, pp6h, pp6l);
    unfold_p62t_f16_kernel<<<GBLK((size_t)B_*FV*KP2_Y), NTHREADS>>>();

    msum_pk_kernel<<<GBLK((size_t)LL*KP2_LL), NTHREADS>>>(mconv_w, mfc_w, mconv_b, mfc_b);
    pack_row_kernel<<<GBLK((size_t)FOUT*KP2_FIN), NTHREADS>>>(fc1_w, pfc1h, pfc1l,
                                                              FOUT, FIN, KP2_FIN, FIN);

    // wf (fp32 + fused pack -> aw[0..8]) ; xf (fused pack only)
    {
        dim3 g((FOUT + 127)/128, (B_*LL + 127)/128, 1);
        gemm_pk_kernel<false,false,true,false><<<g, 256>>>(
            pp4h, pp4l, pfc1h, pfc1l, pwf, pawh, pawl,
            B_*LL, FOUT, FIN/16, KP2_FIN, KP2_FIN, FOUT, KP2_FOUT,
            0, 0, 0, 0, fc1_b);
        gemm_pk_kernel<false,false,true,false><<<g, 256>>>(
            pp6h, pp6l, pfc1h, pfc1l, nullptr, pxfh, pxfl,
            B_*LL, FOUT, FIN/16, KP2_FIN, KP2_FIN, FOUT, KP2_FOUT,
            0, 0, 0, 0, fc1_b);
    }

    pack_vert_kernel<<<GBLK((size_t)B_*KP2_LL*NPAD_VERT), NTHREADS>>>(pwf);

    // W2[b] = Msum ⊗ wf[b]  (fused pack -> aw[8..16])
    {
        dim3 g((FOUT + 127)/128, (LL + 127)/128, B_);
        gemm_pk_kernel<true,false,true,false><<<g, 256>>>(
            pmsh, pmsl, pwvh, pwvl, nullptr,
            pawh + (size_t)B_*LL*KP2_FOUT, pawl + (size_t)B_*LL*KP2_FOUT,
            LL, FOUT, 61, KP2_LL, NPAD_VERT, FOUT, KP2_FOUT,
            0, (long long)KP2_LL*NPAD_VERT, 0, (long long)LL*KP2_FOUT,
            nullptr);
    }

    // Batched A / Ti (bf16x3)
    {
        dim3 g((LL + 127)/128, (LL + 127)/128, 2*B_);
        gemm_pk_kernel<false,true,true,false><<<g, 256>>>(
            pawh, pawl, pxfh, pxfl, pATi, nullptr, nullptr,
            LL, LL, 13, KP2_FOUT, KP2_FOUT, LL, 0,
            (long long)LL*KP2_FOUT, (long long)LL*KP2_FOUT,
            (long long)LL*LL, 0, nullptr);
    }

    softmax_kernel<<<B_*LL, NTHREADS>>>(out);
    pack_am_f16_kernel<<<GBLK((size_t)B_*LL*KP2_Y), NTHREADS>>>(out);

    // y[b] = Am[b] @ p62[b]  — single-pass fp16
    {
        dim3 g((FV + 127)/128, (LL + 127)/128, B_);
        gemm_pk_kernel<false,false,false,true><<<g, 256>>>(
            pamf, nullptr, pptf, nullptr, py, nullptr, nullptr,
            LL, FV, 61, KP2_Y, KP2_Y, FV, 0,
            (long long)LL*KP2_Y, (long long)FV*KP2_Y,
            (long long)LL*FV, 0, nullptr);
    }

    fold_kernel<<<GBLK((size_t)B_*CIN*Hh*Ww), NTHREADS>>>();
    conv3x3_c1_kernel<<<convGrid, NTHREADS>>>(c1_w);
    conv1x1_c2_res_kernel<<<convGrid, NTHREADS>>>(c2_w, x, out + (size_t)B_*LL*LL);
    #undef GBLK
}

// round 14
// speedup vs baseline: 2.5358x; 1.0274x over previous
#include <cuda_runtime.h>
#include <cstdint>
#include <math.h>
#include <float.h>

#define B_   8
#define CIN  32
#define CI   16
#define Hh   128
#define Ww   128
#define NHH  31
#define LL   961
#define FIN  784
#define FOUT 196
#define FV   1568
#define NTHREADS 256

#define KP2_FIN   392
#define KP2_FOUT  104
#define KP2_LL    488
#define NPAD_VERT 256
#define KP2_Y     488

// ---------------- scratch (device globals) ------------------------------------
__device__ float    g_x1[(size_t)B_*CI*Hh*Ww];
__device__ float    g_x2[(size_t)B_*CI*Hh*Ww];
__device__ float    g_x3[(size_t)B_*CIN*Hh*Ww];
__device__ unsigned g_p4h[(size_t)B_*LL*KP2_FIN], g_p4l[(size_t)B_*LL*KP2_FIN];
__device__ unsigned g_p6h[(size_t)B_*LL*KP2_FIN], g_p6l[(size_t)B_*LL*KP2_FIN];
__device__ unsigned g_fc1h[(size_t)FOUT*KP2_FIN], g_fc1l[(size_t)FOUT*KP2_FIN];
__device__ float    g_wf[(size_t)B_*LL*FOUT];
__device__ unsigned g_awh[(size_t)2*B_*LL*KP2_FOUT], g_awl[(size_t)2*B_*LL*KP2_FOUT];
__device__ unsigned g_xfh[(size_t)B_*LL*KP2_FOUT],   g_xfl[(size_t)B_*LL*KP2_FOUT];
__device__ unsigned g_wvh[(size_t)B_*KP2_LL*NPAD_VERT], g_wvl[(size_t)B_*KP2_LL*NPAD_VERT];
__device__ unsigned g_msh[(size_t)LL*KP2_LL], g_msl[(size_t)LL*KP2_LL];
__device__ float    g_bsum[LL];
__device__ float    g_ATi[(size_t)2*B_*LL*LL];
__device__ unsigned g_amf[(size_t)B_*LL*KP2_Y];
__device__ unsigned g_ptf[(size_t)B_*FV*KP2_Y];
__device__ float    g_y[(size_t)B_*LL*FV];
__device__ float    g_fold[(size_t)B_*CIN*Hh*Ww];

static __device__ __forceinline__ float sigmoid_ref(float x) {
    if (x >= 0.f) return 1.f / (1.f + expf(-x));
    float e = expf(x);
    if (e < FLT_MIN) e = 0.f;
    return e / (1.f + e);
}

// =================== pack / mma helpers ========================================
__device__ __forceinline__ unsigned packbf(float x, float y) {
    unsigned r;
    asm("cvt.rn.bf16x2.f32 %0, %1, %2;" : "=r"(r) : "f"(y), "f"(x));
    return r;
}
__device__ __forceinline__ unsigned packf16(float x, float y) {
    unsigned r;
    asm("cvt.rn.f16x2.f32 %0, %1, %2;" : "=r"(r) : "f"(y), "f"(x));
    return r;
}
__device__ __forceinline__ void split2(float x, float y, unsigned& hi, unsigned& lo) {
    hi = packbf(x, y);
    float hx = __uint_as_float(hi << 16);
    float hy = __uint_as_float(hi & 0xFFFF0000u);
    lo = packbf(x - hx, y - hy);
}
__device__ __forceinline__ void mma_bf16(float c[4],
    unsigned a0, unsigned a1, unsigned a2, unsigned a3, unsigned b0, unsigned b1)
{
    asm volatile("mma.sync.aligned.m16n8k16.row.col.f32.bf16.bf16.f32 "
        "{%0,%1,%2,%3}, {%4,%5,%6,%7}, {%8,%9}, {%0,%1,%2,%3};"
        : "+f"(c[0]), "+f"(c[1]), "+f"(c[2]), "+f"(c[3])
        : "r"(a0), "r"(a1), "r"(a2), "r"(a3), "r"(b0), "r"(b1));
}
__device__ __forceinline__ void mma_f16(float c[4],
    unsigned a0, unsigned a1, unsigned a2, unsigned a3, unsigned b0, unsigned b1)
{
    asm volatile("mma.sync.aligned.m16n8k16.row.col.f32.f16.f16.f32 "
        "{%0,%1,%2,%3}, {%4,%5,%6,%7}, {%8,%9}, {%0,%1,%2,%3};"
        : "+f"(c[0]), "+f"(c[1]), "+f"(c[2]), "+f"(c[3])
        : "r"(a0), "r"(a1), "r"(a2), "r"(a3), "r"(b0), "r"(b1));
}

// ---------- conv: refpad 3x3 (x1,x2) + fused 1x1 theta (x3) --------------------
__global__ void conv3x3_dual_theta_kernel(const float* __restrict__ x,
                                          const float* __restrict__ w1, const float* __restrict__ b1,
                                          const float* __restrict__ w2, const float* __restrict__ b2,
                                          const float* __restrict__ tw, const float* __restrict__ tb)
{
    __shared__ float sw1[CI*CIN*9];
    __shared__ float sw2[CI*CIN*9];
    __shared__ float swt[CIN*CI];
    int t = threadIdx.x;
    for (int i = t; i < CI*CIN*9; i += NTHREADS) { sw1[i] = w1[i]; sw2[i] = w2[i]; }
    for (int i = t; i < CIN*CI; i += NTHREADS) swt[i] = tw[i];
    __syncthreads();
    int pix = blockIdx.x * NTHREADS + t;
    int b = blockIdx.y;
    int h = pix >> 7, w = pix & 127;
    float acc1[CI], acc2[CI];
    #pragma unroll
    for (int co = 0; co < CI; co++) { acc1[co] = b1[co]; acc2[co] = b2[co]; }
    const float* xb = x + (size_t)b * CIN * Hh * Ww;
    for (int ci = 0; ci < CIN; ci++) {
        float v[9];
        #pragma unroll
        for (int dh = 0; dh < 3; dh++) {
            int hh = h + dh - 1;
            hh = hh < 0 ? 1 : (hh >= Hh ? Hh - 2 : hh);
            #pragma unroll
            for (int dw = 0; dw < 3; dw++) {
                int w2p = w + dw - 1;
                w2p = w2p < 0 ? 1 : (w2p >= Ww ? Ww - 2 : w2p);
                v[dh*3 + dw] = xb[(ci*Hh + hh)*Ww + w2p];
            }
        }
        #pragma unroll
        for (int co = 0; co < CI; co++) {
            const float* p1 = &sw1[(co*CIN + ci)*9];
            const float* p2 = &sw2[(co*CIN + ci)*9];
            float s1 = 0.f, s2 = 0.f;
            #pragma unroll
            for (int k = 0; k < 9; k++) { s1 += p1[k]*v[k]; s2 += p2[k]*v[k]; }
            acc1[co] += s1; acc2[co] += s2;
        }
    }
    size_t base16 = (size_t)b * CI * Hh * Ww + pix;
    #pragma unroll
    for (int co = 0; co < CI; co++) {
        g_x1[base16 + (size_t)co*Hh*Ww] = acc1[co];
        g_x2[base16 + (size_t)co*Hh*Ww] = acc2[co];
    }
    // fused theta: x3[co] = tb[co] + sum_ci tw[co][ci]*x1[ci]  (same acc1 values)
    size_t base32 = (size_t)b * CIN * Hh * Ww + pix;
    #pragma unroll
    for (int co = 0; co < CIN; co++) {
        float s = tb[co];
        #pragma unroll
        for (int ci = 0; ci < CI; ci++) s += swt[co*CI + ci]*acc1[ci];
        g_x3[base32 + (size_t)co*Hh*Ww] = s;
    }
}

// ---------------- fused unfold + split-pack (p4 from x2, p6 from x1) ----------
__global__ void unfold_pk2_kernel()
{
    size_t t = (size_t)blockIdx.x * NTHREADS + threadIdx.x;
    if (t >= (size_t)B_*LL*KP2_FIN) return;
    int j = (int)(t % KP2_FIN);
    size_t r = t / KP2_FIN;
    int l = (int)(r % LL);
    int b = (int)(r / LL);
    float v4[2], v6[2];
    #pragma unroll
    for (int i = 0; i < 2; i++) {
        int f = 2*j + i;
        int c = f / 49, rr = f % 49, kh = rr / 7, kw = rr % 7;
        int h = (l / NHH)*4 + kh, w = (l % NHH)*4 + kw;
        size_t idx = (((size_t)b*CI + c)*Hh + h)*Ww + w;
        v4[i] = g_x2[idx];
        v6[i] = g_x1[idx];
    }
    unsigned hi, lo;
    split2(v4[0], v4[1], hi, lo);
    g_p4h[t] = hi; g_p4l[t] = lo;
    split2(v6[0], v6[1], hi, lo);
    g_p6h[t] = hi; g_p6l[t] = lo;
}

// ---------------- p62^T fp16 pack ----------------------------------------------
__global__ void unfold_p62t_f16_kernel()
{
    size_t t = (size_t)blockIdx.x * NTHREADS + threadIdx.x;
    if (t >= (size_t)B_*FV*KP2_Y) return;
    int j = (int)(t % KP2_Y);
    size_t r = t / KP2_Y;
    int f = (int)(r % FV);
    int b = (int)(r / FV);
    int c = f / 49, rr = f % 49, kh = rr / 7, kw = rr % 7;
    float v[2] = {0.f, 0.f};
    #pragma unroll
    for (int i = 0; i < 2; i++) {
        int l = 2*j + i;
        if (l < LL) {
            int h = (l / NHH)*4 + kh, w = (l % NHH)*4 + kw;
            v[i] = g_x3[(((size_t)b*CIN + c)*Hh + h)*Ww + w];
        }
    }
    g_ptf[t] = packf16(v[0], v[1]);
}

// ---------------- Msum split-pack + bsum ---------------------------------------
__global__ void msum_pk_kernel(const float* __restrict__ mw1, const float* __restrict__ mw2,
                               const float* __restrict__ mb1, const float* __restrict__ mb2)
{
    size_t t = (size_t)blockIdx.x * NTHREADS + threadIdx.x;
    if (t < (size_t)LL*KP2_LL) {
        int j = (int)(t % KP2_LL);
        int n = (int)(t / KP2_LL);
        int c0 = 2*j, c1 = 2*j + 1;
        float v0 = (c0 < LL) ? mw1[(size_t)n*LL + c0] + mw2[(size_t)n*LL + c0] : 0.f;
        float v1 = (c1 < LL) ? mw1[(size_t)n*LL + c1] + mw2[(size_t)n*LL + c1] : 0.f;
        unsigned hi, lo;
        split2(v0, v1, hi, lo);
        g_msh[t] = hi; g_msl[t] = lo;
    }
    if (t < LL) g_bsum[t] = mb1[t] + mb2[t];
}

// ---------------- generic rowpack (fc1 only) ------------------------------------
__global__ void pack_row_kernel(const float* __restrict__ src,
                                unsigned* __restrict__ dsth, unsigned* __restrict__ dstl,
                                int R, int K, int KP2, int lda)
{
    size_t t = (size_t)blockIdx.x * NTHREADS + threadIdx.x;
    if (t >= (size_t)R*KP2) return;
    int j = (int)(t % KP2);
    int r = (int)(t / KP2);
    int k0 = 2*j;
    float v0 = (k0     < K) ? src[(size_t)r*lda + k0]     : 0.f;
    float v1 = (k0 + 1 < K) ? src[(size_t)r*lda + k0 + 1] : 0.f;
    unsigned hi, lo;
    split2(v0, v1, hi, lo);
    dsth[t] = hi; dstl[t] = lo;
}

// ---------------- wf vertical pack ----------------------------------------------
__global__ void pack_vert_kernel(const float* __restrict__ wf)
{
    size_t t = (size_t)blockIdx.x * NTHREADS + threadIdx.x;
    if (t >= (size_t)B_*KP2_LL*NPAD_VERT) return;
    int n = (int)(t % NPAD_VERT);
    size_t r = t / NPAD_VERT;
    int kk = (int)(r % KP2_LL);
    int b  = (int)(r / KP2_LL);
    int l0 = 2*kk, l1 = 2*kk + 1;
    float v0 = 0.f, v1 = 0.f;
    if (n < FOUT) {
        const float* wb = wf + (size_t)b*LL*FOUT;
        if (l0 < LL) v0 = wb[(size_t)l0*FOUT + n];
        if (l1 < LL) v1 = wb[(size_t)l1*FOUT + n];
    }
    unsigned hi, lo;
    split2(v0, v1, hi, lo);
    g_wvh[t] = hi; g_wvl[t] = lo;
}

// ========= packed pair GEMM (bf16x3 split OR single-pass fp16) =================
template <bool BVERT, bool MODB, bool SPLIT, bool F16>
__global__ void __launch_bounds__(256, 2) gemm_pk_kernel(
    const unsigned* __restrict__ Ahg, const unsigned* __restrict__ Alg,
    const unsigned* __restrict__ Bhg, const unsigned* __restrict__ Blg,
    float* __restrict__ Cg,
    unsigned* __restrict__ Ph, unsigned* __restrict__ Pl,
    int M, int N, int nchunks,
    int lda2, int ldb2, int ldc, int ldp2,
    long long sA2, long long sB2, long long sC, long long sP,
    const float* __restrict__ colBias)
{
    __shared__ unsigned Ah[2][8][136];
    __shared__ unsigned Bh[2][8][136];
    __shared__ unsigned Al[SPLIT ? 2 : 1][SPLIT ? 8 : 1][SPLIT ? 136 : 1];
    __shared__ unsigned Bl[SPLIT ? 2 : 1][SPLIT ? 8 : 1][SPLIT ? 136 : 1];

    const int tid = threadIdx.x;
    const int wid = tid >> 5, lane = tid & 31;
    const int wm = wid >> 2, wn = wid & 3;
    const int m_w = wm * 64, n_w = wn * 32;
    const int g = lane >> 2, tg = lane & 3;
    const int m0 = blockIdx.y * 128, n0 = blockIdx.x * 128;
    const unsigned* Ahb = Ahg + (long long)blockIdx.z * sA2;
    const unsigned* Alb = SPLIT ? (Alg + (long long)blockIdx.z * sA2) : Ahg;
    const long long zb = (long long)(MODB ? (blockIdx.z & 7) : blockIdx.z) * sB2;
    const unsigned* Bhb = Bhg + zb;
    const unsigned* Blb = SPLIT ? (Blg + zb) : Bhg;
    float* Cb = Cg ? (Cg + (long long)blockIdx.z * sC) : nullptr;

    float acc[4][4][4];
    #pragma unroll
    for (int i = 0; i < 4; i++)
        #pragma unroll
        for (int j = 0; j < 4; j++)
            #pragma unroll
            for (int q = 0; q < 4; q++) acc[i][j][q] = 0.f;

    const int a_c = (tid & 3) * 2;
    const int a_r = tid >> 2;
    const int bn_q = (tid & 31) * 4;
    const int bk_r = tid >> 5;

    uint2 vah[2], val[2], vbh[2], vbl[2];
    uint4 bvh, bvl;

    #define LOAD_PK(p0)                                                        \
        _Pragma("unroll")                                                      \
        for (int i = 0; i < 2; i++) {                                          \
            int gm = m0 + a_r + 64*i;                                          \
            if (gm < M) {                                                      \
                long long idx = (long long)gm*lda2 + (p0) + a_c;               \
                vah[i] = *(const uint2*)(Ahb + idx);                           \
                if (SPLIT) val[i] = *(const uint2*)(Alb + idx);                \
            } else { vah[i] = make_uint2(0,0); val[i] = make_uint2(0,0); }     \
        }                                                                      \
        if (!BVERT) {                                                          \
            _Pragma("unroll")                                                  \
            for (int i = 0; i < 2; i++) {                                      \
                int gn = n0 + a_r + 64*i;                                      \
                if (gn < N) {                                                  \
                    long long idx = (long long)gn*ldb2 + (p0) + a_c;           \
                    vbh[i] = *(const uint2*)(Bhb + idx);                       \
                    if (SPLIT) vbl[i] = *(const uint2*)(Blb + idx);            \
                } else { vbh[i] = make_uint2(0,0); vbl[i] = make_uint2(0,0); } \
            }                                                                  \
        } else {                                                               \
            long long idx = (long long)((p0) + bk_r)*ldb2 + n0 + bn_q;         \
            bvh = *(const uint4*)(Bhb + idx);                                  \
            if (SPLIT) bvl = *(const uint4*)(Blb + idx);                       \
        }
    #define STORE_PK(st)                                                       \
        _Pragma("unroll")                                                      \
        for (int i = 0; i < 2; i++) {                                          \
            int m = a_r + 64*i;                                                \
            Ah[st][a_c  ][m] = vah[i].x;  Ah[st][a_c+1][m] = vah[i].y;         \
            if (SPLIT) { Al[st][a_c  ][m] = val[i].x;                          \
                         Al[st][a_c+1][m] = val[i].y; }                        \
        }                                                                      \
        if (!BVERT) {                                                          \
            _Pragma("unroll")                                                  \
            for (int i = 0; i < 2; i++) {                                      \
                int n = a_r + 64*i;                                            \
                Bh[st][a_c  ][n] = vbh[i].x;  Bh[st][a_c+1][n] = vbh[i].y;     \
                if (SPLIT) { Bl[st][a_c  ][n] = vbl[i].x;                      \
                             Bl[st][a_c+1][n] = vbl[i].y; }                    \
            }                                                                  \
        } else {                                                               \
            *(uint4*)&Bh[st][bk_r][bn_q] = bvh;                                \
            if (SPLIT) { *(uint4*)&Bl[st][bk_r][bn_q] = bvl; }                 \
        }

    LOAD_PK(0)
    STORE_PK(0)
    __syncthreads();

    for (int c = 0; c < nchunks; c++) {
        const int st = c & 1;
        if (c + 1 < nchunks) { LOAD_PK((c+1)*8) }
        unsigned bh0[4], bh1[4], bl0[4], bl1[4];
        #pragma unroll
        for (int nt = 0; nt < 4; nt++) {
            int n = n_w + nt*8 + g;
            bh0[nt] = Bh[st][tg  ][n];
            bh1[nt] = Bh[st][tg+4][n];
            if (SPLIT) {
                bl0[nt] = Bl[st][tg  ][n];
                bl1[nt] = Bl[st][tg+4][n];
            }
        }
        #pragma unroll
        for (int mt = 0; mt < 4; mt++) {
            int m = m_w + mt*16 + g;
            unsigned ah0 = Ah[st][tg  ][m];
            unsigned ah1 = Ah[st][tg  ][m+8];
            unsigned ah2 = Ah[st][tg+4][m];
            unsigned ah3 = Ah[st][tg+4][m+8];
            if (SPLIT) {
                unsigned al0 = Al[st][tg  ][m];
                unsigned al1 = Al[st][tg  ][m+8];
                unsigned al2 = Al[st][tg+4][m];
                unsigned al3 = Al[st][tg+4][m+8];
                #pragma unroll
                for (int nt = 0; nt < 4; nt++)
                    mma_bf16(acc[mt][nt], ah0, ah1, ah2, ah3, bh0[nt], bh1[nt]);
                #pragma unroll
                for (int nt = 0; nt < 4; nt++)
                    mma_bf16(acc[mt][nt], ah0, ah1, ah2, ah3, bl0[nt], bl1[nt]);
                #pragma unroll
                for (int nt = 0; nt < 4; nt++)
                    mma_bf16(acc[mt][nt], al0, al1, al2, al3, bh0[nt], bh1[nt]);
            } else {
                #pragma unroll
                for (int nt = 0; nt < 4; nt++) {
                    if (F16) mma_f16(acc[mt][nt], ah0, ah1, ah2, ah3, bh0[nt], bh1[nt]);
                    else     mma_bf16(acc[mt][nt], ah0, ah1, ah2, ah3, bh0[nt], bh1[nt]);
                }
            }
        }
        if (c + 1 < nchunks) { STORE_PK(st ^ 1) }
        __syncthreads();
    }
    #undef LOAD_PK
    #undef STORE_PK

    unsigned* Phb = Ph ? (Ph + (long long)blockIdx.z * sP) : nullptr;
    unsigned* Plb = Pl ? (Pl + (long long)blockIdx.z * sP) : nullptr;

    #pragma unroll
    for (int mt = 0; mt < 4; mt++) {
        #pragma unroll
        for (int nt = 0; nt < 4; nt++) {
            int r0 = m0 + m_w + mt*16 + g;
            int r1 = r0 + 8;
            int c  = n0 + n_w + nt*8 + 2*tg;
            float cb0 = (colBias && c   < N) ? colBias[c]   : 0.f;
            float cb1 = (colBias && c+1 < N) ? colBias[c+1] : 0.f;
            float v00 = acc[mt][nt][0] + cb0, v01 = acc[mt][nt][1] + cb1;
            float v10 = acc[mt][nt][2] + cb0, v11 = acc[mt][nt][3] + cb1;
            if (Cb) {
                if (r0 < M) {
                    if (c   < N) Cb[(long long)r0*ldc + c]   = v00;
                    if (c+1 < N) Cb[(long long)r0*ldc + c+1] = v01;
                }
                if (r1 < M) {
                    if (c   < N) Cb[(long long)r1*ldc + c]   = v10;
                    if (c+1 < N) Cb[(long long)r1*ldc + c+1] = v11;
                }
            }
            if (Phb && c + 1 < N) {
                int j = c >> 1;
                unsigned h, l;
                if (r0 < M) {
                    split2(v00, v01, h, l);
                    Phb[(long long)r0*ldp2 + j] = h;
                    Plb[(long long)r0*ldp2 + j] = l;
                }
                if (r1 < M) {
                    split2(v10, v11, h, l);
                    Phb[(long long)r1*ldp2 + j] = h;
                    Plb[(long long)r1*ldp2 + j] = l;
                }
            }
        }
    }
}

// ---------------- masked softmax -> Am (d_out) + fused fp16 pack ----------------
// thread t handles m = 4t..4t+3 so fp16 pairs come straight from registers.
__global__ void softmax_kernel(float* __restrict__ Am)
{
    int row = blockIdx.x;
    const float* Ar = g_ATi + (size_t)row * LL;
    const float* Tr = g_ATi + (size_t)B_*LL*LL + (size_t)row * LL;
    const float bl = g_bsum[row % LL];
    int t = threadIdx.x;
    const float scale = 0.07142857142857142f;
    float v[4], mb[4];
    float mx = -INFINITY;
    #pragma unroll
    for (int i = 0; i < 4; i++) {
        int m = 4*t + i;
        v[i] = 0.f; mb[i] = 0.f;
        if (m < LL) {
            float mask = sigmoid_ref(Tr[m] + bl);
            v[i] = Ar[m] * mask * scale;
            mb[i] = (mask != 0.f) ? 1.f : 0.f;
            mx = fmaxf(mx, v[i]);
        }
    }
    __shared__ float red[NTHREADS];
    red[t] = mx; __syncthreads();
    for (int s = NTHREADS/2; s > 0; s >>= 1) {
        if (t < s) red[t] = fmaxf(red[t], red[t+s]);
        __syncthreads();
    }
    mx = red[0]; __syncthreads();
    float e[4]; float sum = 0.f;
    #pragma unroll
    for (int i = 0; i < 4; i++) {
        int m = 4*t + i;
        if (m < LL) { e[i] = expf(v[i] - mx); sum += e[i]; } else e[i] = 0.f;
    }
    red[t] = sum; __syncthreads();
    for (int s = NTHREADS/2; s > 0; s >>= 1) {
        if (t < s) red[t] += red[t+s];
        __syncthreads();
    }
    float inv = 1.f / red[0];
    float o[4];
    #pragma unroll
    for (int i = 0; i < 4; i++) {
        int m = 4*t + i;
        o[i] = e[i] * inv * mb[i];
        if (m < LL) Am[(size_t)row*LL + m] = o[i];
    }
    // fused fp16 pair pack for the y GEMM
    unsigned* amr = g_amf + (size_t)row * KP2_Y;
    if (4*t     < LL) amr[2*t]     = packf16(o[0], o[1]);
    if (4*t + 2 < LL) amr[2*t + 1] = packf16(o[2], o[3]);
}

// ---------------- fold (gather form) --------------------------------------------
__global__ void fold_kernel()
{
    size_t t = (size_t)blockIdx.x * NTHREADS + threadIdx.x;
    if (t >= (size_t)B_*CIN*Hh*Ww) return;
    int w = (int)(t % Ww); size_t r = t / Ww;
    int h = (int)(r % Hh); r /= Hh;
    int c = (int)(r % CIN);
    int b = (int)(r / CIN);
    int i0 = (h > 6) ? (h - 3) >> 2 : 0;
    int i1 = h >> 2; if (i1 > NHH - 1) i1 = NHH - 1;
    int j0 = (w > 6) ? (w - 3) >> 2 : 0;
    int j1 = w >> 2; if (j1 > NHH - 1) j1 = NHH - 1;
    float s = 0.f;
    for (int i = i0; i <= i1; i++) {
        int kh = h - i*4;
        for (int j = j0; j <= j1; j++) {
            int kw = w - j*4;
            s += g_y[((size_t)b*LL + i*NHH + j)*FV + c*49 + kh*7 + kw];
        }
    }
    g_fold[t] = s;
}

// ---------- conv c1 (3x3 refpad, leaky) + fused c2 (1x1, leaky) + residual ------
__global__ void conv_c1c2_res_kernel(const float* __restrict__ w1,
                                     const float* __restrict__ cw,
                                     const float* __restrict__ x,
                                     float* __restrict__ outp)
{
    __shared__ float sw[CI*CIN*9];
    __shared__ float sw2[CIN*CI];
    int t = threadIdx.x;
    for (int i = t; i < CI*CIN*9; i += NTHREADS) sw[i] = w1[i];
    for (int i = t; i < CIN*CI; i += NTHREADS) sw2[i] = cw[i];
    __syncthreads();
    int pix = blockIdx.x * NTHREADS + t;
    int b = blockIdx.y;
    int h = pix >> 7, w = pix & 127;
    float acc[CI];
    #pragma unroll
    for (int co = 0; co < CI; co++) acc[co] = 0.f;
    const float* xb = g_fold + (size_t)b * CIN * Hh * Ww;
    for (int ci = 0; ci < CIN; ci++) {
        float v[9];
        #pragma unroll
        for (int dh = 0; dh < 3; dh++) {
            int hh = h + dh - 1;
            hh = hh < 0 ? 1 : (hh >= Hh ? Hh - 2 : hh);
            #pragma unroll
            for (int dw = 0; dw < 3; dw++) {
                int w2p = w + dw - 1;
                w2p = w2p < 0 ? 1 : (w2p >= Ww ? Ww - 2 : w2p);
                v[dh*3 + dw] = xb[(ci*Hh + hh)*Ww + w2p];
            }
        }
        #pragma unroll
        for (int co = 0; co < CI; co++) {
            const float* p1 = &sw[(co*CIN + ci)*9];
            float s1 = 0.f;
            #pragma unroll
            for (int k = 0; k < 9; k++) s1 += p1[k]*v[k];
            acc[co] += s1;
        }
    }
    #pragma unroll
    for (int co = 0; co < CI; co++)
        acc[co] = (acc[co] > 0.f) ? acc[co] : 0.2f*acc[co];
    // fused c2 (1x1) + leaky + residual
    #pragma unroll
    for (int co = 0; co < CIN; co++) {
        float s = 0.f;
        #pragma unroll
        for (int ci = 0; ci < CI; ci++) s += sw2[co*CI + ci]*acc[ci];
        s = (s > 0.f) ? s : 0.2f*s;
        size_t idx = ((size_t)b*CIN + co)*Hh*Ww + pix;
        outp[idx] = x[idx] + s;
    }
}

// ---------------- launch -----------------------------------------------------------
extern "C" void kernel_launch(void* const* d_in, const int* in_sizes, int n_in,
                              void* d_out, int out_size)
{
    const float* x        = (const float*)d_in[0];
    const float* g_w      = (const float*)d_in[1];
    const float* g_b      = (const float*)d_in[2];
    const float* w_w      = (const float*)d_in[3];
    const float* w_b      = (const float*)d_in[4];
    const float* theta_w  = (const float*)d_in[5];
    const float* theta_b  = (const float*)d_in[6];
    const float* fc1_w    = (const float*)d_in[7];
    const float* fc1_b    = (const float*)d_in[8];
    const float* mconv_w  = (const float*)d_in[9];
    const float* mconv_b  = (const float*)d_in[10];
    const float* mfc_w    = (const float*)d_in[11];
    const float* mfc_b    = (const float*)d_in[12];
    const float* c1_w     = (const float*)d_in[13];
    const float* c2_w     = (const float*)d_in[14];
    float* out = (float*)d_out;

    float *pwf, *pATi, *py;
    unsigned *pp4h, *pp4l, *pp6h, *pp6l, *pfc1h, *pfc1l,
             *pawh, *pawl, *pxfh, *pxfl, *pwvh, *pwvl, *pmsh, *pmsl,
             *pamf, *pptf;
    cudaGetSymbolAddress((void**)&pwf,  g_wf);
    cudaGetSymbolAddress((void**)&pATi, g_ATi);
    cudaGetSymbolAddress((void**)&py,   g_y);
    cudaGetSymbolAddress((void**)&pp4h, g_p4h);
    cudaGetSymbolAddress((void**)&pp4l, g_p4l);
    cudaGetSymbolAddress((void**)&pp6h, g_p6h);
    cudaGetSymbolAddress((void**)&pp6l, g_p6l);
    cudaGetSymbolAddress((void**)&pfc1h,g_fc1h);
    cudaGetSymbolAddress((void**)&pfc1l,g_fc1l);
    cudaGetSymbolAddress((void**)&pawh, g_awh);
    cudaGetSymbolAddress((void**)&pawl, g_awl);
    cudaGetSymbolAddress((void**)&pxfh, g_xfh);
    cudaGetSymbolAddress((void**)&pxfl, g_xfl);
    cudaGetSymbolAddress((void**)&pwvh, g_wvh);
    cudaGetSymbolAddress((void**)&pwvl, g_wvl);
    cudaGetSymbolAddress((void**)&pmsh, g_msh);
    cudaGetSymbolAddress((void**)&pmsl, g_msl);
    cudaGetSymbolAddress((void**)&pamf, g_amf);
    cudaGetSymbolAddress((void**)&pptf, g_ptf);

    dim3 convGrid(Hh*Ww/NTHREADS, B_);
    #define GBLK(n) ((int)(((size_t)(n) + NTHREADS - 1) / NTHREADS))

    conv3x3_dual_theta_kernel<<<convGrid, NTHREADS>>>(x, g_w, g_b, w_w, w_b,
                                                      theta_w, theta_b);

    unfold_pk2_kernel<<<GBLK((size_t)B_*LL*KP2_FIN), NTHREADS>>>();
    unfold_p62t_f16_kernel<<<GBLK((size_t)B_*FV*KP2_Y), NTHREADS>>>();

    msum_pk_kernel<<<GBLK((size_t)LL*KP2_LL), NTHREADS>>>(mconv_w, mfc_w, mconv_b, mfc_b);
    pack_row_kernel<<<GBLK((size_t)FOUT*KP2_FIN), NTHREADS>>>(fc1_w, pfc1h, pfc1l,
                                                              FOUT, FIN, KP2_FIN, FIN);

    // wf (fp32 + fused pack -> aw[0..8]) ; xf (fused pack only)
    {
        dim3 g((FOUT + 127)/128, (B_*LL + 127)/128, 1);
        gemm_pk_kernel<false,false,true,false><<<g, 256>>>(
            pp4h, pp4l, pfc1h, pfc1l, pwf, pawh, pawl,
            B_*LL, FOUT, FIN/16, KP2_FIN, KP2_FIN, FOUT, KP2_FOUT,
            0, 0, 0, 0, fc1_b);
        gemm_pk_kernel<false,false,true,false><<<g, 256>>>(
            pp6h, pp6l, pfc1h, pfc1l, nullptr, pxfh, pxfl,
            B_*LL, FOUT, FIN/16, KP2_FIN, KP2_FIN, FOUT, KP2_FOUT,
            0, 0, 0, 0, fc1_b);
    }

    pack_vert_kernel<<<GBLK((size_t)B_*KP2_LL*NPAD_VERT), NTHREADS>>>(pwf);

    // W2[b] = Msum ⊗ wf[b]  (fused pack -> aw[8..16])
    {
        dim3 g((FOUT + 127)/128, (LL + 127)/128, B_);
        gemm_pk_kernel<true,false,true,false><<<g, 256>>>(
            pmsh, pmsl, pwvh, pwvl, nullptr,
            pawh + (size_t)B_*LL*KP2_FOUT, pawl + (size_t)B_*LL*KP2_FOUT,
            LL, FOUT, 61, KP2_LL, NPAD_VERT, FOUT, KP2_FOUT,
            0, (long long)KP2_LL*NPAD_VERT, 0, (long long)LL*KP2_FOUT,
            nullptr);
    }

    // Batched A / Ti (bf16x3)
    {
        dim3 g((LL + 127)/128, (LL + 127)/128, 2*B_);
        gemm_pk_kernel<false,true,true,false><<<g, 256>>>(
            pawh, pawl, pxfh, pxfl, pATi, nullptr, nullptr,
            LL, LL, 13, KP2_FOUT, KP2_FOUT, LL, 0,
            (long long)LL*KP2_FOUT, (long long)LL*KP2_FOUT,
            (long long)LL*LL, 0, nullptr);
    }

    softmax_kernel<<<B_*LL, NTHREADS>>>(out);

    // y[b] = Am[b] @ p62[b]  — single-pass fp16
    {
        dim3 g((FV + 127)/128, (LL + 127)/128, B_);
        gemm_pk_kernel<false,false,false,true><<<g, 256>>>(
            pamf, nullptr, pptf, nullptr, py, nullptr, nullptr,
            LL, FV, 61, KP2_Y, KP2_Y, FV, 0,
            (long long)LL*KP2_Y, (long long)FV*KP2_Y,
            (long long)LL*FV, 0, nullptr);
    }

    fold_kernel<<<GBLK((size_t)B_*CIN*Hh*Ww), NTHREADS>>>();
    conv_c1c2_res_kernel<<<convGrid, NTHREADS>>>(c1_w, c2_w, x, out + (size_t)B_*LL*LL);
    #undef GBLK
}

// round 15
// speedup vs baseline: 2.5830x; 1.0186x over previous
#include <cuda_runtime.h>
#include <cstdint>
#include <math.h>
#include <float.h>

#define B_   8
#define CIN  32
#define CI   16
#define Hh   128
#define Ww   128
#define NHH  31
#define LL   961
#define FIN  784
#define FOUT 196
#define FV   1568
#define NTHREADS 256

#define KP2_FIN   392
#define KP2_FOUT  104
#define KP2_LL    488
#define NPAD_VERT 256
#define KP2_Y     488

// ---------------- scratch (device globals) ------------------------------------
__device__ float    g_x1[(size_t)B_*CI*Hh*Ww];
__device__ float    g_x2[(size_t)B_*CI*Hh*Ww];
__device__ float    g_x3[(size_t)B_*CIN*Hh*Ww];
__device__ unsigned g_p4h[(size_t)B_*LL*KP2_FIN], g_p4l[(size_t)B_*LL*KP2_FIN];
__device__ unsigned g_p6h[(size_t)B_*LL*KP2_FIN], g_p6l[(size_t)B_*LL*KP2_FIN];
__device__ unsigned g_fc1h[(size_t)FOUT*KP2_FIN], g_fc1l[(size_t)FOUT*KP2_FIN];
__device__ float    g_wf[(size_t)B_*LL*FOUT];
__device__ float    g_W2a[(size_t)B_*LL*FOUT];
__device__ float    g_W2b[(size_t)B_*LL*FOUT];
__device__ unsigned g_awh[(size_t)2*B_*LL*KP2_FOUT], g_awl[(size_t)2*B_*LL*KP2_FOUT];
__device__ unsigned g_xfh[(size_t)B_*LL*KP2_FOUT],   g_xfl[(size_t)B_*LL*KP2_FOUT];
__device__ unsigned g_wvh[(size_t)B_*KP2_LL*NPAD_VERT], g_wvl[(size_t)B_*KP2_LL*NPAD_VERT];
__device__ unsigned g_msh[(size_t)LL*KP2_LL], g_msl[(size_t)LL*KP2_LL];
__device__ float    g_bsum[LL];
__device__ float    g_ATi[(size_t)2*B_*LL*LL];
__device__ unsigned g_amf[(size_t)B_*LL*KP2_Y];
__device__ unsigned g_ptf[(size_t)B_*FV*KP2_Y];
__device__ float    g_y[(size_t)B_*LL*FV];
__device__ float    g_fold[(size_t)B_*CIN*Hh*Ww];

static __device__ __forceinline__ float sigmoid_ref(float x) {
    if (x >= 0.f) return 1.f / (1.f + expf(-x));
    float e = expf(x);
    if (e < FLT_MIN) e = 0.f;
    return e / (1.f + e);
}

// =================== pack / mma helpers ========================================
__device__ __forceinline__ unsigned packbf(float x, float y) {
    unsigned r;
    asm("cvt.rn.bf16x2.f32 %0, %1, %2;" : "=r"(r) : "f"(y), "f"(x));
    return r;
}
__device__ __forceinline__ unsigned packf16(float x, float y) {
    unsigned r;
    asm("cvt.rn.f16x2.f32 %0, %1, %2;" : "=r"(r) : "f"(y), "f"(x));
    return r;
}
__device__ __forceinline__ void split2(float x, float y, unsigned& hi, unsigned& lo) {
    hi = packbf(x, y);
    float hx = __uint_as_float(hi << 16);
    float hy = __uint_as_float(hi & 0xFFFF0000u);
    lo = packbf(x - hx, y - hy);
}
__device__ __forceinline__ void mma_bf16(float c[4],
    unsigned a0, unsigned a1, unsigned a2, unsigned a3, unsigned b0, unsigned b1)
{
    asm volatile("mma.sync.aligned.m16n8k16.row.col.f32.bf16.bf16.f32 "
        "{%0,%1,%2,%3}, {%4,%5,%6,%7}, {%8,%9}, {%0,%1,%2,%3};"
        : "+f"(c[0]), "+f"(c[1]), "+f"(c[2]), "+f"(c[3])
        : "r"(a0), "r"(a1), "r"(a2), "r"(a3), "r"(b0), "r"(b1));
}
__device__ __forceinline__ void mma_f16(float c[4],
    unsigned a0, unsigned a1, unsigned a2, unsigned a3, unsigned b0, unsigned b1)
{
    asm volatile("mma.sync.aligned.m16n8k16.row.col.f32.f16.f16.f32 "
        "{%0,%1,%2,%3}, {%4,%5,%6,%7}, {%8,%9}, {%0,%1,%2,%3};"
        : "+f"(c[0]), "+f"(c[1]), "+f"(c[2]), "+f"(c[3])
        : "r"(a0), "r"(a1), "r"(a2), "r"(a3), "r"(b0), "r"(b1));
}

// ---------- conv: refpad 3x3 (x1,x2) + fused 1x1 theta (x3) --------------------
__global__ void conv3x3_dual_theta_kernel(const float* __restrict__ x,
                                          const float* __restrict__ w1, const float* __restrict__ b1,
                                          const float* __restrict__ w2, const float* __restrict__ b2,
                                          const float* __restrict__ tw, const float* __restrict__ tb)
{
    __shared__ float sw1[CI*CIN*9];
    __shared__ float sw2[CI*CIN*9];
    __shared__ float swt[CIN*CI];
    int t = threadIdx.x;
    for (int i = t; i < CI*CIN*9; i += NTHREADS) { sw1[i] = w1[i]; sw2[i] = w2[i]; }
    for (int i = t; i < CIN*CI; i += NTHREADS) swt[i] = tw[i];
    __syncthreads();
    int pix = blockIdx.x * NTHREADS + t;
    int b = blockIdx.y;
    int h = pix >> 7, w = pix & 127;
    float acc1[CI], acc2[CI];
    #pragma unroll
    for (int co = 0; co < CI; co++) { acc1[co] = b1[co]; acc2[co] = b2[co]; }
    const float* xb = x + (size_t)b * CIN * Hh * Ww;
    for (int ci = 0; ci < CIN; ci++) {
        float v[9];
        #pragma unroll
        for (int dh = 0; dh < 3; dh++) {
            int hh = h + dh - 1;
            hh = hh < 0 ? 1 : (hh >= Hh ? Hh - 2 : hh);
            #pragma unroll
            for (int dw = 0; dw < 3; dw++) {
                int w2p = w + dw - 1;
                w2p = w2p < 0 ? 1 : (w2p >= Ww ? Ww - 2 : w2p);
                v[dh*3 + dw] = xb[(ci*Hh + hh)*Ww + w2p];
            }
        }
        #pragma unroll
        for (int co = 0; co < CI; co++) {
            const float* p1 = &sw1[(co*CIN + ci)*9];
            const float* p2 = &sw2[(co*CIN + ci)*9];
            float s1 = 0.f, s2 = 0.f;
            #pragma unroll
            for (int k = 0; k < 9; k++) { s1 += p1[k]*v[k]; s2 += p2[k]*v[k]; }
            acc1[co] += s1; acc2[co] += s2;
        }
    }
    size_t base16 = (size_t)b * CI * Hh * Ww + pix;
    #pragma unroll
    for (int co = 0; co < CI; co++) {
        g_x1[base16 + (size_t)co*Hh*Ww] = acc1[co];
        g_x2[base16 + (size_t)co*Hh*Ww] = acc2[co];
    }
    size_t base32 = (size_t)b * CIN * Hh * Ww + pix;
    #pragma unroll
    for (int co = 0; co < CIN; co++) {
        float s = tb[co];
        #pragma unroll
        for (int ci = 0; ci < CI; ci++) s += swt[co*CI + ci]*acc1[ci];
        g_x3[base32 + (size_t)co*Hh*Ww] = s;
    }
}

// ---------------- fused unfold + split-pack (p4 from x2, p6 from x1) ----------
__global__ void unfold_pk2_kernel()
{
    size_t t = (size_t)blockIdx.x * NTHREADS + threadIdx.x;
    if (t >= (size_t)B_*LL*KP2_FIN) return;
    int j = (int)(t % KP2_FIN);
    size_t r = t / KP2_FIN;
    int l = (int)(r % LL);
    int b = (int)(r / LL);
    float v4[2], v6[2];
    #pragma unroll
    for (int i = 0; i < 2; i++) {
        int f = 2*j + i;
        int c = f / 49, rr = f % 49, kh = rr / 7, kw = rr % 7;
        int h = (l / NHH)*4 + kh, w = (l % NHH)*4 + kw;
        size_t idx = (((size_t)b*CI + c)*Hh + h)*Ww + w;
        v4[i] = g_x2[idx];
        v6[i] = g_x1[idx];
    }
    unsigned hi, lo;
    split2(v4[0], v4[1], hi, lo);
    g_p4h[t] = hi; g_p4l[t] = lo;
    split2(v6[0], v6[1], hi, lo);
    g_p6h[t] = hi; g_p6l[t] = lo;
}

// ---------------- p62^T fp16 pack ----------------------------------------------
__global__ void unfold_p62t_f16_kernel()
{
    size_t t = (size_t)blockIdx.x * NTHREADS + threadIdx.x;
    if (t >= (size_t)B_*FV*KP2_Y) return;
    int j = (int)(t % KP2_Y);
    size_t r = t / KP2_Y;
    int f = (int)(r % FV);
    int b = (int)(r / FV);
    int c = f / 49, rr = f % 49, kh = rr / 7, kw = rr % 7;
    float v[2] = {0.f, 0.f};
    #pragma unroll
    for (int i = 0; i < 2; i++) {
        int l = 2*j + i;
        if (l < LL) {
            int h = (l / NHH)*4 + kh, w = (l % NHH)*4 + kw;
            v[i] = g_x3[(((size_t)b*CIN + c)*Hh + h)*Ww + w];
        }
    }
    g_ptf[t] = packf16(v[0], v[1]);
}

// ---------------- Msum split-pack + bsum ---------------------------------------
__global__ void msum_pk_kernel(const float* __restrict__ mw1, const float* __restrict__ mw2,
                               const float* __restrict__ mb1, const float* __restrict__ mb2)
{
    size_t t = (size_t)blockIdx.x * NTHREADS + threadIdx.x;
    if (t < (size_t)LL*KP2_LL) {
        int j = (int)(t % KP2_LL);
        int n = (int)(t / KP2_LL);
        int c0 = 2*j, c1 = 2*j + 1;
        float v0 = (c0 < LL) ? mw1[(size_t)n*LL + c0] + mw2[(size_t)n*LL + c0] : 0.f;
        float v1 = (c1 < LL) ? mw1[(size_t)n*LL + c1] + mw2[(size_t)n*LL + c1] : 0.f;
        unsigned hi, lo;
        split2(v0, v1, hi, lo);
        g_msh[t] = hi; g_msl[t] = lo;
    }
    if (t < LL) g_bsum[t] = mb1[t] + mb2[t];
}

// ---------------- generic rowpack (fc1 only) ------------------------------------
__global__ void pack_row_kernel(const float* __restrict__ src,
                                unsigned* __restrict__ dsth, unsigned* __restrict__ dstl,
                                int R, int K, int KP2, int lda)
{
    size_t t = (size_t)blockIdx.x * NTHREADS + threadIdx.x;
    if (t >= (size_t)R*KP2) return;
    int j = (int)(t % KP2);
    int r = (int)(t / KP2);
    int k0 = 2*j;
    float v0 = (k0     < K) ? src[(size_t)r*lda + k0]     : 0.f;
    float v1 = (k0 + 1 < K) ? src[(size_t)r*lda + k0 + 1] : 0.f;
    unsigned hi, lo;
    split2(v0, v1, hi, lo);
    dsth[t] = hi; dstl[t] = lo;
}

// ---------------- wf vertical pack ----------------------------------------------
__global__ void pack_vert_kernel(const float* __restrict__ wf)
{
    size_t t = (size_t)blockIdx.x * NTHREADS + threadIdx.x;
    if (t >= (size_t)B_*KP2_LL*NPAD_VERT) return;
    int n = (int)(t % NPAD_VERT);
    size_t r = t / NPAD_VERT;
    int kk = (int)(r % KP2_LL);
    int b  = (int)(r / KP2_LL);
    int l0 = 2*kk, l1 = 2*kk + 1;
    float v0 = 0.f, v1 = 0.f;
    if (n < FOUT) {
        const float* wb = wf + (size_t)b*LL*FOUT;
        if (l0 < LL) v0 = wb[(size_t)l0*FOUT + n];
        if (l1 < LL) v1 = wb[(size_t)l1*FOUT + n];
    }
    unsigned hi, lo;
    split2(v0, v1, hi, lo);
    g_wvh[t] = hi; g_wvl[t] = lo;
}

// ---------------- W2 partial combine + pack -> aw[8..16) ------------------------
__global__ void w2_combine_pk_kernel()
{
    size_t t = (size_t)blockIdx.x * NTHREADS + threadIdx.x;
    if (t >= (size_t)B_*LL*(FOUT/2)) return;
    int j = (int)(t % (FOUT/2));
    size_t row = t / (FOUT/2);
    float v0 = g_W2a[row*FOUT + 2*j]     + g_W2b[row*FOUT + 2*j];
    float v1 = g_W2a[row*FOUT + 2*j + 1] + g_W2b[row*FOUT + 2*j + 1];
    unsigned hi, lo;
    split2(v0, v1, hi, lo);
    size_t o = (size_t)B_*LL*KP2_FOUT + row*KP2_FOUT + j;
    g_awh[o] = hi; g_awl[o] = lo;
}

// ========= packed pair GEMM ======================================================
// MODE 0: normal (MODB: B batch = z&7).
// MODE 1: DUAL — z in {0,1}: z selects A set (Ah/Al vs Ah2/Al2), output set
//         (Cg,Ph,Pl vs Cg2,Ph2,Pl2); batch strides 0.
// MODE 2: KSPLIT — z = kh*8 + b: A shared (+koff2 pairs for kh=1), B batch b,
//         C = (kh? Cg2 : Cg) + b*sC; nchunks per kh; no pack.
template <bool BVERT, bool MODB, bool SPLIT, bool F16, int MODE>
__global__ void __launch_bounds__(256, 2) gemm_pk_kernel(
    const unsigned* __restrict__ Ahg, const unsigned* __restrict__ Alg,
    const unsigned* __restrict__ Ahg2, const unsigned* __restrict__ Alg2,
    const unsigned* __restrict__ Bhg, const unsigned* __restrict__ Blg,
    float* __restrict__ Cg, float* __restrict__ Cg2,
    unsigned* __restrict__ Ph, unsigned* __restrict__ Pl,
    unsigned* __restrict__ Ph2, unsigned* __restrict__ Pl2,
    int M, int N, int nchunks, int nchunks2, int koff2,
    int lda2, int ldb2, int ldc, int ldp2,
    long long sA2, long long sB2, long long sC, long long sP,
    const float* __restrict__ colBias)
{
    __shared__ unsigned Ah[2][8][136];
    __shared__ unsigned Bh[2][8][136];
    __shared__ unsigned Al[SPLIT ? 2 : 1][SPLIT ? 8 : 1][SPLIT ? 136 : 1];
    __shared__ unsigned Bl[SPLIT ? 2 : 1][SPLIT ? 8 : 1][SPLIT ? 136 : 1];

    const int tid = threadIdx.x;
    const int wid = tid >> 5, lane = tid & 31;
    const int wm = wid >> 2, wn = wid & 3;
    const int m_w = wm * 64, n_w = wn * 32;
    const int g = lane >> 2, tg = lane & 3;
    const int m0 = blockIdx.y * 128, n0 = blockIdx.x * 128;

    const unsigned* AHsel = Ahg;
    const unsigned* ALsel = Alg;
    float* Csel = Cg;
    unsigned* PHsel = Ph;
    unsigned* PLsel = Pl;
    long long abatch = blockIdx.z, bbatch = blockIdx.z, cbatch = blockIdx.z;
    int koff = 0, nch = nchunks;

    if (MODE == 0) {
        if (MODB) bbatch = blockIdx.z & 7;
    } else if (MODE == 1) {
        abatch = 0; bbatch = 0; cbatch = 0;
        if (blockIdx.z) { AHsel = Ahg2; ALsel = Alg2; Csel = Cg2; PHsel = Ph2; PLsel = Pl2; }
    } else { // MODE == 2
        int kh = blockIdx.z >> 3;
        int bb = blockIdx.z & 7;
        abatch = 0; bbatch = bb; cbatch = bb;
        if (kh) { koff = koff2; nch = nchunks2; Csel = Cg2; }
        PHsel = nullptr; PLsel = nullptr;
    }

    const unsigned* Ahb = AHsel + abatch * sA2;
    const unsigned* Alb = SPLIT ? (ALsel + abatch * sA2) : AHsel;
    const unsigned* Bhb = Bhg + bbatch * sB2;
    const unsigned* Blb = SPLIT ? (Blg + bbatch * sB2) : Bhg;
    float* Cb = Csel ? (Csel + cbatch * sC) : nullptr;

    float acc[4][4][4];
    #pragma unroll
    for (int i = 0; i < 4; i++)
        #pragma unroll
        for (int j = 0; j < 4; j++)
            #pragma unroll
            for (int q = 0; q < 4; q++) acc[i][j][q] = 0.f;

    const int a_c = (tid & 3) * 2;
    const int a_r = tid >> 2;
    const int bn_q = (tid & 31) * 4;
    const int bk_r = tid >> 5;

    uint2 vah[2], val[2], vbh[2], vbl[2];
    uint4 bvh, bvl;

    #define LOAD_PK(p0)                                                        \
        _Pragma("unroll")                                                      \
        for (int i = 0; i < 2; i++) {                                          \
            int gm = m0 + a_r + 64*i;                                          \
            if (gm < M) {                                                      \
                long long idx = (long long)gm*lda2 + (p0) + a_c;               \
                vah[i] = *(const uint2*)(Ahb + idx);                           \
                if (SPLIT) val[i] = *(const uint2*)(Alb + idx);                \
            } else { vah[i] = make_uint2(0,0); val[i] = make_uint2(0,0); }     \
        }                                                                      \
        if (!BVERT) {                                                          \
            _Pragma("unroll")                                                  \
            for (int i = 0; i < 2; i++) {                                      \
                int gn = n0 + a_r + 64*i;                                      \
                if (gn < N) {                                                  \
                    long long idx = (long long)gn*ldb2 + (p0) + a_c;           \
                    vbh[i] = *(const uint2*)(Bhb + idx);                       \
                    if (SPLIT) vbl[i] = *(const uint2*)(Blb + idx);            \
                } else { vbh[i] = make_uint2(0,0); vbl[i] = make_uint2(0,0); } \
            }                                                                  \
        } else {                                                               \
            long long idx = (long long)((p0) + bk_r)*ldb2 + n0 + bn_q;         \
            bvh = *(const uint4*)(Bhb + idx);                                  \
            if (SPLIT) bvl = *(const uint4*)(Blb + idx);                       \
        }
    #define STORE_PK(st)                                                       \
        _Pragma("unroll")                                                      \
        for (int i = 0; i < 2; i++) {                                          \
            int m = a_r + 64*i;                                                \
            Ah[st][a_c  ][m] = vah[i].x;  Ah[st][a_c+1][m] = vah[i].y;         \
            if (SPLIT) { Al[st][a_c  ][m] = val[i].x;                          \
                         Al[st][a_c+1][m] = val[i].y; }                        \
        }                                                                      \
        if (!BVERT) {                                                          \
            _Pragma("unroll")                                                  \
            for (int i = 0; i < 2; i++) {                                      \
                int n = a_r + 64*i;                                            \
                Bh[st][a_c  ][n] = vbh[i].x;  Bh[st][a_c+1][n] = vbh[i].y;     \
                if (SPLIT) { Bl[st][a_c  ][n] = vbl[i].x;                      \
                             Bl[st][a_c+1][n] = vbl[i].y; }                    \
            }                                                                  \
        } else {                                                               \
            *(uint4*)&Bh[st][bk_r][bn_q] = bvh;                                \
            if (SPLIT) { *(uint4*)&Bl[st][bk_r][bn_q] = bvl; }                 \
        }

    LOAD_PK(koff)
    STORE_PK(0)
    __syncthreads();

    for (int c = 0; c < nch; c++) {
        const int st = c & 1;
        if (c + 1 < nch) { LOAD_PK(koff + (c+1)*8) }
        unsigned bh0[4], bh1[4], bl0[4], bl1[4];
        #pragma unroll
        for (int nt = 0; nt < 4; nt++) {
            int n = n_w + nt*8 + g;
            bh0[nt] = Bh[st][tg  ][n];
            bh1[nt] = Bh[st][tg+4][n];
            if (SPLIT) {
                bl0[nt] = Bl[st][tg  ][n];
                bl1[nt] = Bl[st][tg+4][n];
            }
        }
        #pragma unroll
        for (int mt = 0; mt < 4; mt++) {
            int m = m_w + mt*16 + g;
            unsigned ah0 = Ah[st][tg  ][m];
            unsigned ah1 = Ah[st][tg  ][m+8];
            unsigned ah2 = Ah[st][tg+4][m];
            unsigned ah3 = Ah[st][tg+4][m+8];
            if (SPLIT) {
                unsigned al0 = Al[st][tg  ][m];
                unsigned al1 = Al[st][tg  ][m+8];
                unsigned al2 = Al[st][tg+4][m];
                unsigned al3 = Al[st][tg+4][m+8];
                #pragma unroll
                for (int nt = 0; nt < 4; nt++)
                    mma_bf16(acc[mt][nt], ah0, ah1, ah2, ah3, bh0[nt], bh1[nt]);
                #pragma unroll
                for (int nt = 0; nt < 4; nt++)
                    mma_bf16(acc[mt][nt], ah0, ah1, ah2, ah3, bl0[nt], bl1[nt]);
                #pragma unroll
                for (int nt = 0; nt < 4; nt++)
                    mma_bf16(acc[mt][nt], al0, al1, al2, al3, bh0[nt], bh1[nt]);
            } else {
                #pragma unroll
                for (int nt = 0; nt < 4; nt++) {
                    if (F16) mma_f16(acc[mt][nt], ah0, ah1, ah2, ah3, bh0[nt], bh1[nt]);
                    else     mma_bf16(acc[mt][nt], ah0, ah1, ah2, ah3, bh0[nt], bh1[nt]);
                }
            }
        }
        if (c + 1 < nch) { STORE_PK(st ^ 1) }
        __syncthreads();
    }
    #undef LOAD_PK
    #undef STORE_PK

    unsigned* Phb = PHsel ? (PHsel + cbatch * sP) : nullptr;
    unsigned* Plb = PLsel ? (PLsel + cbatch * sP) : nullptr;

    #pragma unroll
    for (int mt = 0; mt < 4; mt++) {
        #pragma unroll
        for (int nt = 0; nt < 4; nt++) {
            int r0 = m0 + m_w + mt*16 + g;
            int r1 = r0 + 8;
            int c  = n0 + n_w + nt*8 + 2*tg;
            float cb0 = (colBias && c   < N) ? colBias[c]   : 0.f;
            float cb1 = (colBias && c+1 < N) ? colBias[c+1] : 0.f;
            float v00 = acc[mt][nt][0] + cb0, v01 = acc[mt][nt][1] + cb1;
            float v10 = acc[mt][nt][2] + cb0, v11 = acc[mt][nt][3] + cb1;
            if (Cb) {
                if (r0 < M) {
                    if (c   < N) Cb[(long long)r0*ldc + c]   = v00;
                    if (c+1 < N) Cb[(long long)r0*ldc + c+1] = v01;
                }
                if (r1 < M) {
                    if (c   < N) Cb[(long long)r1*ldc + c]   = v10;
                    if (c+1 < N) Cb[(long long)r1*ldc + c+1] = v11;
                }
            }
            if (Phb && c + 1 < N) {
                int j = c >> 1;
                unsigned h, l;
                if (r0 < M) {
                    split2(v00, v01, h, l);
                    Phb[(long long)r0*ldp2 + j] = h;
                    Plb[(long long)r0*ldp2 + j] = l;
                }
                if (r1 < M) {
                    split2(v10, v11, h, l);
                    Phb[(long long)r1*ldp2 + j] = h;
                    Plb[(long long)r1*ldp2 + j] = l;
                }
            }
        }
    }
}

// ---------------- masked softmax -> Am (d_out) + fused fp16 pack ----------------
__global__ void softmax_kernel(float* __restrict__ Am)
{
    int row = blockIdx.x;
    const float* Ar = g_ATi + (size_t)row * LL;
    const float* Tr = g_ATi + (size_t)B_*LL*LL + (size_t)row * LL;
    const float bl = g_bsum[row % LL];
    int t = threadIdx.x;
    const float scale = 0.07142857142857142f;
    float v[4], mb[4];
    float mx = -INFINITY;
    #pragma unroll
    for (int i = 0; i < 4; i++) {
        int m = 4*t + i;
        v[i] = 0.f; mb[i] = 0.f;
        if (m < LL) {
            float mask = sigmoid_ref(Tr[m] + bl);
            v[i] = Ar[m] * mask * scale;
            mb[i] = (mask != 0.f) ? 1.f : 0.f;
            mx = fmaxf(mx, v[i]);
        }
    }
    __shared__ float red[NTHREADS];
    red[t] = mx; __syncthreads();
    for (int s = NTHREADS/2; s > 0; s >>= 1) {
        if (t < s) red[t] = fmaxf(red[t], red[t+s]);
        __syncthreads();
    }
    mx = red[0]; __syncthreads();
    float e[4]; float sum = 0.f;
    #pragma unroll
    for (int i = 0; i < 4; i++) {
        int m = 4*t + i;
        if (m < LL) { e[i] = expf(v[i] - mx); sum += e[i]; } else e[i] = 0.f;
    }
    red[t] = sum; __syncthreads();
    for (int s = NTHREADS/2; s > 0; s >>= 1) {
        if (t < s) red[t] += red[t+s];
        __syncthreads();
    }
    float inv = 1.f / red[0];
    float o[4];
    #pragma unroll
    for (int i = 0; i < 4; i++) {
        int m = 4*t + i;
        o[i] = e[i] * inv * mb[i];
        if (m < LL) Am[(size_t)row*LL + m] = o[i];
    }
    unsigned* amr = g_amf + (size_t)row * KP2_Y;
    if (4*t     < LL) amr[2*t]     = packf16(o[0], o[1]);
    if (4*t + 2 < LL) amr[2*t + 1] = packf16(o[2], o[3]);
}

// ---------------- fold (gather form) --------------------------------------------
__global__ void fold_kernel()
{
    size_t t = (size_t)blockIdx.x * NTHREADS + threadIdx.x;
    if (t >= (size_t)B_*CIN*Hh*Ww) return;
    int w = (int)(t % Ww); size_t r = t / Ww;
    int h = (int)(r % Hh); r /= Hh;
    int c = (int)(r % CIN);
    int b = (int)(r / CIN);
    int i0 = (h > 6) ? (h - 3) >> 2 : 0;
    int i1 = h >> 2; if (i1 > NHH - 1) i1 = NHH - 1;
    int j0 = (w > 6) ? (w - 3) >> 2 : 0;
    int j1 = w >> 2; if (j1 > NHH - 1) j1 = NHH - 1;
    float s = 0.f;
    for (int i = i0; i <= i1; i++) {
        int kh = h - i*4;
        for (int j = j0; j <= j1; j++) {
            int kw = w - j*4;
            s += g_y[((size_t)b*LL + i*NHH + j)*FV + c*49 + kh*7 + kw];
        }
    }
    g_fold[t] = s;
}

// ---------- conv c1 (3x3 refpad, leaky) + fused c2 (1x1, leaky) + residual ------
__global__ void conv_c1c2_res_kernel(const float* __restrict__ w1,
                                     const float* __restrict__ cw,
                                     const float* __restrict__ x,
                                     float* __restrict__ outp)
{
    __shared__ float sw[CI*CIN*9];
    __shared__ float sw2[CIN*CI];
    int t = threadIdx.x;
    for (int i = t; i < CI*CIN*9; i += NTHREADS) sw[i] = w1[i];
    for (int i = t; i < CIN*CI; i += NTHREADS) sw2[i] = cw[i];
    __syncthreads();
    int pix = blockIdx.x * NTHREADS + t;
    int b = blockIdx.y;
    int h = pix >> 7, w = pix & 127;
    float acc[CI];
    #pragma unroll
    for (int co = 0; co < CI; co++) acc[co] = 0.f;
    const float* xb = g_fold + (size_t)b * CIN * Hh * Ww;
    for (int ci = 0; ci < CIN; ci++) {
        float v[9];
        #pragma unroll
        for (int dh = 0; dh < 3; dh++) {
            int hh = h + dh - 1;
            hh = hh < 0 ? 1 : (hh >= Hh ? Hh - 2 : hh);
            #pragma unroll
            for (int dw = 0; dw < 3; dw++) {
                int w2p = w + dw - 1;
                w2p = w2p < 0 ? 1 : (w2p >= Ww ? Ww - 2 : w2p);
                v[dh*3 + dw] = xb[(ci*Hh + hh)*Ww + w2p];
            }
        }
        #pragma unroll
        for (int co = 0; co < CI; co++) {
            const float* p1 = &sw[(co*CIN + ci)*9];
            float s1 = 0.f;
            #pragma unroll
            for (int k = 0; k < 9; k++) s1 += p1[k]*v[k];
            acc[co] += s1;
        }
    }
    #pragma unroll
    for (int co = 0; co < CI; co++)
        acc[co] = (acc[co] > 0.f) ? acc[co] : 0.2f*acc[co];
    #pragma unroll
    for (int co = 0; co < CIN; co++) {
        float s = 0.f;
        #pragma unroll
        for (int ci = 0; ci < CI; ci++) s += sw2[co*CI + ci]*acc[ci];
        s = (s > 0.f) ? s : 0.2f*s;
        size_t idx = ((size_t)b*CIN + co)*Hh*Ww + pix;
        outp[idx] = x[idx] + s;
    }
}

// ---------------- launch -----------------------------------------------------------
extern "C" void kernel_launch(void* const* d_in, const int* in_sizes, int n_in,
                              void* d_out, int out_size)
{
    const float* x        = (const float*)d_in[0];
    const float* g_w      = (const float*)d_in[1];
    const float* g_b      = (const float*)d_in[2];
    const float* w_w      = (const float*)d_in[3];
    const float* w_b      = (const float*)d_in[4];
    const float* theta_w  = (const float*)d_in[5];
    const float* theta_b  = (const float*)d_in[6];
    const float* fc1_w    = (const float*)d_in[7];
    const float* fc1_b    = (const float*)d_in[8];
    const float* mconv_w  = (const float*)d_in[9];
    const float* mconv_b  = (const float*)d_in[10];
    const float* mfc_w    = (const float*)d_in[11];
    const float* mfc_b    = (const float*)d_in[12];
    const float* c1_w     = (const float*)d_in[13];
    const float* c2_w     = (const float*)d_in[14];
    float* out = (float*)d_out;

    float *pwf, *pW2a, *pW2b, *pATi, *py;
    unsigned *pp4h, *pp4l, *pp6h, *pp6l, *pfc1h, *pfc1l,
             *pawh, *pawl, *pxfh, *pxfl, *pwvh, *pwvl, *pmsh, *pmsl,
             *pamf, *pptf;
    cudaGetSymbolAddress((void**)&pwf,  g_wf);
    cudaGetSymbolAddress((void**)&pW2a, g_W2a);
    cudaGetSymbolAddress((void**)&pW2b, g_W2b);
    cudaGetSymbolAddress((void**)&pATi, g_ATi);
    cudaGetSymbolAddress((void**)&py,   g_y);
    cudaGetSymbolAddress((void**)&pp4h, g_p4h);
    cudaGetSymbolAddress((void**)&pp4l, g_p4l);
    cudaGetSymbolAddress((void**)&pp6h, g_p6h);
    cudaGetSymbolAddress((void**)&pp6l, g_p6l);
    cudaGetSymbolAddress((void**)&pfc1h,g_fc1h);
    cudaGetSymbolAddress((void**)&pfc1l,g_fc1l);
    cudaGetSymbolAddress((void**)&pawh, g_awh);
    cudaGetSymbolAddress((void**)&pawl, g_awl);
    cudaGetSymbolAddress((void**)&pxfh, g_xfh);
    cudaGetSymbolAddress((void**)&pxfl, g_xfl);
    cudaGetSymbolAddress((void**)&pwvh, g_wvh);
    cudaGetSymbolAddress((void**)&pwvl, g_wvl);
    cudaGetSymbolAddress((void**)&pmsh, g_msh);
    cudaGetSymbolAddress((void**)&pmsl, g_msl);
    cudaGetSymbolAddress((void**)&pamf, g_amf);
    cudaGetSymbolAddress((void**)&pptf, g_ptf);

    dim3 convGrid(Hh*Ww/NTHREADS, B_);
    #define GBLK(n) ((int)(((size_t)(n) + NTHREADS - 1) / NTHREADS))

    conv3x3_dual_theta_kernel<<<convGrid, NTHREADS>>>(x, g_w, g_b, w_w, w_b,
                                                      theta_w, theta_b);

    unfold_pk2_kernel<<<GBLK((size_t)B_*LL*KP2_FIN), NTHREADS>>>();
    unfold_p62t_f16_kernel<<<GBLK((size_t)B_*FV*KP2_Y), NTHREADS>>>();

    msum_pk_kernel<<<GBLK((size_t)LL*KP2_LL), NTHREADS>>>(mconv_w, mfc_w, mconv_b, mfc_b);
    pack_row_kernel<<<GBLK((size_t)FOUT*KP2_FIN), NTHREADS>>>(fc1_w, pfc1h, pfc1l,
                                                              FOUT, FIN, KP2_FIN, FIN);

    // DUAL: z0 -> wf (fp32 + pack aw[0..8)); z1 -> xf (pack only)
    {
        dim3 g((FOUT + 127)/128, (B_*LL + 127)/128, 2);
        gemm_pk_kernel<false,false,true,false,1><<<g, 256>>>(
            pp4h, pp4l, pp6h, pp6l, pfc1h, pfc1l,
            pwf, nullptr, pawh, pawl, pxfh, pxfl,
            B_*LL, FOUT, FIN/16, 0, 0,
            KP2_FIN, KP2_FIN, FOUT, KP2_FOUT,
            0, 0, 0, 0, fc1_b);
    }

    pack_vert_kernel<<<GBLK((size_t)B_*KP2_LL*NPAD_VERT), NTHREADS>>>(pwf);

    // W2 KSPLIT: z = kh*8 + b; kh0: chunks 0..30, kh1: chunks 31..60
    {
        dim3 g((FOUT + 127)/128, (LL + 127)/128, 2*B_);
        gemm_pk_kernel<true,false,true,false,2><<<g, 256>>>(
            pmsh, pmsl, nullptr, nullptr, pwvh, pwvl,
            pW2a, pW2b, nullptr, nullptr, nullptr, nullptr,
            LL, FOUT, 31, 30, 248,
            KP2_LL, NPAD_VERT, FOUT, 0,
            0, (long long)KP2_LL*NPAD_VERT, (long long)LL*FOUT, 0,
            nullptr);
    }
    w2_combine_pk_kernel<<<GBLK((size_t)B_*LL*(FOUT/2)), NTHREADS>>>();

    // Batched A / Ti (bf16x3)
    {
        dim3 g((LL + 127)/128, (LL + 127)/128, 2*B_);
        gemm_pk_kernel<false,true,true,false,0><<<g, 256>>>(
            pawh, pawl, nullptr, nullptr, pxfh, pxfl,
            pATi, nullptr, nullptr, nullptr, nullptr, nullptr,
            LL, LL, 13, 0, 0,
            KP2_FOUT, KP2_FOUT, LL, 0,
            (long long)LL*KP2_FOUT, (long long)LL*KP2_FOUT,
            (long long)LL*LL, 0, nullptr);
    }

    softmax_kernel<<<B_*LL, NTHREADS>>>(out);

    // y[b] = Am[b] @ p62[b]  — single-pass fp16
    {
        dim3 g((FV + 127)/128, (LL + 127)/128, B_);
        gemm_pk_kernel<false,false,false,true,0><<<g, 256>>>(
            pamf, nullptr, nullptr, nullptr, pptf, nullptr,
            py, nullptr, nullptr, nullptr, nullptr, nullptr,
            LL, FV, 61, 0, 0,
            KP2_Y, KP2_Y, FV, 0,
            (long long)LL*KP2_Y, (long long)FV*KP2_Y,
            (long long)LL*FV, 0, nullptr);
    }

    fold_kernel<<<GBLK((size_t)B_*CIN*Hh*Ww), NTHREADS>>>();
    conv_c1c2_res_kernel<<<convGrid, NTHREADS>>>(c1_w, c2_w, x, out + (size_t)B_*LL*LL);
    #undef GBLK
}

// round 17
// speedup vs baseline: 2.6939x; 1.0429x over previous
#include <cuda_runtime.h>
#include <cstdint>
#include <math.h>
#include <float.h>

#define B_   8
#define CIN  32
#define CI   16
#define Hh   128
#define Ww   128
#define NHH  31
#define LL   961
#define FIN  784
#define FOUT 196
#define FV   1568
#define NTHREADS 256

#define KP2_FIN   392
#define KP2_FOUT  104
#define KP2_LL    488
#define NPAD_VERT 256
#define KP2_Y     488

// ---------------- scratch (device globals) ------------------------------------
__device__ float    g_x1[(size_t)B_*CI*Hh*Ww];
__device__ float    g_x2[(size_t)B_*CI*Hh*Ww];
__device__ float    g_x3[(size_t)B_*CIN*Hh*Ww];
__device__ unsigned g_p4h[(size_t)B_*LL*KP2_FIN], g_p4l[(size_t)B_*LL*KP2_FIN];
__device__ unsigned g_p6h[(size_t)B_*LL*KP2_FIN], g_p6l[(size_t)B_*LL*KP2_FIN];
__device__ unsigned g_fc1h[(size_t)FOUT*KP2_FIN], g_fc1l[(size_t)FOUT*KP2_FIN];
__device__ float    g_wf[(size_t)B_*LL*FOUT];
__device__ float    g_W2a[(size_t)B_*LL*FOUT];
__device__ float    g_W2b[(size_t)B_*LL*FOUT];
__device__ unsigned g_awh[(size_t)2*B_*LL*KP2_FOUT], g_awl[(size_t)2*B_*LL*KP2_FOUT];
__device__ unsigned g_xfh[(size_t)B_*LL*KP2_FOUT],   g_xfl[(size_t)B_*LL*KP2_FOUT];
__device__ unsigned g_wvh[(size_t)B_*KP2_LL*NPAD_VERT], g_wvl[(size_t)B_*KP2_LL*NPAD_VERT];
__device__ unsigned g_msh[(size_t)LL*KP2_LL], g_msl[(size_t)LL*KP2_LL];
__device__ float    g_bsum[LL];
__device__ float    g_ATi[(size_t)2*B_*LL*LL];
__device__ unsigned g_amf[(size_t)B_*LL*KP2_Y];
__device__ unsigned g_ptf[(size_t)B_*FV*KP2_Y];
__device__ float    g_y[(size_t)B_*LL*FV];
__device__ float    g_fold[(size_t)B_*CIN*Hh*Ww];

static __device__ __forceinline__ float sigmoid_ref(float x) {
    if (x >= 0.f) return 1.f / (1.f + expf(-x));
    float e = expf(x);
    if (e < FLT_MIN) e = 0.f;
    return e / (1.f + e);
}

// =================== pack / mma helpers ========================================
__device__ __forceinline__ unsigned packbf(float x, float y) {
    unsigned r;
    asm("cvt.rn.bf16x2.f32 %0, %1, %2;" : "=r"(r) : "f"(y), "f"(x));
    return r;
}
__device__ __forceinline__ unsigned packf16(float x, float y) {
    unsigned r;
    asm("cvt.rn.f16x2.f32 %0, %1, %2;" : "=r"(r) : "f"(y), "f"(x));
    return r;
}
__device__ __forceinline__ void split2(float x, float y, unsigned& hi, unsigned& lo) {
    hi = packbf(x, y);
    float hx = __uint_as_float(hi << 16);
    float hy = __uint_as_float(hi & 0xFFFF0000u);
    lo = packbf(x - hx, y - hy);
}
__device__ __forceinline__ void mma_bf16(float c[4],
    unsigned a0, unsigned a1, unsigned a2, unsigned a3, unsigned b0, unsigned b1)
{
    asm volatile("mma.sync.aligned.m16n8k16.row.col.f32.bf16.bf16.f32 "
        "{%0,%1,%2,%3}, {%4,%5,%6,%7}, {%8,%9}, {%0,%1,%2,%3};"
        : "+f"(c[0]), "+f"(c[1]), "+f"(c[2]), "+f"(c[3])
        : "r"(a0), "r"(a1), "r"(a2), "r"(a3), "r"(b0), "r"(b1));
}
__device__ __forceinline__ void mma_f16(float c[4],
    unsigned a0, unsigned a1, unsigned a2, unsigned a3, unsigned b0, unsigned b1)
{
    asm volatile("mma.sync.aligned.m16n8k16.row.col.f32.f16.f16.f32 "
        "{%0,%1,%2,%3}, {%4,%5,%6,%7}, {%8,%9}, {%0,%1,%2,%3};"
        : "+f"(c[0]), "+f"(c[1]), "+f"(c[2]), "+f"(c[3])
        : "r"(a0), "r"(a1), "r"(a2), "r"(a3), "r"(b0), "r"(b1));
}

// ---------- conv: refpad 3x3 (x1,x2) + fused 1x1 theta (x3) --------------------
__global__ void conv3x3_dual_theta_kernel(const float* __restrict__ x,
                                          const float* __restrict__ w1, const float* __restrict__ b1,
                                          const float* __restrict__ w2, const float* __restrict__ b2,
                                          const float* __restrict__ tw, const float* __restrict__ tb)
{
    __shared__ float sw1[CI*CIN*9];
    __shared__ float sw2[CI*CIN*9];
    __shared__ float swt[CIN*CI];
    int t = threadIdx.x;
    for (int i = t; i < CI*CIN*9; i += NTHREADS) { sw1[i] = w1[i]; sw2[i] = w2[i]; }
    for (int i = t; i < CIN*CI; i += NTHREADS) swt[i] = tw[i];
    __syncthreads();
    int pix = blockIdx.x * NTHREADS + t;
    int b = blockIdx.y;
    int h = pix >> 7, w = pix & 127;
    float acc1[CI], acc2[CI];
    #pragma unroll
    for (int co = 0; co < CI; co++) { acc1[co] = b1[co]; acc2[co] = b2[co]; }
    const float* xb = x + (size_t)b * CIN * Hh * Ww;
    for (int ci = 0; ci < CIN; ci++) {
        float v[9];
        #pragma unroll
        for (int dh = 0; dh < 3; dh++) {
            int hh = h + dh - 1;
            hh = hh < 0 ? 1 : (hh >= Hh ? Hh - 2 : hh);
            #pragma unroll
            for (int dw = 0; dw < 3; dw++) {
                int w2p = w + dw - 1;
                w2p = w2p < 0 ? 1 : (w2p >= Ww ? Ww - 2 : w2p);
                v[dh*3 + dw] = xb[(ci*Hh + hh)*Ww + w2p];
            }
        }
        #pragma unroll
        for (int co = 0; co < CI; co++) {
            const float* p1 = &sw1[(co*CIN + ci)*9];
            const float* p2 = &sw2[(co*CIN + ci)*9];
            float s1 = 0.f, s2 = 0.f;
            #pragma unroll
            for (int k = 0; k < 9; k++) { s1 += p1[k]*v[k]; s2 += p2[k]*v[k]; }
            acc1[co] += s1; acc2[co] += s2;
        }
    }
    size_t base16 = (size_t)b * CI * Hh * Ww + pix;
    #pragma unroll
    for (int co = 0; co < CI; co++) {
        g_x1[base16 + (size_t)co*Hh*Ww] = acc1[co];
        g_x2[base16 + (size_t)co*Hh*Ww] = acc2[co];
    }
    size_t base32 = (size_t)b * CIN * Hh * Ww + pix;
    #pragma unroll
    for (int co = 0; co < CIN; co++) {
        float s = tb[co];
        #pragma unroll
        for (int ci = 0; ci < CI; ci++) s += swt[co*CI + ci]*acc1[ci];
        g_x3[base32 + (size_t)co*Hh*Ww] = s;
    }
}

// ------- fused unfold + split-pack, 4 elems (2 pairs) per thread ---------------
__global__ void unfold_pk2_kernel()
{
    size_t t = (size_t)blockIdx.x * NTHREADS + threadIdx.x;
    if (t >= (size_t)B_*LL*(KP2_FIN/2)) return;
    int q = (int)(t % (KP2_FIN/2));
    size_t r = t / (KP2_FIN/2);
    int l = (int)(r % LL);
    int b = (int)(r / LL);
    int hb = (l / NHH)*4, wb = (l % NHH)*4;
    float v4[4], v6[4];
    #pragma unroll
    for (int i = 0; i < 4; i++) {
        int f = 4*q + i;
        int c = f / 49, rr = f % 49, kh = rr / 7, kw = rr % 7;
        size_t idx = (((size_t)b*CI + c)*Hh + hb + kh)*Ww + wb + kw;
        v4[i] = g_x2[idx];
        v6[i] = g_x1[idx];
    }
    uint2 h2, l2;
    split2(v4[0], v4[1], h2.x, l2.x);
    split2(v4[2], v4[3], h2.y, l2.y);
    *(uint2*)(g_p4h + 2*t) = h2;
    *(uint2*)(g_p4l + 2*t) = l2;
    split2(v6[0], v6[1], h2.x, l2.x);
    split2(v6[2], v6[3], h2.y, l2.y);
    *(uint2*)(g_p6h + 2*t) = h2;
    *(uint2*)(g_p6l + 2*t) = l2;
}

// ---------------- p62^T fp16 pack, 4 l-values per thread -----------------------
__global__ void unfold_p62t_f16_kernel()
{
    size_t t = (size_t)blockIdx.x * NTHREADS + threadIdx.x;
    if (t >= (size_t)B_*FV*(KP2_Y/2)) return;
    int j2 = (int)(t % (KP2_Y/2));
    size_t r = t / (KP2_Y/2);
    int f = (int)(r % FV);
    int b = (int)(r / FV);
    int c = f / 49, rr = f % 49, kh = rr / 7, kw = rr % 7;
    const float* src = g_x3 + ((size_t)b*CIN + c)*Hh*Ww;
    float v[4] = {0.f, 0.f, 0.f, 0.f};
    #pragma unroll
    for (int i = 0; i < 4; i++) {
        int l = 4*j2 + i;
        if (l < LL) {
            int h = (l / NHH)*4 + kh, w = (l % NHH)*4 + kw;
            v[i] = src[(size_t)h*Ww + w];
        }
    }
    uint2 p;
    p.x = packf16(v[0], v[1]);
    p.y = packf16(v[2], v[3]);
    *(uint2*)(g_ptf + r*KP2_Y + 2*j2) = p;
}

// ------- merged: Msum split-pack + bsum + fc1 rowpack ---------------------------
#define MS_TOT  ((size_t)LL*KP2_LL)
#define FC_TOT  ((size_t)FOUT*KP2_FIN)
__global__ void msum_fc1_pk_kernel(const float* __restrict__ mw1, const float* __restrict__ mw2,
                                   const float* __restrict__ mb1, const float* __restrict__ mb2,
                                   const float* __restrict__ fc1)
{
    size_t t = (size_t)blockIdx.x * NTHREADS + threadIdx.x;
    if (t < MS_TOT) {
        int j = (int)(t % KP2_LL);
        int n = (int)(t / KP2_LL);
        int c0 = 2*j, c1 = 2*j + 1;
        float v0 = (c0 < LL) ? mw1[(size_t)n*LL + c0] + mw2[(size_t)n*LL + c0] : 0.f;
        float v1 = (c1 < LL) ? mw1[(size_t)n*LL + c1] + mw2[(size_t)n*LL + c1] : 0.f;
        unsigned hi, lo;
        split2(v0, v1, hi, lo);
        g_msh[t] = hi; g_msl[t] = lo;
    } else if (t < MS_TOT + FC_TOT) {
        size_t u = t - MS_TOT;
        int j = (int)(u % KP2_FIN);
        int rr = (int)(u / KP2_FIN);
        int k0 = 2*j;
        float v0 = (k0     < FIN) ? fc1[(size_t)rr*FIN + k0]     : 0.f;
        float v1 = (k0 + 1 < FIN) ? fc1[(size_t)rr*FIN + k0 + 1] : 0.f;
        unsigned hi, lo;
        split2(v0, v1, hi, lo);
        g_fc1h[u] = hi; g_fc1l[u] = lo;
    }
    if (t < LL) g_bsum[t] = mb1[t] + mb2[t];
}

// ---------------- wf vertical pack ----------------------------------------------
__global__ void pack_vert_kernel(const float* __restrict__ wf)
{
    size_t t = (size_t)blockIdx.x * NTHREADS + threadIdx.x;
    if (t >= (size_t)B_*KP2_LL*NPAD_VERT) return;
    int n = (int)(t % NPAD_VERT);
    size_t r = t / NPAD_VERT;
    int kk = (int)(r % KP2_LL);
    int b  = (int)(r / KP2_LL);
    int l0 = 2*kk, l1 = 2*kk + 1;
    float v0 = 0.f, v1 = 0.f;
    if (n < FOUT) {
        const float* wb = wf + (size_t)b*LL*FOUT;
        if (l0 < LL) v0 = wb[(size_t)l0*FOUT + n];
        if (l1 < LL) v1 = wb[(size_t)l1*FOUT + n];
    }
    unsigned hi, lo;
    split2(v0, v1, hi, lo);
    g_wvh[t] = hi; g_wvl[t] = lo;
}

// ---------------- W2 partial combine + pack -> aw[8..16) ------------------------
__global__ void w2_combine_pk_kernel()
{
    size_t t = (size_t)blockIdx.x * NTHREADS + threadIdx.x;
    if (t >= (size_t)B_*LL*(FOUT/2)) return;
    int j = (int)(t % (FOUT/2));
    size_t row = t / (FOUT/2);
    float v0 = g_W2a[row*FOUT + 2*j]     + g_W2b[row*FOUT + 2*j];
    float v1 = g_W2a[row*FOUT + 2*j + 1] + g_W2b[row*FOUT + 2*j + 1];
    unsigned hi, lo;
    split2(v0, v1, hi, lo);
    size_t o = (size_t)B_*LL*KP2_FOUT + row*KP2_FOUT + j;
    g_awh[o] = hi; g_awl[o] = lo;
}

// ========= packed pair GEMM (unchanged) ==========================================
template <bool BVERT, bool MODB, bool SPLIT, bool F16, int MODE>
__global__ void __launch_bounds__(256, 2) gemm_pk_kernel(
    const unsigned* __restrict__ Ahg, const unsigned* __restrict__ Alg,
    const unsigned* __restrict__ Ahg2, const unsigned* __restrict__ Alg2,
    const unsigned* __restrict__ Bhg, const unsigned* __restrict__ Blg,
    float* __restrict__ Cg, float* __restrict__ Cg2,
    unsigned* __restrict__ Ph, unsigned* __restrict__ Pl,
    unsigned* __restrict__ Ph2, unsigned* __restrict__ Pl2,
    int M, int N, int nchunks, int nchunks2, int koff2,
    int lda2, int ldb2, int ldc, int ldp2,
    long long sA2, long long sB2, long long sC, long long sP,
    const float* __restrict__ colBias)
{
    __shared__ unsigned Ah[2][8][136];
    __shared__ unsigned Bh[2][8][136];
    __shared__ unsigned Al[SPLIT ? 2 : 1][SPLIT ? 8 : 1][SPLIT ? 136 : 1];
    __shared__ unsigned Bl[SPLIT ? 2 : 1][SPLIT ? 8 : 1][SPLIT ? 136 : 1];

    const int tid = threadIdx.x;
    const int wid = tid >> 5, lane = tid & 31;
    const int wm = wid >> 2, wn = wid & 3;
    const int m_w = wm * 64, n_w = wn * 32;
    const int g = lane >> 2, tg = lane & 3;
    const int m0 = blockIdx.y * 128, n0 = blockIdx.x * 128;

    const unsigned* AHsel = Ahg;
    const unsigned* ALsel = Alg;
    float* Csel = Cg;
    unsigned* PHsel = Ph;
    unsigned* PLsel = Pl;
    long long abatch = blockIdx.z, bbatch = blockIdx.z, cbatch = blockIdx.z;
    int koff = 0, nch = nchunks;

    if (MODE == 0) {
        if (MODB) bbatch = blockIdx.z & 7;
    } else if (MODE == 1) {
        abatch = 0; bbatch = 0; cbatch = 0;
        if (blockIdx.z) { AHsel = Ahg2; ALsel = Alg2; Csel = Cg2; PHsel = Ph2; PLsel = Pl2; }
    } else {
        int kh = blockIdx.z >> 3;
        int bb = blockIdx.z & 7;
        abatch = 0; bbatch = bb; cbatch = bb;
        if (kh) { koff = koff2; nch = nchunks2; Csel = Cg2; }
        PHsel = nullptr; PLsel = nullptr;
    }

    const unsigned* Ahb = AHsel + abatch * sA2;
    const unsigned* Alb = SPLIT ? (ALsel + abatch * sA2) : AHsel;
    const unsigned* Bhb = Bhg + bbatch * sB2;
    const unsigned* Blb = SPLIT ? (Blg + bbatch * sB2) : Bhg;
    float* Cb = Csel ? (Csel + cbatch * sC) : nullptr;

    float acc[4][4][4];
    #pragma unroll
    for (int i = 0; i < 4; i++)
        #pragma unroll
        for (int j = 0; j < 4; j++)
            #pragma unroll
            for (int q = 0; q < 4; q++) acc[i][j][q] = 0.f;

    const int a_c = (tid & 3) * 2;
    const int a_r = tid >> 2;
    const int bn_q = (tid & 31) * 4;
    const int bk_r = tid >> 5;

    uint2 vah[2], val[2], vbh[2], vbl[2];
    uint4 bvh, bvl;

    #define LOAD_PK(p0)                                                        \
        _Pragma("unroll")                                                      \
        for (int i = 0; i < 2; i++) {                                          \
            int gm = m0 + a_r + 64*i;                                          \
            if (gm < M) {                                                      \
                long long idx = (long long)gm*lda2 + (p0) + a_c;               \
                vah[i] = *(const uint2*)(Ahb + idx);                           \
                if (SPLIT) val[i] = *(const uint2*)(Alb + idx);                \
            } else { vah[i] = make_uint2(0,0); val[i] = make_uint2(0,0); }     \
        }                                                                      \
        if (!BVERT) {                                                          \
            _Pragma("unroll")                                                  \
            for (int i = 0; i < 2; i++) {                                      \
                int gn = n0 + a_r + 64*i;                                      \
                if (gn < N) {                                                  \
                    long long idx = (long long)gn*ldb2 + (p0) + a_c;           \
                    vbh[i] = *(const uint2*)(Bhb + idx);                       \
                    if (SPLIT) vbl[i] = *(const uint2*)(Blb + idx);            \
                } else { vbh[i] = make_uint2(0,0); vbl[i] = make_uint2(0,0); } \
            }                                                                  \
        } else {                                                               \
            long long idx = (long long)((p0) + bk_r)*ldb2 + n0 + bn_q;         \
            bvh = *(const uint4*)(Bhb + idx);                                  \
            if (SPLIT) bvl = *(const uint4*)(Blb + idx);                       \
        }
    #define STORE_PK(st)                                                       \
        _Pragma("unroll")                                                      \
        for (int i = 0; i < 2; i++) {                                          \
            int m = a_r + 64*i;                                                \
            Ah[st][a_c  ][m] = vah[i].x;  Ah[st][a_c+1][m] = vah[i].y;         \
            if (SPLIT) { Al[st][a_c  ][m] = val[i].x;                          \
                         Al[st][a_c+1][m] = val[i].y; }                        \
        }                                                                      \
        if (!BVERT) {                                                          \
            _Pragma("unroll")                                                  \
            for (int i = 0; i < 2; i++) {                                      \
                int n = a_r + 64*i;                                            \
                Bh[st][a_c  ][n] = vbh[i].x;  Bh[st][a_c+1][n] = vbh[i].y;     \
                if (SPLIT) { Bl[st][a_c  ][n] = vbl[i].x;                      \
                             Bl[st][a_c+1][n] = vbl[i].y; }                    \
            }                                                                  \
        } else {                                                               \
            *(uint4*)&Bh[st][bk_r][bn_q] = bvh;                                \
            if (SPLIT) { *(uint4*)&Bl[st][bk_r][bn_q] = bvl; }                 \
        }

    LOAD_PK(koff)
    STORE_PK(0)
    __syncthreads();

    for (int c = 0; c < nch; c++) {
        const int st = c & 1;
        if (c + 1 < nch) { LOAD_PK(koff + (c+1)*8) }
        unsigned bh0[4], bh1[4], bl0[4], bl1[4];
        #pragma unroll
        for (int nt = 0; nt < 4; nt++) {
            int n = n_w + nt*8 + g;
            bh0[nt] = Bh[st][tg  ][n];
            bh1[nt] = Bh[st][tg+4][n];
            if (SPLIT) {
                bl0[nt] = Bl[st][tg  ][n];
                bl1[nt] = Bl[st][tg+4][n];
            }
        }
        #pragma unroll
        for (int mt = 0; mt < 4; mt++) {
            int m = m_w + mt*16 + g;
            unsigned ah0 = Ah[st][tg  ][m];
            unsigned ah1 = Ah[st][tg  ][m+8];
            unsigned ah2 = Ah[st][tg+4][m];
            unsigned ah3 = Ah[st][tg+4][m+8];
            if (SPLIT) {
                unsigned al0 = Al[st][tg  ][m];
                unsigned al1 = Al[st][tg  ][m+8];
                unsigned al2 = Al[st][tg+4][m];
                unsigned al3 = Al[st][tg+4][m+8];
                #pragma unroll
                for (int nt = 0; nt < 4; nt++)
                    mma_bf16(acc[mt][nt], ah0, ah1, ah2, ah3, bh0[nt], bh1[nt]);
                #pragma unroll
                for (int nt = 0; nt < 4; nt++)
                    mma_bf16(acc[mt][nt], ah0, ah1, ah2, ah3, bl0[nt], bl1[nt]);
                #pragma unroll
                for (int nt = 0; nt < 4; nt++)
                    mma_bf16(acc[mt][nt], al0, al1, al2, al3, bh0[nt], bh1[nt]);
            } else {
                #pragma unroll
                for (int nt = 0; nt < 4; nt++) {
                    if (F16) mma_f16(acc[mt][nt], ah0, ah1, ah2, ah3, bh0[nt], bh1[nt]);
                    else     mma_bf16(acc[mt][nt], ah0, ah1, ah2, ah3, bh0[nt], bh1[nt]);
                }
            }
        }
        if (c + 1 < nch) { STORE_PK(st ^ 1) }
        __syncthreads();
    }
    #undef LOAD_PK
    #undef STORE_PK

    unsigned* Phb = PHsel ? (PHsel + cbatch * sP) : nullptr;
    unsigned* Plb = PLsel ? (PLsel + cbatch * sP) : nullptr;

    #pragma unroll
    for (int mt = 0; mt < 4; mt++) {
        #pragma unroll
        for (int nt = 0; nt < 4; nt++) {
            int r0 = m0 + m_w + mt*16 + g;
            int r1 = r0 + 8;
            int c  = n0 + n_w + nt*8 + 2*tg;
            float cb0 = (colBias && c   < N) ? colBias[c]   : 0.f;
            float cb1 = (colBias && c+1 < N) ? colBias[c+1] : 0.f;
            float v00 = acc[mt][nt][0] + cb0, v01 = acc[mt][nt][1] + cb1;
            float v10 = acc[mt][nt][2] + cb0, v11 = acc[mt][nt][3] + cb1;
            if (Cb) {
                if (r0 < M) {
                    if (c   < N) Cb[(long long)r0*ldc + c]   = v00;
                    if (c+1 < N) Cb[(long long)r0*ldc + c+1] = v01;
                }
                if (r1 < M) {
                    if (c   < N) Cb[(long long)r1*ldc + c]   = v10;
                    if (c+1 < N) Cb[(long long)r1*ldc + c+1] = v11;
                }
            }
            if (Phb && c + 1 < N) {
                int j = c >> 1;
                unsigned h, l;
                if (r0 < M) {
                    split2(v00, v01, h, l);
                    Phb[(long long)r0*ldp2 + j] = h;
                    Plb[(long long)r0*ldp2 + j] = l;
                }
                if (r1 < M) {
                    split2(v10, v11, h, l);
                    Phb[(long long)r1*ldp2 + j] = h;
                    Plb[(long long)r1*ldp2 + j] = l;
                }
            }
        }
    }
}

// -------- masked softmax -> Am (d_out) + fused fp16 pack (shuffle reductions) ---
__global__ void softmax_kernel(float* __restrict__ Am)
{
    int row = blockIdx.x;
    const float* Ar = g_ATi + (size_t)row * LL;
    const float* Tr = g_ATi + (size_t)B_*LL*LL + (size_t)row * LL;
    const float bl = g_bsum[row % LL];
    int t = threadIdx.x;
    const int lane = t & 31, warp = t >> 5;
    const float scale = 0.07142857142857142f;
    float v[4], mb[4];
    float mx = -INFINITY;
    #pragma unroll
    for (int i = 0; i < 4; i++) {
        int m = 4*t + i;
        v[i] = 0.f; mb[i] = 0.f;
        if (m < LL) {
            float mask = sigmoid_ref(Tr[m] + bl);
            v[i] = Ar[m] * mask * scale;
            mb[i] = (mask != 0.f) ? 1.f : 0.f;
            mx = fmaxf(mx, v[i]);
        }
    }
    __shared__ float red[8];
    #pragma unroll
    for (int s = 16; s > 0; s >>= 1)
        mx = fmaxf(mx, __shfl_xor_sync(0xFFFFFFFFu, mx, s));
    if (lane == 0) red[warp] = mx;
    __syncthreads();
    {
        float m8 = red[lane & 7];
        #pragma unroll
        for (int s = 4; s > 0; s >>= 1)
            m8 = fmaxf(m8, __shfl_xor_sync(0xFFFFFFFFu, m8, s));
        mx = m8;
    }
    float e[4]; float sum = 0.f;
    #pragma unroll
    for (int i = 0; i < 4; i++) {
        int m = 4*t + i;
        if (m < LL) { e[i] = expf(v[i] - mx); sum += e[i]; } else e[i] = 0.f;
    }
    #pragma unroll
    for (int s = 16; s > 0; s >>= 1)
        sum += __shfl_xor_sync(0xFFFFFFFFu, sum, s);
    __syncthreads();
    if (lane == 0) red[warp] = sum;
    __syncthreads();
    {
        float s8 = red[lane & 7];
        #pragma unroll
        for (int s = 4; s > 0; s >>= 1)
            s8 += __shfl_xor_sync(0xFFFFFFFFu, s8, s);
        sum = s8;   // xor{4,2,1} reduces each aligned 8-lane group holding red[0..7] once each
    }
    float inv = 1.f / sum;
    float o[4];
    #pragma unroll
    for (int i = 0; i < 4; i++) {
        int m = 4*t + i;
        o[i] = e[i] * inv * mb[i];
        if (m < LL) Am[(size_t)row*LL + m] = o[i];
    }
    unsigned* amr = g_amf + (size_t)row * KP2_Y;
    if (4*t     < LL) amr[2*t]     = packf16(o[0], o[1]);
    if (4*t + 2 < LL) amr[2*t + 1] = packf16(o[2], o[3]);
}

// ---------------- fold (gather form) --------------------------------------------
__global__ void fold_kernel()
{
    size_t t = (size_t)blockIdx.x * NTHREADS + threadIdx.x;
    if (t >= (size_t)B_*CIN*Hh*Ww) return;
    int w = (int)(t % Ww); size_t r = t / Ww;
    int h = (int)(r % Hh); r /= Hh;
    int c = (int)(r % CIN);
    int b = (int)(r / CIN);
    int i0 = (h > 6) ? (h - 3) >> 2 : 0;
    int i1 = h >> 2; if (i1 > NHH - 1) i1 = NHH - 1;
    int j0 = (w > 6) ? (w - 3) >> 2 : 0;
    int j1 = w >> 2; if (j1 > NHH - 1) j1 = NHH - 1;
    float s = 0.f;
    for (int i = i0; i <= i1; i++) {
        int kh = h - i*4;
        for (int j = j0; j <= j1; j++) {
            int kw = w - j*4;
            s += g_y[((size_t)b*LL + i*NHH + j)*FV + c*49 + kh*7 + kw];
        }
    }
    g_fold[t] = s;
}

// ---------- conv c1 (3x3 refpad, leaky) + fused c2 (1x1, leaky) + residual ------
__global__ void conv_c1c2_res_kernel(const float* __restrict__ w1,
                                     const float* __restrict__ cw,
                                     const float* __restrict__ x,
                                     float* __restrict__ outp)
{
    __shared__ float sw[CI*CIN*9];
    __shared__ float sw2[CIN*CI];
    int t = threadIdx.x;
    for (int i = t; i < CI*CIN*9; i += NTHREADS) sw[i] = w1[i];
    for (int i = t; i < CIN*CI; i += NTHREADS) sw2[i] = cw[i];
    __syncthreads();
    int pix = blockIdx.x * NTHREADS + t;
    int b = blockIdx.y;
    int h = pix >> 7, w = pix & 127;
    float acc[CI];
    #pragma unroll
    for (int co = 0; co < CI; co++) acc[co] = 0.f;
    const float* xb = g_fold + (size_t)b * CIN * Hh * Ww;
    for (int ci = 0; ci < CIN; ci++) {
        float v[9];
        #pragma unroll
        for (int dh = 0; dh < 3; dh++) {
            int hh = h + dh - 1;
            hh = hh < 0 ? 1 : (hh >= Hh ? Hh - 2 : hh);
            #pragma unroll
            for (int dw = 0; dw < 3; dw++) {
                int w2p = w + dw - 1;
                w2p = w2p < 0 ? 1 : (w2p >= Ww ? Ww - 2 : w2p);
                v[dh*3 + dw] = xb[(ci*Hh + hh)*Ww + w2p];
            }
        }
        #pragma unroll
        for (int co = 0; co < CI; co++) {
            const float* p1 = &sw[(co*CIN + ci)*9];
            float s1 = 0.f;
            #pragma unroll
            for (int k = 0; k < 9; k++) s1 += p1[k]*v[k];
            acc[co] += s1;
        }
    }
    #pragma unroll
    for (int co = 0; co < CI; co++)
        acc[co] = (acc[co] > 0.f) ? acc[co] : 0.2f*acc[co];
    #pragma unroll
    for (int co = 0; co < CIN; co++) {
        float s = 0.f;
        #pragma unroll
        for (int ci = 0; ci < CI; ci++) s += sw2[co*CI + ci]*acc[ci];
        s = (s > 0.f) ? s : 0.2f*s;
        size_t idx = ((size_t)b*CIN + co)*Hh*Ww + pix;
        outp[idx] = x[idx] + s;
    }
}

// ---------------- launch -----------------------------------------------------------
extern "C" void kernel_launch(void* const* d_in, const int* in_sizes, int n_in,
                              void* d_out, int out_size)
{
    const float* x        = (const float*)d_in[0];
    const float* g_w      = (const float*)d_in[1];
    const float* g_b      = (const float*)d_in[2];
    const float* w_w      = (const float*)d_in[3];
    const float* w_b      = (const float*)d_in[4];
    const float* theta_w  = (const float*)d_in[5];
    const float* theta_b  = (const float*)d_in[6];
    const float* fc1_w    = (const float*)d_in[7];
    const float* fc1_b    = (const float*)d_in[8];
    const float* mconv_w  = (const float*)d_in[9];
    const float* mconv_b  = (const float*)d_in[10];
    const float* mfc_w    = (const float*)d_in[11];
    const float* mfc_b    = (const float*)d_in[12];
    const float* c1_w     = (const float*)d_in[13];
    const float* c2_w     = (const float*)d_in[14];
    float* out = (float*)d_out;

    float *pwf, *pW2a, *pW2b, *pATi, *py;
    unsigned *pp4h, *pp4l, *pp6h, *pp6l, *pfc1h, *pfc1l,
             *pawh, *pawl, *pxfh, *pxfl, *pwvh, *pwvl,
             *pamf, *pptf, *pmsh, *pmsl;
    cudaGetSymbolAddress((void**)&pwf,  g_wf);
    cudaGetSymbolAddress((void**)&pW2a, g_W2a);
    cudaGetSymbolAddress((void**)&pW2b, g_W2b);
    cudaGetSymbolAddress((void**)&pATi, g_ATi);
    cudaGetSymbolAddress((void**)&py,   g_y);
    cudaGetSymbolAddress((void**)&pp4h, g_p4h);
    cudaGetSymbolAddress((void**)&pp4l, g_p4l);
    cudaGetSymbolAddress((void**)&pp6h, g_p6h);
    cudaGetSymbolAddress((void**)&pp6l, g_p6l);
    cudaGetSymbolAddress((void**)&pfc1h,g_fc1h);
    cudaGetSymbolAddress((void**)&pfc1l,g_fc1l);
    cudaGetSymbolAddress((void**)&pawh, g_awh);
    cudaGetSymbolAddress((void**)&pawl, g_awl);
    cudaGetSymbolAddress((void**)&pxfh, g_xfh);
    cudaGetSymbolAddress((void**)&pxfl, g_xfl);
    cudaGetSymbolAddress((void**)&pwvh, g_wvh);
    cudaGetSymbolAddress((void**)&pwvl, g_wvl);
    cudaGetSymbolAddress((void**)&pmsh, g_msh);
    cudaGetSymbolAddress((void**)&pmsl, g_msl);
    cudaGetSymbolAddress((void**)&pamf, g_amf);
    cudaGetSymbolAddress((void**)&pptf, g_ptf);

    dim3 convGrid(Hh*Ww/NTHREADS, B_);
    #define GBLK(n) ((int)(((size_t)(n) + NTHREADS - 1) / NTHREADS))

    conv3x3_dual_theta_kernel<<<convGrid, NTHREADS>>>(x, g_w, g_b, w_w, w_b,
                                                      theta_w, theta_b);

    unfold_pk2_kernel<<<GBLK((size_t)B_*LL*(KP2_FIN/2)), NTHREADS>>>();
    unfold_p62t_f16_kernel<<<GBLK((size_t)B_*FV*(KP2_Y/2)), NTHREADS>>>();

    msum_fc1_pk_kernel<<<GBLK(MS_TOT + FC_TOT), NTHREADS>>>(
        mconv_w, mfc_w, mconv_b, mfc_b, fc1_w);

    // DUAL: z0 -> wf (fp32 + pack aw[0..8)); z1 -> xf (pack only)
    {
        dim3 g((FOUT + 127)/128, (B_*LL + 127)/128, 2);
        gemm_pk_kernel<false,false,true,false,1><<<g, 256>>>(
            pp4h, pp4l, pp6h, pp6l, pfc1h, pfc1l,
            pwf, nullptr, pawh, pawl, pxfh, pxfl,
            B_*LL, FOUT, FIN/16, 0, 0,
            KP2_FIN, KP2_FIN, FOUT, KP2_FOUT,
            0, 0, 0, 0, fc1_b);
    }

    pack_vert_kernel<<<GBLK((size_t)B_*KP2_LL*NPAD_VERT), NTHREADS>>>(pwf);

    // W2 KSPLIT: z = kh*8 + b
    {
        dim3 g((FOUT + 127)/128, (LL + 127)/128, 2*B_);
        gemm_pk_kernel<true,false,true,false,2><<<g, 256>>>(
            pmsh, pmsl, nullptr, nullptr, pwvh, pwvl,
            pW2a, pW2b, nullptr, nullptr, nullptr, nullptr,
            LL, FOUT, 31, 30, 248,
            KP2_LL, NPAD_VERT, FOUT, 0,
            0, (long long)KP2_LL*NPAD_VERT, (long long)LL*FOUT, 0,
            nullptr);
    }
    w2_combine_pk_kernel<<<GBLK((size_t)B_*LL*(FOUT/2)), NTHREADS>>>();

    // Batched A / Ti (bf16x3)
    {
        dim3 g((LL + 127)/128, (LL + 127)/128, 2*B_);
        gemm_pk_kernel<false,true,true,false,0><<<g, 256>>>(
            pawh, pawl, nullptr, nullptr, pxfh, pxfl,
            pATi, nullptr, nullptr, nullptr, nullptr, nullptr,
            LL, LL, 13, 0, 0,
            KP2_FOUT, KP2_FOUT, LL, 0,
            (long long)LL*KP2_FOUT, (long long)LL*KP2_FOUT,
            (long long)LL*LL, 0, nullptr);
    }

    softmax_kernel<<<B_*LL, NTHREADS>>>(out);

    // y[b] = Am[b] @ p62[b]  — single-pass fp16
    {
        dim3 g((FV + 127)/128, (LL + 127)/128, B_);
        gemm_pk_kernel<false,false,false,true,0><<<g, 256>>>(
            pamf, nullptr, nullptr, nullptr, pptf, nullptr,
            py, nullptr, nullptr, nullptr, nullptr, nullptr,
            LL, FV, 61, 0, 0,
            KP2_Y, KP2_Y, FV, 0,
            (long long)LL*KP2_Y, (long long)FV*KP2_Y,
            (long long)LL*FV, 0, nullptr);
    }

    fold_kernel<<<GBLK((size_t)B_*CIN*Hh*Ww), NTHREADS>>>();
    conv_c1c2_res_kernel<<<convGrid, NTHREADS>>>(c1_w, c2_w, x, out + (size_t)B_*LL*LL);
    #undef GBLK
}